// round 9
// baseline (speedup 1.0000x reference)
#include <cuda_runtime.h>
#include <cuda_bf16.h>
#include <cstdint>
#include <cstddef>

typedef __nv_bfloat16 bf16;

#define NB_B    4096
#define NB_OBS  1024
#define NB_HID  1024
#define NB_LAT  512
#define NB_OUT  19
#define NB_E    8
#define NB_NB   3
#define NB_DISP (NB_B*2)

#define BM 256
#define BN 128
#define BK 32
#define ROWB 80u                      // padded row: 32 bf16 = 64B + 16B pad
#define A_OP (256u*ROWB)              // 20480
#define B_OP (128u*ROWB)              // 10240
#define STG_BYTES (2u*A_OP + 2u*B_OP) // 61440 (Ah,Al,Bh,Bl)
#define GEMM_SMEM (2u*STG_BYTES)      // 122880 -> 1 CTA/SM

// ---------------- static side streams/events (created at program load) ----------
struct SideStreams {
    cudaStream_t s2, s3;
    cudaEvent_t ev0, ev2, ev3;
    SideStreams() {
        cudaStreamCreateWithFlags(&s2, cudaStreamNonBlocking);
        cudaStreamCreateWithFlags(&s3, cudaStreamNonBlocking);
        cudaEventCreateWithFlags(&ev0, cudaEventDisableTiming);
        cudaEventCreateWithFlags(&ev2, cudaEventDisableTiming);
        cudaEventCreateWithFlags(&ev3, cudaEventDisableTiming);
    }
};
static SideStreams g_ss;

// ---------------- scratch ----------------
__device__ __align__(16) bf16 g_encW1t_h[NB_NB*NB_OBS*NB_HID];
__device__ __align__(16) bf16 g_encW1t_l[NB_NB*NB_OBS*NB_HID];
__device__ __align__(16) bf16 g_encW2t_h[NB_NB*NB_HID*NB_OBS];
__device__ __align__(16) bf16 g_encW2t_l[NB_NB*NB_HID*NB_OBS];
__device__ __align__(16) bf16 g_encWft_h[NB_OBS*NB_LAT];
__device__ __align__(16) bf16 g_encWft_l[NB_OBS*NB_LAT];
__device__ __align__(16) bf16 g_expW1t_h[NB_E*NB_NB*NB_LAT*NB_HID];
__device__ __align__(16) bf16 g_expW1t_l[NB_E*NB_NB*NB_LAT*NB_HID];
__device__ __align__(16) bf16 g_expW2t_h[NB_E*NB_NB*NB_HID*NB_LAT];
__device__ __align__(16) bf16 g_expW2t_l[NB_E*NB_NB*NB_HID*NB_LAT];
__device__ __align__(16) bf16 g_valW1t_h[NB_NB*NB_OBS*NB_HID];
__device__ __align__(16) bf16 g_valW1t_l[NB_NB*NB_OBS*NB_HID];
__device__ __align__(16) bf16 g_valW2t_h[NB_NB*NB_HID*NB_OBS];
__device__ __align__(16) bf16 g_valW2t_l[NB_NB*NB_HID*NB_OBS];
__device__ __align__(16) bf16 g_obs_h[NB_B*NB_OBS];
__device__ __align__(16) bf16 g_obs_l[NB_B*NB_OBS];
// encoder-chain activations
__device__ __align__(16) bf16 g_h_h[NB_B*NB_HID];
__device__ __align__(16) bf16 g_h_l[NB_B*NB_HID];
__device__ __align__(16) float g_xa_f[NB_B*NB_OBS];
__device__ __align__(16) bf16 g_xa_h[NB_B*NB_OBS];
__device__ __align__(16) bf16 g_xa_l[NB_B*NB_OBS];
__device__ __align__(16) float g_xb_f[NB_B*NB_OBS];
__device__ __align__(16) bf16 g_xb_h[NB_B*NB_OBS];
__device__ __align__(16) bf16 g_xb_l[NB_B*NB_OBS];
// value-chain activations
__device__ __align__(16) bf16 g_h2_h[NB_B*NB_HID];
__device__ __align__(16) bf16 g_h2_l[NB_B*NB_HID];
__device__ __align__(16) float g_ya_f[NB_B*NB_OBS];
__device__ __align__(16) bf16 g_ya_h[NB_B*NB_OBS];
__device__ __align__(16) bf16 g_ya_l[NB_B*NB_OBS];
__device__ __align__(16) float g_yb_f[NB_B*NB_OBS];
__device__ __align__(16) bf16 g_yb_h[NB_B*NB_OBS];
__device__ __align__(16) bf16 g_yb_l[NB_B*NB_OBS];
// latent + MoE
__device__ __align__(16) float g_lat_f[NB_B*NB_LAT];
__device__ __align__(16) bf16 g_lat_h[NB_B*NB_LAT];
__device__ __align__(16) bf16 g_lat_l[NB_B*NB_LAT];
__device__ __align__(16) float g_xea_f[NB_DISP*NB_LAT];
__device__ __align__(16) bf16 g_xea_h[NB_DISP*NB_LAT];
__device__ __align__(16) bf16 g_xea_l[NB_DISP*NB_LAT];
__device__ __align__(16) float g_xeb_f[NB_DISP*NB_LAT];
__device__ __align__(16) bf16 g_xeb_h[NB_DISP*NB_LAT];
__device__ __align__(16) bf16 g_xeb_l[NB_DISP*NB_LAT];
__device__ __align__(16) bf16 g_he_h[NB_DISP*NB_HID];
__device__ __align__(16) bf16 g_he_l[NB_DISP*NB_HID];
__device__ int   g_tokidx[NB_E*NB_B];
__device__ float g_gatew [NB_E*NB_B];
__device__ int   g_cnt[NB_E];
__device__ int   g_off[NB_E];
__device__ int   g_dtok[NB_DISP];
__device__ float g_dg  [NB_DISP];

// ---------------- PTX helpers (portable, sm_80+) ----------------
__device__ __forceinline__ uint32_t smem_u32(const void* p){ return (uint32_t)__cvta_generic_to_shared(p); }
__device__ __forceinline__ void cp16(uint32_t s, const void* g){
    asm volatile("cp.async.cg.shared.global [%0], [%1], 16;"::"r"(s),"l"(g):"memory");
}
__device__ __forceinline__ void ldm_x4(uint32_t& r0,uint32_t& r1,uint32_t& r2,uint32_t& r3,uint32_t a){
    asm volatile("ldmatrix.sync.aligned.m8n8.x4.shared.b16 {%0,%1,%2,%3},[%4];"
        :"=r"(r0),"=r"(r1),"=r"(r2),"=r"(r3):"r"(a));
}
__device__ __forceinline__ void mma16816(float* c, const uint32_t* a, const uint32_t* b){
    asm volatile("mma.sync.aligned.m16n8k16.row.col.f32.bf16.bf16.f32 "
        "{%0,%1,%2,%3},{%4,%5,%6,%7},{%8,%9},{%0,%1,%2,%3};"
        :"+f"(c[0]),"+f"(c[1]),"+f"(c[2]),"+f"(c[3])
        :"r"(a[0]),"r"(a[1]),"r"(a[2]),"r"(a[3]),"r"(b[0]),"r"(b[1]));
}

// ---------------- bf16x3 warp-MMA GEMM: C = epi(A@W^T + bias [,+R]) ----------------
// Tile: 256x128, 8 warps (warp tile 64x64), 2-stage cp.async pipeline.
__device__ __forceinline__ void gemm_core(
    const bf16* __restrict__ Ah, const bf16* __restrict__ Al,
    const bf16* __restrict__ Bh, const bf16* __restrict__ Bl,
    const float* __restrict__ bias, const float* __restrict__ Rf,
    float* __restrict__ Cf, bf16* __restrict__ Ch, bf16* __restrict__ Cl,
    int M, int N, int K, int epi, char* dsm)
{
    const int tid=threadIdx.x, wid=tid>>5, lane=tid&31;
    const int row0=blockIdx.y*BM, col0=blockIdx.x*BN;
    const int wm=wid>>1, wn=wid&1;                  // warp tile: 64 x 64
    const uint32_t sb0 = smem_u32(dsm);

    // cp.async mapping: A = 1024 16B units (4/thread), B = 512 units (2/thread)
    uint32_t soffA[4]; size_t aoff[4];
#pragma unroll
    for (int i=0;i<4;i++){
        int u=tid+256*i, row=u>>2, seg=u&3;
        soffA[i]=(uint32_t)row*ROWB + (uint32_t)seg*16u;
        int ar=row0+row; if (ar>M-1) ar=M-1;
        aoff[i]=(size_t)ar*K + seg*8;
    }
    uint32_t soffB[2]; size_t boff[2];
#pragma unroll
    for (int i=0;i<2;i++){
        int u=tid+256*i, row=u>>2, seg=u&3;
        soffB[i]=(uint32_t)row*ROWB + (uint32_t)seg*16u;
        boff[i]=(size_t)(col0+row)*K + seg*8;
    }
    const int NC = K/BK;
    auto prefetch = [&](int c){
        uint32_t st = sb0 + (uint32_t)(c&1)*STG_BYTES;
        size_t k0 = (size_t)c*BK;
#pragma unroll
        for (int i=0;i<4;i++){
            cp16(st + soffA[i],            Ah+aoff[i]+k0);
            cp16(st + A_OP + soffA[i],     Al+aoff[i]+k0);
        }
#pragma unroll
        for (int i=0;i<2;i++){
            cp16(st + 2u*A_OP + soffB[i],        Bh+boff[i]+k0);
            cp16(st + 2u*A_OP + B_OP + soffB[i], Bl+boff[i]+k0);
        }
        asm volatile("cp.async.commit_group;":::"memory");
    };

    // A: x4 per 16-row block
    const uint32_t a_lane = (uint32_t)(wm*64 + (lane&7) + ((lane>>3)&1)*8)*ROWB + (uint32_t)(lane>>4)*16u;
    // B: x4 covering TWO n8 blocks (bit3 -> k-half, bit4 -> next 8 rows)
    const uint32_t b_lane4 = (uint32_t)(wn*64 + (lane&7) + ((lane>>4)&1)*8)*ROWB + (uint32_t)((lane>>3)&1)*16u;

    float acc[4][8][4];
#pragma unroll
    for (int i=0;i<4;i++)
#pragma unroll
        for (int j=0;j<8;j++)
#pragma unroll
            for (int k=0;k<4;k++) acc[i][j][k]=0.f;

    prefetch(0); if (NC>1) prefetch(1);
    for (int c=0;c<NC;c++){
        if (c==NC-1) asm volatile("cp.async.wait_group 0;":::"memory");
        else         asm volatile("cp.async.wait_group 1;":::"memory");
        __syncthreads();

        uint32_t st = sb0 + (uint32_t)(c&1)*STG_BYTES;
#pragma unroll
        for (int ks=0;ks<2;ks++){
            uint32_t ah[4][4], al[4][4], bh[8][2], blo[8][2];
#pragma unroll
            for (int mt=0;mt<4;mt++){
                uint32_t ad = st + a_lane + (uint32_t)mt*16u*ROWB + (uint32_t)ks*32u;
                ldm_x4(ah[mt][0],ah[mt][1],ah[mt][2],ah[mt][3], ad);
                ldm_x4(al[mt][0],al[mt][1],al[mt][2],al[mt][3], ad + A_OP);
            }
#pragma unroll
            for (int np=0;np<4;np++){    // each x4 covers nt=2*np and nt=2*np+1
                uint32_t bd = st + 2u*A_OP + b_lane4 + (uint32_t)np*16u*ROWB + (uint32_t)ks*32u;
                ldm_x4(bh[2*np][0], bh[2*np][1], bh[2*np+1][0], bh[2*np+1][1], bd);
                ldm_x4(blo[2*np][0],blo[2*np][1],blo[2*np+1][0],blo[2*np+1][1], bd + B_OP);
            }
#pragma unroll
            for (int mt=0;mt<4;mt++)
#pragma unroll
                for (int nt=0;nt<8;nt++){
                    mma16816(acc[mt][nt], ah[mt], bh[nt]);
                    mma16816(acc[mt][nt], ah[mt], blo[nt]);
                    mma16816(acc[mt][nt], al[mt], bh[nt]);
                }
        }
        __syncthreads();
        if (c+2<NC) prefetch(c+2);   // stage (c&1) is free now
    }

    // ---------------- epilogue ----------------
    const int rbase = row0 + wm*64 + (lane>>2);
    const int cbase = col0 + wn*64 + (lane&3)*2;
#pragma unroll
    for (int mt=0;mt<4;mt++){
#pragma unroll
        for (int half=0; half<2; half++){
            const int rr = rbase + mt*16 + half*8;
            if (rr >= M) continue;
#pragma unroll
            for (int nt=0;nt<8;nt++){
                const int cc = cbase + nt*8;
                float v0 = acc[mt][nt][half*2+0] + bias[cc];
                float v1 = acc[mt][nt][half*2+1] + bias[cc+1];
                const size_t base = (size_t)rr*N + cc;
                if (epi==0){ v0=fmaxf(v0,0.f); v1=fmaxf(v1,0.f); }
                else if (epi==1){
                    float2 r2 = *(const float2*)(Rf + base);
                    v0 += r2.x; v1 += r2.y;
                }
                if (Cf){ float2 o; o.x=v0; o.y=v1; *(float2*)(Cf+base)=o; }
                bf16 h0=__float2bfloat16(v0), h1=__float2bfloat16(v1);
                __nv_bfloat162 th; th.x=h0; th.y=h1;
                __nv_bfloat162 tl; tl.x=__float2bfloat16(v0-__bfloat162float(h0));
                tl.y=__float2bfloat16(v1-__bfloat162float(h1));
                *(__nv_bfloat162*)(Ch+base)=th;
                *(__nv_bfloat162*)(Cl+base)=tl;
            }
        }
    }
}

__global__ void __launch_bounds__(256,1)
gemm_dense(const bf16* Ah, const bf16* Al, const bf16* Bh, const bf16* Bl,
           const float* bias, const float* Rf, float* Cf, bf16* Ch, bf16* Cl,
           int M, int N, int K, int epi)
{
    extern __shared__ char dsm[];
    gemm_core(Ah,Al,Bh,Bl,bias,Rf,Cf,Ch,Cl,M,N,K,epi,dsm);
}

__global__ void __launch_bounds__(256,1)
gemm_exp(const bf16* Ah, const bf16* Al, const bf16* Wh, const bf16* Wl, long wstride,
         const float* bias, long bstride, const float* Rf, float* Cf, bf16* Ch, bf16* Cl,
         int N, int K, int epi, const int* cnt, const int* off)
{
    extern __shared__ char dsm[];
    int e = blockIdx.z, M = cnt[e];
    if ((int)(blockIdx.y*BM) >= M) return;
    size_t o = (size_t)off[e];
    gemm_core(Ah+o*K, Al+o*K, Wh+(size_t)e*wstride, Wl+(size_t)e*wstride,
              bias+(size_t)e*bstride, Rf?Rf+o*N:nullptr, Cf?Cf+o*N:nullptr,
              Ch+o*N, Cl+o*N, M, N, K, epi, dsm);
}

// ---------------- conversions ----------------
__global__ void conv_split(const float* __restrict__ s, bf16* __restrict__ dh, bf16* __restrict__ dl, int n4)
{
    int i = blockIdx.x*blockDim.x + threadIdx.x;
    if (i>=n4) return;
    float4 v = ((const float4*)s)[i];
    __nv_bfloat162 h0,h1,l0,l1;
    h0.x=__float2bfloat16(v.x); h0.y=__float2bfloat16(v.y);
    h1.x=__float2bfloat16(v.z); h1.y=__float2bfloat16(v.w);
    l0.x=__float2bfloat16(v.x-__bfloat162float(h0.x));
    l0.y=__float2bfloat16(v.y-__bfloat162float(h0.y));
    l1.x=__float2bfloat16(v.z-__bfloat162float(h1.x));
    l1.y=__float2bfloat16(v.w-__bfloat162float(h1.y));
    ((__nv_bfloat162*)dh)[i*2]=h0; ((__nv_bfloat162*)dh)[i*2+1]=h1;
    ((__nv_bfloat162*)dl)[i*2]=l0; ((__nv_bfloat162*)dl)[i*2+1]=l1;
}

// [mats,K,N] fp32 -> [mats,N,K] bf16 hi/lo
__global__ void transpose_conv(const float* __restrict__ src, bf16* __restrict__ dh,
                               bf16* __restrict__ dl, int K, int N)
{
    __shared__ float t[32][33];
    int m = blockIdx.z;
    const float* S = src + (size_t)m*K*N;
    bf16* DH = dh + (size_t)m*K*N;
    bf16* DL = dl + (size_t)m*K*N;
    int n0=blockIdx.x*32, k0=blockIdx.y*32, x=threadIdx.x, y0=threadIdx.y;
#pragma unroll
    for (int yy=0;yy<32;yy+=8) t[y0+yy][x] = S[(size_t)(k0+y0+yy)*N + n0 + x];
    __syncthreads();
#pragma unroll
    for (int yy=0;yy<32;yy+=8){
        float v = t[x][y0+yy];
        bf16 h = __float2bfloat16(v);
        size_t di = (size_t)(n0+y0+yy)*K + k0 + x;
        DH[di]=h; DL[di]=__float2bfloat16(v-__bfloat162float(h));
    }
}

// ---------------- MoE plumbing ----------------
__global__ void init_kernel(float* out, int* cnt)
{
    int i = blockIdx.x*blockDim.x + threadIdx.x;
    if (i<NB_E) cnt[i]=0;
    if (i<NB_B*NB_OUT){ int b=i/NB_OUT, c=i%NB_OUT; out[b*(NB_OUT+1)+c]=0.f; }
}

__global__ void __launch_bounds__(256)
gate_kernel(const float* __restrict__ lat, const float* __restrict__ wg,
            int* tokidx, float* gatew, int* cnt)
{
    __shared__ float swg[NB_LAT*NB_E];
    for (int i=threadIdx.x;i<NB_LAT*NB_E;i+=blockDim.x) swg[i]=wg[i];
    __syncthreads();
    int warp=threadIdx.x>>5, lane=threadIdx.x&31;
    int b = blockIdx.x*8 + warp;
    float acc[NB_E];
#pragma unroll
    for (int e=0;e<NB_E;e++) acc[e]=0.f;
    for (int k=lane;k<NB_LAT;k+=32){
        float x = lat[(size_t)b*NB_LAT+k];
#pragma unroll
        for (int e=0;e<NB_E;e++) acc[e]=fmaf(x,swg[k*NB_E+e],acc[e]);
    }
#pragma unroll
    for (int e=0;e<NB_E;e++)
#pragma unroll
        for (int o=16;o;o>>=1) acc[e]+=__shfl_xor_sync(0xFFFFFFFFu,acc[e],o);
    if (lane==0){
        int e0=0; float v0=acc[0];
        for (int e=1;e<NB_E;e++) if (acc[e]>v0){v0=acc[e];e0=e;}
        int e1=-1; float v1=-3.4e38f;
        for (int e=0;e<NB_E;e++) if (e!=e0 && acc[e]>v1){v1=acc[e];e1=e;}
        float w1=expf(v1-v0), s=1.f+w1, w0=1.f/s; w1/=s;
        int p0=atomicAdd(&cnt[e0],1); tokidx[e0*NB_B+p0]=b; gatew[e0*NB_B+p0]=w0;
        int p1=atomicAdd(&cnt[e1],1); tokidx[e1*NB_B+p1]=b; gatew[e1*NB_B+p1]=w1;
    }
}

__global__ void scan_kernel(const int* cnt, int* off)
{
    if (threadIdx.x==0){ int s=0; for (int e=0;e<NB_E;e++){ off[e]=s; s+=cnt[e]; } }
}

__global__ void __launch_bounds__(256)
gather_kernel(const float* __restrict__ latf, const bf16* __restrict__ lath, const bf16* __restrict__ latl,
              const int* tokidx, const float* gatew, const int* cnt, const int* off,
              float* xef, bf16* xeh, bf16* xel, int* dtok, float* dg)
{
    int e=blockIdx.x, r=blockIdx.y*8 + (threadIdx.x>>5), lane=threadIdx.x&31;
    if (r>=cnt[e]) return;
    int tok = tokidx[e*NB_B+r], dst = off[e]+r;
    const float4* sf=(const float4*)(latf+(size_t)tok*NB_LAT);
    float4* df=(float4*)(xef+(size_t)dst*NB_LAT);
#pragma unroll
    for (int i=0;i<4;i++) df[lane+32*i]=sf[lane+32*i];
    const uint4* sh_=(const uint4*)(lath+(size_t)tok*NB_LAT);
    uint4* dh_=(uint4*)(xeh+(size_t)dst*NB_LAT);
    const uint4* sl_=(const uint4*)(latl+(size_t)tok*NB_LAT);
    uint4* dl_=(uint4*)(xel+(size_t)dst*NB_LAT);
#pragma unroll
    for (int i=0;i<2;i++){ dh_[lane+32*i]=sh_[lane+32*i]; dl_[lane+32*i]=sl_[lane+32*i]; }
    if (lane==0){ dtok[dst]=tok; dg[dst]=gatew[e*NB_B+r]; }
}

__global__ void __launch_bounds__(256)
expert_final_kernel(const float* __restrict__ xe, const float* __restrict__ Wf, const float* __restrict__ bf_,
                    const int* cnt, const int* off, const int* dtok, const float* dg, float* out)
{
    int e=blockIdx.x;
    __shared__ float sW[NB_LAT*NB_OUT];
    for (int i=threadIdx.x;i<NB_LAT*NB_OUT;i+=blockDim.x) sW[i]=Wf[(size_t)e*NB_LAT*NB_OUT+i];
    __syncthreads();
    int r=blockIdx.y*8 + (threadIdx.x>>5), lane=threadIdx.x&31;
    if (r>=cnt[e]) return;
    int dst=off[e]+r;
    float acc[NB_OUT];
#pragma unroll
    for (int c=0;c<NB_OUT;c++) acc[c]=0.f;
    const float* x = xe + (size_t)dst*NB_LAT;
#pragma unroll
    for (int i=0;i<NB_LAT/32;i++){
        int k=lane+32*i; float xv=x[k];
#pragma unroll
        for (int c=0;c<NB_OUT;c++) acc[c]=fmaf(xv,sW[k*NB_OUT+c],acc[c]);
    }
#pragma unroll
    for (int c=0;c<NB_OUT;c++)
#pragma unroll
        for (int o=16;o;o>>=1) acc[c]+=__shfl_xor_sync(0xFFFFFFFFu,acc[c],o);
    if (lane==0){
        int tok=dtok[dst]; float g=dg[dst];
#pragma unroll
        for (int c=0;c<NB_OUT;c++)
            atomicAdd(&out[tok*(NB_OUT+1)+c], g*(acc[c]+bf_[e*NB_OUT+c]));
    }
}

__global__ void __launch_bounds__(256)
value_final_kernel(const float* __restrict__ xv, const float* __restrict__ Wf,
                   const float* __restrict__ bf_, float* out)
{
    int b=blockIdx.x*8 + (threadIdx.x>>5), lane=threadIdx.x&31;
    float acc=0.f;
    const float* x = xv + (size_t)b*NB_OBS;
#pragma unroll
    for (int i=0;i<NB_OBS/32;i++) acc=fmaf(x[lane+32*i],Wf[lane+32*i],acc);
#pragma unroll
    for (int o=16;o;o>>=1) acc+=__shfl_xor_sync(0xFFFFFFFFu,acc,o);
    if (lane==0) out[b*(NB_OUT+1)+NB_OUT]=acc+bf_[0];
}

__global__ void eps_kernel(float* out)
{
    int i=blockIdx.x*blockDim.x+threadIdx.x;
    if (i<NB_B*NB_OUT){
        int b=i/NB_OUT, c=i%NB_OUT;
        float* p=&out[b*(NB_OUT+1)+c];
        if (*p==0.f) *p=2.2204460492503131e-16f;
    }
}

// =====================================================================================
extern "C" void kernel_launch(void* const* d_in, const int* in_sizes, int n_in,
                              void* d_out, int out_size)
{
    const float* obs   =(const float*)d_in[0];
    const float* encW1 =(const float*)d_in[1];  const float* encb1=(const float*)d_in[2];
    const float* encW2 =(const float*)d_in[3];  const float* encb2=(const float*)d_in[4];
    const float* encWf =(const float*)d_in[5];  const float* encbf=(const float*)d_in[6];
    const float* expW1 =(const float*)d_in[7];  const float* expb1=(const float*)d_in[8];
    const float* expW2 =(const float*)d_in[9];  const float* expb2=(const float*)d_in[10];
    const float* expWf =(const float*)d_in[11]; const float* expbf=(const float*)d_in[12];
    const float* valW1 =(const float*)d_in[13]; const float* valb1=(const float*)d_in[14];
    const float* valW2 =(const float*)d_in[15]; const float* valb2=(const float*)d_in[16];
    const float* valWf =(const float*)d_in[17]; const float* valbf=(const float*)d_in[18];
    const float* wgate =(const float*)d_in[19];
    float* out=(float*)d_out;

#define SYM(T,v,s) T* v; cudaGetSymbolAddress((void**)&v, s)
    SYM(bf16,eW1h,g_encW1t_h); SYM(bf16,eW1l,g_encW1t_l);
    SYM(bf16,eW2h,g_encW2t_h); SYM(bf16,eW2l,g_encW2t_l);
    SYM(bf16,eWfh,g_encWft_h); SYM(bf16,eWfl,g_encWft_l);
    SYM(bf16,xW1h,g_expW1t_h); SYM(bf16,xW1l,g_expW1t_l);
    SYM(bf16,xW2h,g_expW2t_h); SYM(bf16,xW2l,g_expW2t_l);
    SYM(bf16,vW1h,g_valW1t_h); SYM(bf16,vW1l,g_valW1t_l);
    SYM(bf16,vW2h,g_valW2t_h); SYM(bf16,vW2l,g_valW2t_l);
    SYM(bf16,obsh,g_obs_h);    SYM(bf16,obsl,g_obs_l);
    SYM(bf16,hh,g_h_h);        SYM(bf16,hl,g_h_l);
    SYM(float,xaf,g_xa_f); SYM(bf16,xah,g_xa_h); SYM(bf16,xal,g_xa_l);
    SYM(float,xbf,g_xb_f); SYM(bf16,xbh,g_xb_h); SYM(bf16,xbl,g_xb_l);
    SYM(bf16,h2h,g_h2_h);  SYM(bf16,h2l,g_h2_l);
    SYM(float,yaf,g_ya_f); SYM(bf16,yah,g_ya_h); SYM(bf16,yal,g_ya_l);
    SYM(float,ybf,g_yb_f); SYM(bf16,ybh,g_yb_h); SYM(bf16,ybl,g_yb_l);
    SYM(float,latf,g_lat_f); SYM(bf16,lath,g_lat_h); SYM(bf16,latl,g_lat_l);
    SYM(float,xeaf,g_xea_f); SYM(bf16,xeah,g_xea_h); SYM(bf16,xeal,g_xea_l);
    SYM(float,xebf,g_xeb_f); SYM(bf16,xebh,g_xeb_h); SYM(bf16,xebl,g_xeb_l);
    SYM(bf16,heh,g_he_h);    SYM(bf16,hel,g_he_l);
    SYM(int,tokidx,g_tokidx); SYM(float,gatew,g_gatew);
    SYM(int,cnt,g_cnt); SYM(int,off,g_off); SYM(int,dtok,g_dtok); SYM(float,dg,g_dg);
#undef SYM

    cudaFuncSetAttribute(gemm_dense, cudaFuncAttributeMaxDynamicSharedMemorySize, GEMM_SMEM);
    cudaFuncSetAttribute(gemm_exp,   cudaFuncAttributeMaxDynamicSharedMemorySize, GEMM_SMEM);

    cudaStream_t s2 = g_ss.s2, s3 = g_ss.s3;
    cudaEvent_t ev0 = g_ss.ev0, ev2 = g_ss.ev2, ev3 = g_ss.ev3;

    dim3 tcb(32,8);
    dim3 gh(NB_HID/BN, NB_B/BM), go(NB_OBS/BN, NB_B/BM), gl(NB_LAT/BN, NB_B/BM);
    const size_t W1M=(size_t)NB_OBS*NB_HID;

    init_kernel<<<(NB_B*NB_OUT+255)/256, 256>>>(out, cnt);
    conv_split<<<(NB_B*NB_OBS/4+255)/256, 256>>>(obs, obsh, obsl, NB_B*NB_OBS/4);
    cudaEventRecord(ev0, 0);   // obs split done -> side chains may start

    transpose_conv<<<dim3(NB_HID/32, NB_OBS/32, NB_NB), tcb>>>(encW1, eW1h, eW1l, NB_OBS, NB_HID);
    transpose_conv<<<dim3(NB_OBS/32, NB_HID/32, NB_NB), tcb>>>(encW2, eW2h, eW2l, NB_HID, NB_OBS);
    transpose_conv<<<dim3(NB_LAT/32, NB_OBS/32, 1),     tcb>>>(encWf, eWfh, eWfl, NB_OBS, NB_LAT);

    // encoder GEMM 1
    gemm_dense<<<gh,256,GEMM_SMEM>>>(obsh,obsl, eW1h,eW1l, encb1, nullptr, nullptr, hh,hl, NB_B,NB_HID,NB_OBS,0);

    // fork side streams
    cudaStreamWaitEvent(s2, ev0, 0);
    cudaStreamWaitEvent(s3, ev0, 0);
    // s3: expert weight prep
    transpose_conv<<<dim3(NB_HID/32, NB_LAT/32, NB_E*NB_NB), tcb, 0, s3>>>(expW1, xW1h, xW1l, NB_LAT, NB_HID);
    transpose_conv<<<dim3(NB_LAT/32, NB_HID/32, NB_E*NB_NB), tcb, 0, s3>>>(expW2, xW2h, xW2l, NB_HID, NB_LAT);
    cudaEventRecord(ev3, s3);
    // s2: value weight prep + value chain
    transpose_conv<<<dim3(NB_HID/32, NB_OBS/32, NB_NB), tcb, 0, s2>>>(valW1, vW1h, vW1l, NB_OBS, NB_HID);
    transpose_conv<<<dim3(NB_OBS/32, NB_HID/32, NB_NB), tcb, 0, s2>>>(valW2, vW2h, vW2l, NB_HID, NB_OBS);
    gemm_dense<<<gh,256,GEMM_SMEM,s2>>>(obsh,obsl, vW1h,vW1l, valb1, nullptr, nullptr, h2h,h2l, NB_B,NB_HID,NB_OBS,0);
    gemm_dense<<<go,256,GEMM_SMEM,s2>>>(h2h,h2l, vW2h,vW2l, valb2, obs, yaf, yah,yal, NB_B,NB_OBS,NB_HID,1);
    gemm_dense<<<gh,256,GEMM_SMEM,s2>>>(yah,yal, vW1h+W1M,vW1l+W1M, valb1+NB_HID, nullptr, nullptr, h2h,h2l, NB_B,NB_HID,NB_OBS,0);
    gemm_dense<<<go,256,GEMM_SMEM,s2>>>(h2h,h2l, vW2h+W1M,vW2l+W1M, valb2+NB_OBS, yaf, ybf, ybh,ybl, NB_B,NB_OBS,NB_HID,1);
    gemm_dense<<<gh,256,GEMM_SMEM,s2>>>(ybh,ybl, vW1h+2*W1M,vW1l+2*W1M, valb1+2*NB_HID, nullptr, nullptr, h2h,h2l, NB_B,NB_HID,NB_OBS,0);
    gemm_dense<<<go,256,GEMM_SMEM,s2>>>(h2h,h2l, vW2h+2*W1M,vW2l+2*W1M, valb2+2*NB_OBS, ybf, yaf, yah,yal, NB_B,NB_OBS,NB_HID,1);
    value_final_kernel<<<NB_B/8,256,0,s2>>>(yaf, valWf, valbf, out);
    cudaEventRecord(ev2, s2);

    // main: remaining encoder ResNet
    gemm_dense<<<go,256,GEMM_SMEM>>>(hh,hl, eW2h,eW2l, encb2, obs, xaf, xah,xal, NB_B,NB_OBS,NB_HID,1);
    gemm_dense<<<gh,256,GEMM_SMEM>>>(xah,xal, eW1h+W1M,eW1l+W1M, encb1+NB_HID, nullptr, nullptr, hh,hl, NB_B,NB_HID,NB_OBS,0);
    gemm_dense<<<go,256,GEMM_SMEM>>>(hh,hl, eW2h+W1M,eW2l+W1M, encb2+NB_OBS, xaf, xbf, xbh,xbl, NB_B,NB_OBS,NB_HID,1);
    gemm_dense<<<gh,256,GEMM_SMEM>>>(xbh,xbl, eW1h+2*W1M,eW1l+2*W1M, encb1+2*NB_HID, nullptr, nullptr, hh,hl, NB_B,NB_HID,NB_OBS,0);
    gemm_dense<<<go,256,GEMM_SMEM>>>(hh,hl, eW2h+2*W1M,eW2l+2*W1M, encb2+2*NB_OBS, xbf, xaf, xah,xal, NB_B,NB_OBS,NB_HID,1);
    gemm_dense<<<gl,256,GEMM_SMEM>>>(xah,xal, eWfh,eWfl, encbf, nullptr, latf, lath,latl, NB_B,NB_LAT,NB_OBS,2);

    // gating + dispatch
    gate_kernel<<<NB_B/8,256>>>(latf, wgate, tokidx, gatew, cnt);
    scan_kernel<<<1,32>>>(cnt, off);
    gather_kernel<<<dim3(NB_E,NB_B/8),256>>>(latf,lath,latl,tokidx,gatew,cnt,off,xeaf,xeah,xeal,dtok,dg);

    // join expert-weight prep before expert GEMMs
    cudaStreamWaitEvent(0, ev3, 0);

    const long w1s=(long)NB_NB*NB_LAT*NB_HID, b1s=(long)NB_NB*NB_HID;
    const long w2s=(long)NB_NB*NB_HID*NB_LAT, b2s=(long)NB_NB*NB_LAT;
    dim3 eg1(NB_HID/BN, NB_B/BM, NB_E), eg2(NB_LAT/BN, NB_B/BM, NB_E);
    float *cf=xeaf, *nf=xebf; bf16 *chh=xeah,*cll=xeal,*nhh=xebh,*nll=xebl;
    for (int blk=0;blk<NB_NB;blk++){
        gemm_exp<<<eg1,256,GEMM_SMEM>>>(chh,cll, xW1h+(size_t)blk*NB_LAT*NB_HID, xW1l+(size_t)blk*NB_LAT*NB_HID, w1s,
                                        expb1+blk*NB_HID, b1s, nullptr, nullptr, heh,hel, NB_HID,NB_LAT,0, cnt,off);
        gemm_exp<<<eg2,256,GEMM_SMEM>>>(heh,hel, xW2h+(size_t)blk*NB_HID*NB_LAT, xW2l+(size_t)blk*NB_HID*NB_LAT, w2s,
                                        expb2+blk*NB_LAT, b2s, cf, nf, nhh,nll, NB_LAT,NB_HID,1, cnt,off);
        { float* t=cf; cf=nf; nf=t; } { bf16* t=chh; chh=nhh; nhh=t; t=cll; cll=nll; nll=t; }
    }
    expert_final_kernel<<<dim3(NB_E,NB_B/8),256>>>(cf, expWf, expbf, cnt, off, dtok, dg, out);

    eps_kernel<<<(NB_B*NB_OUT+255)/256, 256>>>(out);

    // join value chain before returning
    cudaStreamWaitEvent(0, ev2, 0);
}

// round 10
// speedup vs baseline: 1.0366x; 1.0366x over previous
#include <cuda_runtime.h>
#include <cuda_bf16.h>
#include <cstdint>
#include <cstddef>

typedef __nv_bfloat16 bf16;

#define NB_B    4096
#define NB_OBS  1024
#define NB_HID  1024
#define NB_LAT  512
#define NB_OUT  19
#define NB_E    8
#define NB_NB   3
#define NB_DISP (NB_B*2)

#define BM 128
#define BN 128
#define BK 32
#define ROWB 80u                      // padded row: 32 bf16 = 64B + 16B pad
#define OP_BYTES (128u*ROWB)          // 10240
#define STG_BYTES (4u*OP_BYTES)       // 40960 (Ah,Al,Bh,Bl)
#define GEMM_SMEM (2u*STG_BYTES)      // 81920 -> 2 CTAs/SM

// ---------------- static side streams/events (created at program load) ----------
struct SideStreams {
    cudaStream_t s2, s3;
    cudaEvent_t ev0, ev2, ev3;
    SideStreams() {
        cudaStreamCreateWithFlags(&s2, cudaStreamNonBlocking);
        cudaStreamCreateWithFlags(&s3, cudaStreamNonBlocking);
        cudaEventCreateWithFlags(&ev0, cudaEventDisableTiming);
        cudaEventCreateWithFlags(&ev2, cudaEventDisableTiming);
        cudaEventCreateWithFlags(&ev3, cudaEventDisableTiming);
    }
};
static SideStreams g_ss;

// ---------------- scratch ----------------
__device__ __align__(16) bf16 g_encW1t_h[NB_NB*NB_OBS*NB_HID];
__device__ __align__(16) bf16 g_encW1t_l[NB_NB*NB_OBS*NB_HID];
__device__ __align__(16) bf16 g_encW2t_h[NB_NB*NB_HID*NB_OBS];
__device__ __align__(16) bf16 g_encW2t_l[NB_NB*NB_HID*NB_OBS];
__device__ __align__(16) bf16 g_encWft_h[NB_OBS*NB_LAT];
__device__ __align__(16) bf16 g_encWft_l[NB_OBS*NB_LAT];
__device__ __align__(16) bf16 g_expW1t_h[NB_E*NB_NB*NB_LAT*NB_HID];
__device__ __align__(16) bf16 g_expW1t_l[NB_E*NB_NB*NB_LAT*NB_HID];
__device__ __align__(16) bf16 g_expW2t_h[NB_E*NB_NB*NB_HID*NB_LAT];
__device__ __align__(16) bf16 g_expW2t_l[NB_E*NB_NB*NB_HID*NB_LAT];
__device__ __align__(16) bf16 g_valW1t_h[NB_NB*NB_OBS*NB_HID];
__device__ __align__(16) bf16 g_valW1t_l[NB_NB*NB_OBS*NB_HID];
__device__ __align__(16) bf16 g_valW2t_h[NB_NB*NB_HID*NB_OBS];
__device__ __align__(16) bf16 g_valW2t_l[NB_NB*NB_HID*NB_OBS];
__device__ __align__(16) bf16 g_obs_h[NB_B*NB_OBS];
__device__ __align__(16) bf16 g_obs_l[NB_B*NB_OBS];
// encoder-chain activations
__device__ __align__(16) bf16 g_h_h[NB_B*NB_HID];
__device__ __align__(16) bf16 g_h_l[NB_B*NB_HID];
__device__ __align__(16) float g_xa_f[NB_B*NB_OBS];
__device__ __align__(16) bf16 g_xa_h[NB_B*NB_OBS];
__device__ __align__(16) bf16 g_xa_l[NB_B*NB_OBS];
__device__ __align__(16) float g_xb_f[NB_B*NB_OBS];
__device__ __align__(16) bf16 g_xb_h[NB_B*NB_OBS];
__device__ __align__(16) bf16 g_xb_l[NB_B*NB_OBS];
// value-chain activations
__device__ __align__(16) bf16 g_h2_h[NB_B*NB_HID];
__device__ __align__(16) bf16 g_h2_l[NB_B*NB_HID];
__device__ __align__(16) float g_ya_f[NB_B*NB_OBS];
__device__ __align__(16) bf16 g_ya_h[NB_B*NB_OBS];
__device__ __align__(16) bf16 g_ya_l[NB_B*NB_OBS];
__device__ __align__(16) float g_yb_f[NB_B*NB_OBS];
__device__ __align__(16) bf16 g_yb_h[NB_B*NB_OBS];
__device__ __align__(16) bf16 g_yb_l[NB_B*NB_OBS];
// latent + MoE
__device__ __align__(16) float g_lat_f[NB_B*NB_LAT];
__device__ __align__(16) bf16 g_lat_h[NB_B*NB_LAT];
__device__ __align__(16) bf16 g_lat_l[NB_B*NB_LAT];
__device__ __align__(16) float g_xea_f[NB_DISP*NB_LAT];
__device__ __align__(16) bf16 g_xea_h[NB_DISP*NB_LAT];
__device__ __align__(16) bf16 g_xea_l[NB_DISP*NB_LAT];
__device__ __align__(16) float g_xeb_f[NB_DISP*NB_LAT];
__device__ __align__(16) bf16 g_xeb_h[NB_DISP*NB_LAT];
__device__ __align__(16) bf16 g_xeb_l[NB_DISP*NB_LAT];
__device__ __align__(16) bf16 g_he_h[NB_DISP*NB_HID];
__device__ __align__(16) bf16 g_he_l[NB_DISP*NB_HID];
__device__ int   g_tokidx[NB_E*NB_B];
__device__ float g_gatew [NB_E*NB_B];
__device__ int   g_cnt[NB_E];
__device__ int   g_off[NB_E];
__device__ int   g_dtok[NB_DISP];
__device__ float g_dg  [NB_DISP];

// ---------------- PTX helpers (portable, sm_80+) ----------------
__device__ __forceinline__ uint32_t smem_u32(const void* p){ return (uint32_t)__cvta_generic_to_shared(p); }
__device__ __forceinline__ void cp16(uint32_t s, const void* g){
    asm volatile("cp.async.cg.shared.global [%0], [%1], 16;"::"r"(s),"l"(g):"memory");
}
__device__ __forceinline__ void ldm_x4(uint32_t& r0,uint32_t& r1,uint32_t& r2,uint32_t& r3,uint32_t a){
    asm volatile("ldmatrix.sync.aligned.m8n8.x4.shared.b16 {%0,%1,%2,%3},[%4];"
        :"=r"(r0),"=r"(r1),"=r"(r2),"=r"(r3):"r"(a));
}
__device__ __forceinline__ void mma16816(float* c, const uint32_t* a, const uint32_t* b){
    asm volatile("mma.sync.aligned.m16n8k16.row.col.f32.bf16.bf16.f32 "
        "{%0,%1,%2,%3},{%4,%5,%6,%7},{%8,%9},{%0,%1,%2,%3};"
        :"+f"(c[0]),"+f"(c[1]),"+f"(c[2]),"+f"(c[3])
        :"r"(a[0]),"r"(a[1]),"r"(a[2]),"r"(a[3]),"r"(b[0]),"r"(b[1]));
}

// ---------------- bf16x3 warp-MMA GEMM: C = epi(A@W^T + bias [,+R]) ----------------
// Tile 128x128, 8 warps (warp tile 64x32), 2-stage cp.async pipeline, 2 CTAs/SM.
// Inner loop streams A fragments (low register pressure, no spills).
__device__ __forceinline__ void gemm_core(
    const bf16* __restrict__ Ah, const bf16* __restrict__ Al,
    const bf16* __restrict__ Bh, const bf16* __restrict__ Bl,
    const float* __restrict__ bias, const float* __restrict__ Rf,
    float* __restrict__ Cf, bf16* __restrict__ Ch, bf16* __restrict__ Cl,
    int M, int N, int K, int epi, char* dsm)
{
    const int tid=threadIdx.x, wid=tid>>5, lane=tid&31;
    const int row0=blockIdx.y*BM, col0=blockIdx.x*BN;
    const int wm=wid>>2, wn=wid&3;                  // warp tile: 64 x 32
    const uint32_t sb0 = smem_u32(dsm);

    uint32_t soff[2]; size_t aoff[2], boff[2];
#pragma unroll
    for (int i=0;i<2;i++){
        int u=tid*2+i, row=u>>2, seg=u&3;
        soff[i]=(uint32_t)row*ROWB + (uint32_t)seg*16u;
        int ar=row0+row; if (ar>M-1) ar=M-1;
        aoff[i]=(size_t)ar*K + seg*8;
        boff[i]=(size_t)(col0+row)*K + seg*8;
    }
    const int NC = K/BK;
    auto prefetch = [&](int c){
        uint32_t st = sb0 + (uint32_t)(c&1)*STG_BYTES;
        size_t k0 = (size_t)c*BK;
#pragma unroll
        for (int i=0;i<2;i++){
            cp16(st + 0u*OP_BYTES + soff[i], Ah+aoff[i]+k0);
            cp16(st + 1u*OP_BYTES + soff[i], Al+aoff[i]+k0);
            cp16(st + 2u*OP_BYTES + soff[i], Bh+boff[i]+k0);
            cp16(st + 3u*OP_BYTES + soff[i], Bl+boff[i]+k0);
        }
        asm volatile("cp.async.commit_group;":::"memory");
    };

    // A: x4 per 16-row block
    const uint32_t a_lane = (uint32_t)(wm*64 + (lane&7) + ((lane>>3)&1)*8)*ROWB + (uint32_t)(lane>>4)*16u;
    // B: x4 covering TWO n8 blocks (bit3 -> k-half, bit4 -> next 8 rows)
    const uint32_t b_lane4 = (uint32_t)(wn*32 + (lane&7) + ((lane>>4)&1)*8)*ROWB + (uint32_t)((lane>>3)&1)*16u;

    float acc[4][4][4];
#pragma unroll
    for (int i=0;i<4;i++)
#pragma unroll
        for (int j=0;j<4;j++)
#pragma unroll
            for (int k=0;k<4;k++) acc[i][j][k]=0.f;

    prefetch(0); if (NC>1) prefetch(1);
    for (int c=0;c<NC;c++){
        if (c==NC-1) asm volatile("cp.async.wait_group 0;":::"memory");
        else         asm volatile("cp.async.wait_group 1;":::"memory");
        __syncthreads();

        uint32_t st = sb0 + (uint32_t)(c&1)*STG_BYTES;
#pragma unroll
        for (int ks=0;ks<2;ks++){
            // preload all B fragments for this k-half (16 regs live)
            uint32_t bh[4][2], blo[4][2];
#pragma unroll
            for (int np=0;np<2;np++){    // each x4 covers nt=2*np and nt=2*np+1
                uint32_t bd = st + 2u*OP_BYTES + b_lane4 + (uint32_t)np*16u*ROWB + (uint32_t)ks*32u;
                ldm_x4(bh[2*np][0], bh[2*np][1], bh[2*np+1][0], bh[2*np+1][1], bd);
                ldm_x4(blo[2*np][0],blo[2*np][1],blo[2*np+1][0],blo[2*np+1][1], bd + OP_BYTES);
            }
            // stream A fragments: only 8 A-regs live at a time
#pragma unroll
            for (int mt=0;mt<4;mt++){
                uint32_t ah[4], al[4];
                uint32_t ad = st + a_lane + (uint32_t)mt*16u*ROWB + (uint32_t)ks*32u;
                ldm_x4(ah[0],ah[1],ah[2],ah[3], ad);
                ldm_x4(al[0],al[1],al[2],al[3], ad + OP_BYTES);
#pragma unroll
                for (int nt=0;nt<4;nt++){
                    mma16816(acc[mt][nt], ah, bh[nt]);
                    mma16816(acc[mt][nt], ah, blo[nt]);
                    mma16816(acc[mt][nt], al, bh[nt]);
                }
            }
        }
        __syncthreads();
        if (c+2<NC) prefetch(c+2);   // stage (c&1) is free now
    }

    // ---------------- epilogue ----------------
    const int rbase = row0 + wm*64 + (lane>>2);
    const int cbase = col0 + wn*32 + (lane&3)*2;
#pragma unroll
    for (int mt=0;mt<4;mt++){
#pragma unroll
        for (int half=0; half<2; half++){
            const int rr = rbase + mt*16 + half*8;
            if (rr >= M) continue;
#pragma unroll
            for (int nt=0;nt<4;nt++){
                const int cc = cbase + nt*8;
                float v0 = acc[mt][nt][half*2+0] + bias[cc];
                float v1 = acc[mt][nt][half*2+1] + bias[cc+1];
                const size_t base = (size_t)rr*N + cc;
                if (epi==0){ v0=fmaxf(v0,0.f); v1=fmaxf(v1,0.f); }
                else if (epi==1){
                    float2 r2 = *(const float2*)(Rf + base);
                    v0 += r2.x; v1 += r2.y;
                }
                if (Cf){ float2 o; o.x=v0; o.y=v1; *(float2*)(Cf+base)=o; }
                if (Ch){
                    bf16 h0=__float2bfloat16(v0), h1=__float2bfloat16(v1);
                    __nv_bfloat162 th; th.x=h0; th.y=h1;
                    __nv_bfloat162 tl; tl.x=__float2bfloat16(v0-__bfloat162float(h0));
                    tl.y=__float2bfloat16(v1-__bfloat162float(h1));
                    *(__nv_bfloat162*)(Ch+base)=th;
                    *(__nv_bfloat162*)(Cl+base)=tl;
                }
            }
        }
    }
}

__global__ void __launch_bounds__(256,2)
gemm_dense(const bf16* Ah, const bf16* Al, const bf16* Bh, const bf16* Bl,
           const float* bias, const float* Rf, float* Cf, bf16* Ch, bf16* Cl,
           int M, int N, int K, int epi)
{
    extern __shared__ char dsm[];
    gemm_core(Ah,Al,Bh,Bl,bias,Rf,Cf,Ch,Cl,M,N,K,epi,dsm);
}

__global__ void __launch_bounds__(256,2)
gemm_exp(const bf16* Ah, const bf16* Al, const bf16* Wh, const bf16* Wl, long wstride,
         const float* bias, long bstride, const float* Rf, float* Cf, bf16* Ch, bf16* Cl,
         int N, int K, int epi, const int* cnt, const int* off)
{
    extern __shared__ char dsm[];
    int e = blockIdx.z, M = cnt[e];
    if ((int)(blockIdx.y*BM) >= M) return;
    size_t o = (size_t)off[e];
    gemm_core(Ah+o*K, Al+o*K, Wh+(size_t)e*wstride, Wl+(size_t)e*wstride,
              bias+(size_t)e*bstride, Rf?Rf+o*N:nullptr, Cf?Cf+o*N:nullptr,
              Ch?Ch+o*N:nullptr, Cl?Cl+o*N:nullptr, M, N, K, epi, dsm);
}

// ---------------- conversions ----------------
__global__ void conv_split(const float* __restrict__ s, bf16* __restrict__ dh, bf16* __restrict__ dl, int n4)
{
    int i = blockIdx.x*blockDim.x + threadIdx.x;
    if (i>=n4) return;
    float4 v = ((const float4*)s)[i];
    __nv_bfloat162 h0,h1,l0,l1;
    h0.x=__float2bfloat16(v.x); h0.y=__float2bfloat16(v.y);
    h1.x=__float2bfloat16(v.z); h1.y=__float2bfloat16(v.w);
    l0.x=__float2bfloat16(v.x-__bfloat162float(h0.x));
    l0.y=__float2bfloat16(v.y-__bfloat162float(h0.y));
    l1.x=__float2bfloat16(v.z-__bfloat162float(h1.x));
    l1.y=__float2bfloat16(v.w-__bfloat162float(h1.y));
    ((__nv_bfloat162*)dh)[i*2]=h0; ((__nv_bfloat162*)dh)[i*2+1]=h1;
    ((__nv_bfloat162*)dl)[i*2]=l0; ((__nv_bfloat162*)dl)[i*2+1]=l1;
}

// [mats,K,N] fp32 -> [mats,N,K] bf16 hi/lo
__global__ void transpose_conv(const float* __restrict__ src, bf16* __restrict__ dh,
                               bf16* __restrict__ dl, int K, int N)
{
    __shared__ float t[32][33];
    int m = blockIdx.z;
    const float* S = src + (size_t)m*K*N;
    bf16* DH = dh + (size_t)m*K*N;
    bf16* DL = dl + (size_t)m*K*N;
    int n0=blockIdx.x*32, k0=blockIdx.y*32, x=threadIdx.x, y0=threadIdx.y;
#pragma unroll
    for (int yy=0;yy<32;yy+=8) t[y0+yy][x] = S[(size_t)(k0+y0+yy)*N + n0 + x];
    __syncthreads();
#pragma unroll
    for (int yy=0;yy<32;yy+=8){
        float v = t[x][y0+yy];
        bf16 h = __float2bfloat16(v);
        size_t di = (size_t)(n0+y0+yy)*K + k0 + x;
        DH[di]=h; DL[di]=__float2bfloat16(v-__bfloat162float(h));
    }
}

// ---------------- MoE plumbing ----------------
__global__ void init_kernel(float* out, int* cnt)
{
    int i = blockIdx.x*blockDim.x + threadIdx.x;
    if (i<NB_E) cnt[i]=0;
    if (i<NB_B*NB_OUT){ int b=i/NB_OUT, c=i%NB_OUT; out[b*(NB_OUT+1)+c]=0.f; }
}

__global__ void __launch_bounds__(256)
gate_kernel(const float* __restrict__ lat, const float* __restrict__ wg,
            int* tokidx, float* gatew, int* cnt)
{
    __shared__ float swg[NB_LAT*NB_E];
    for (int i=threadIdx.x;i<NB_LAT*NB_E;i+=blockDim.x) swg[i]=wg[i];
    __syncthreads();
    int warp=threadIdx.x>>5, lane=threadIdx.x&31;
    int b = blockIdx.x*8 + warp;
    float acc[NB_E];
#pragma unroll
    for (int e=0;e<NB_E;e++) acc[e]=0.f;
    for (int k=lane;k<NB_LAT;k+=32){
        float x = lat[(size_t)b*NB_LAT+k];
#pragma unroll
        for (int e=0;e<NB_E;e++) acc[e]=fmaf(x,swg[k*NB_E+e],acc[e]);
    }
#pragma unroll
    for (int e=0;e<NB_E;e++)
#pragma unroll
        for (int o=16;o;o>>=1) acc[e]+=__shfl_xor_sync(0xFFFFFFFFu,acc[e],o);
    if (lane==0){
        int e0=0; float v0=acc[0];
        for (int e=1;e<NB_E;e++) if (acc[e]>v0){v0=acc[e];e0=e;}
        int e1=-1; float v1=-3.4e38f;
        for (int e=0;e<NB_E;e++) if (e!=e0 && acc[e]>v1){v1=acc[e];e1=e;}
        float w1=expf(v1-v0), s=1.f+w1, w0=1.f/s; w1/=s;
        int p0=atomicAdd(&cnt[e0],1); tokidx[e0*NB_B+p0]=b; gatew[e0*NB_B+p0]=w0;
        int p1=atomicAdd(&cnt[e1],1); tokidx[e1*NB_B+p1]=b; gatew[e1*NB_B+p1]=w1;
    }
}

__global__ void scan_kernel(const int* cnt, int* off)
{
    if (threadIdx.x==0){ int s=0; for (int e=0;e<NB_E;e++){ off[e]=s; s+=cnt[e]; } }
}

__global__ void __launch_bounds__(256)
gather_kernel(const float* __restrict__ latf, const bf16* __restrict__ lath, const bf16* __restrict__ latl,
              const int* tokidx, const float* gatew, const int* cnt, const int* off,
              float* xef, bf16* xeh, bf16* xel, int* dtok, float* dg)
{
    int e=blockIdx.x, r=blockIdx.y*8 + (threadIdx.x>>5), lane=threadIdx.x&31;
    if (r>=cnt[e]) return;
    int tok = tokidx[e*NB_B+r], dst = off[e]+r;
    const float4* sf=(const float4*)(latf+(size_t)tok*NB_LAT);
    float4* df=(float4*)(xef+(size_t)dst*NB_LAT);
#pragma unroll
    for (int i=0;i<4;i++) df[lane+32*i]=sf[lane+32*i];
    const uint4* sh_=(const uint4*)(lath+(size_t)tok*NB_LAT);
    uint4* dh_=(uint4*)(xeh+(size_t)dst*NB_LAT);
    const uint4* sl_=(const uint4*)(latl+(size_t)tok*NB_LAT);
    uint4* dl_=(uint4*)(xel+(size_t)dst*NB_LAT);
#pragma unroll
    for (int i=0;i<2;i++){ dh_[lane+32*i]=sh_[lane+32*i]; dl_[lane+32*i]=sl_[lane+32*i]; }
    if (lane==0){ dtok[dst]=tok; dg[dst]=gatew[e*NB_B+r]; }
}

__global__ void __launch_bounds__(256)
expert_final_kernel(const float* __restrict__ xe, const float* __restrict__ Wf, const float* __restrict__ bf_,
                    const int* cnt, const int* off, const int* dtok, const float* dg, float* out)
{
    int e=blockIdx.x;
    __shared__ float sW[NB_LAT*NB_OUT];
    for (int i=threadIdx.x;i<NB_LAT*NB_OUT;i+=blockDim.x) sW[i]=Wf[(size_t)e*NB_LAT*NB_OUT+i];
    __syncthreads();
    int r=blockIdx.y*8 + (threadIdx.x>>5), lane=threadIdx.x&31;
    if (r>=cnt[e]) return;
    int dst=off[e]+r;
    float acc[NB_OUT];
#pragma unroll
    for (int c=0;c<NB_OUT;c++) acc[c]=0.f;
    const float* x = xe + (size_t)dst*NB_LAT;
#pragma unroll
    for (int i=0;i<NB_LAT/32;i++){
        int k=lane+32*i; float xv=x[k];
#pragma unroll
        for (int c=0;c<NB_OUT;c++) acc[c]=fmaf(xv,sW[k*NB_OUT+c],acc[c]);
    }
#pragma unroll
    for (int c=0;c<NB_OUT;c++)
#pragma unroll
        for (int o=16;o;o>>=1) acc[c]+=__shfl_xor_sync(0xFFFFFFFFu,acc[c],o);
    if (lane==0){
        int tok=dtok[dst]; float g=dg[dst];
#pragma unroll
        for (int c=0;c<NB_OUT;c++)
            atomicAdd(&out[tok*(NB_OUT+1)+c], g*(acc[c]+bf_[e*NB_OUT+c]));
    }
}

__global__ void __launch_bounds__(256)
value_final_kernel(const float* __restrict__ xv, const float* __restrict__ Wf,
                   const float* __restrict__ bf_, float* out)
{
    int b=blockIdx.x*8 + (threadIdx.x>>5), lane=threadIdx.x&31;
    float acc=0.f;
    const float* x = xv + (size_t)b*NB_OBS;
#pragma unroll
    for (int i=0;i<NB_OBS/32;i++) acc=fmaf(x[lane+32*i],Wf[lane+32*i],acc);
#pragma unroll
    for (int o=16;o;o>>=1) acc+=__shfl_xor_sync(0xFFFFFFFFu,acc,o);
    if (lane==0) out[b*(NB_OUT+1)+NB_OUT]=acc+bf_[0];
}

__global__ void eps_kernel(float* out)
{
    int i=blockIdx.x*blockDim.x+threadIdx.x;
    if (i<NB_B*NB_OUT){
        int b=i/NB_OUT, c=i%NB_OUT;
        float* p=&out[b*(NB_OUT+1)+c];
        if (*p==0.f) *p=2.2204460492503131e-16f;
    }
}

// =====================================================================================
extern "C" void kernel_launch(void* const* d_in, const int* in_sizes, int n_in,
                              void* d_out, int out_size)
{
    const float* obs   =(const float*)d_in[0];
    const float* encW1 =(const float*)d_in[1];  const float* encb1=(const float*)d_in[2];
    const float* encW2 =(const float*)d_in[3];  const float* encb2=(const float*)d_in[4];
    const float* encWf =(const float*)d_in[5];  const float* encbf=(const float*)d_in[6];
    const float* expW1 =(const float*)d_in[7];  const float* expb1=(const float*)d_in[8];
    const float* expW2 =(const float*)d_in[9];  const float* expb2=(const float*)d_in[10];
    const float* expWf =(const float*)d_in[11]; const float* expbf=(const float*)d_in[12];
    const float* valW1 =(const float*)d_in[13]; const float* valb1=(const float*)d_in[14];
    const float* valW2 =(const float*)d_in[15]; const float* valb2=(const float*)d_in[16];
    const float* valWf =(const float*)d_in[17]; const float* valbf=(const float*)d_in[18];
    const float* wgate =(const float*)d_in[19];
    float* out=(float*)d_out;

#define SYM(T,v,s) T* v; cudaGetSymbolAddress((void**)&v, s)
    SYM(bf16,eW1h,g_encW1t_h); SYM(bf16,eW1l,g_encW1t_l);
    SYM(bf16,eW2h,g_encW2t_h); SYM(bf16,eW2l,g_encW2t_l);
    SYM(bf16,eWfh,g_encWft_h); SYM(bf16,eWfl,g_encWft_l);
    SYM(bf16,xW1h,g_expW1t_h); SYM(bf16,xW1l,g_expW1t_l);
    SYM(bf16,xW2h,g_expW2t_h); SYM(bf16,xW2l,g_expW2t_l);
    SYM(bf16,vW1h,g_valW1t_h); SYM(bf16,vW1l,g_valW1t_l);
    SYM(bf16,vW2h,g_valW2t_h); SYM(bf16,vW2l,g_valW2t_l);
    SYM(bf16,obsh,g_obs_h);    SYM(bf16,obsl,g_obs_l);
    SYM(bf16,hh,g_h_h);        SYM(bf16,hl,g_h_l);
    SYM(float,xaf,g_xa_f); SYM(bf16,xah,g_xa_h); SYM(bf16,xal,g_xa_l);
    SYM(float,xbf,g_xb_f); SYM(bf16,xbh,g_xb_h); SYM(bf16,xbl,g_xb_l);
    SYM(bf16,h2h,g_h2_h);  SYM(bf16,h2l,g_h2_l);
    SYM(float,yaf,g_ya_f); SYM(bf16,yah,g_ya_h); SYM(bf16,yal,g_ya_l);
    SYM(float,ybf,g_yb_f); SYM(bf16,ybh,g_yb_h); SYM(bf16,ybl,g_yb_l);
    SYM(float,latf,g_lat_f); SYM(bf16,lath,g_lat_h); SYM(bf16,latl,g_lat_l);
    SYM(float,xeaf,g_xea_f); SYM(bf16,xeah,g_xea_h); SYM(bf16,xeal,g_xea_l);
    SYM(float,xebf,g_xeb_f); SYM(bf16,xebh,g_xeb_h); SYM(bf16,xebl,g_xeb_l);
    SYM(bf16,heh,g_he_h);    SYM(bf16,hel,g_he_l);
    SYM(int,tokidx,g_tokidx); SYM(float,gatew,g_gatew);
    SYM(int,cnt,g_cnt); SYM(int,off,g_off); SYM(int,dtok,g_dtok); SYM(float,dg,g_dg);
#undef SYM

    cudaFuncSetAttribute(gemm_dense, cudaFuncAttributeMaxDynamicSharedMemorySize, GEMM_SMEM);
    cudaFuncSetAttribute(gemm_exp,   cudaFuncAttributeMaxDynamicSharedMemorySize, GEMM_SMEM);

    cudaStream_t s2 = g_ss.s2, s3 = g_ss.s3;
    cudaEvent_t ev0 = g_ss.ev0, ev2 = g_ss.ev2, ev3 = g_ss.ev3;

    dim3 tcb(32,8);
    dim3 gh(NB_HID/BN, NB_B/BM), go(NB_OBS/BN, NB_B/BM), gl(NB_LAT/BN, NB_B/BM);
    const size_t W1M=(size_t)NB_OBS*NB_HID;

    init_kernel<<<(NB_B*NB_OUT+255)/256, 256>>>(out, cnt);
    conv_split<<<(NB_B*NB_OBS/4+255)/256, 256>>>(obs, obsh, obsl, NB_B*NB_OBS/4);
    cudaEventRecord(ev0, 0);   // obs split done -> side chains may start

    transpose_conv<<<dim3(NB_HID/32, NB_OBS/32, NB_NB), tcb>>>(encW1, eW1h, eW1l, NB_OBS, NB_HID);
    transpose_conv<<<dim3(NB_OBS/32, NB_HID/32, NB_NB), tcb>>>(encW2, eW2h, eW2l, NB_HID, NB_OBS);
    transpose_conv<<<dim3(NB_LAT/32, NB_OBS/32, 1),     tcb>>>(encWf, eWfh, eWfl, NB_OBS, NB_LAT);

    // encoder GEMM 1
    gemm_dense<<<gh,256,GEMM_SMEM>>>(obsh,obsl, eW1h,eW1l, encb1, nullptr, nullptr, hh,hl, NB_B,NB_HID,NB_OBS,0);

    // fork side streams
    cudaStreamWaitEvent(s2, ev0, 0);
    cudaStreamWaitEvent(s3, ev0, 0);
    // s3: expert weight prep
    transpose_conv<<<dim3(NB_HID/32, NB_LAT/32, NB_E*NB_NB), tcb, 0, s3>>>(expW1, xW1h, xW1l, NB_LAT, NB_HID);
    transpose_conv<<<dim3(NB_LAT/32, NB_HID/32, NB_E*NB_NB), tcb, 0, s3>>>(expW2, xW2h, xW2l, NB_HID, NB_LAT);
    cudaEventRecord(ev3, s3);
    // s2: value weight prep + value chain
    transpose_conv<<<dim3(NB_HID/32, NB_OBS/32, NB_NB), tcb, 0, s2>>>(valW1, vW1h, vW1l, NB_OBS, NB_HID);
    transpose_conv<<<dim3(NB_OBS/32, NB_HID/32, NB_NB), tcb, 0, s2>>>(valW2, vW2h, vW2l, NB_HID, NB_OBS);
    gemm_dense<<<gh,256,GEMM_SMEM,s2>>>(obsh,obsl, vW1h,vW1l, valb1, nullptr, nullptr, h2h,h2l, NB_B,NB_HID,NB_OBS,0);
    gemm_dense<<<go,256,GEMM_SMEM,s2>>>(h2h,h2l, vW2h,vW2l, valb2, obs, yaf, yah,yal, NB_B,NB_OBS,NB_HID,1);
    gemm_dense<<<gh,256,GEMM_SMEM,s2>>>(yah,yal, vW1h+W1M,vW1l+W1M, valb1+NB_HID, nullptr, nullptr, h2h,h2l, NB_B,NB_HID,NB_OBS,0);
    gemm_dense<<<go,256,GEMM_SMEM,s2>>>(h2h,h2l, vW2h+W1M,vW2l+W1M, valb2+NB_OBS, yaf, ybf, ybh,ybl, NB_B,NB_OBS,NB_HID,1);
    gemm_dense<<<gh,256,GEMM_SMEM,s2>>>(ybh,ybl, vW1h+2*W1M,vW1l+2*W1M, valb1+2*NB_HID, nullptr, nullptr, h2h,h2l, NB_B,NB_HID,NB_OBS,0);
    // last value GEMM: bf16 outputs unused -> skip split store
    gemm_dense<<<go,256,GEMM_SMEM,s2>>>(h2h,h2l, vW2h+2*W1M,vW2l+2*W1M, valb2+2*NB_OBS, ybf, yaf, nullptr,nullptr, NB_B,NB_OBS,NB_HID,1);
    value_final_kernel<<<NB_B/8,256,0,s2>>>(yaf, valWf, valbf, out);
    cudaEventRecord(ev2, s2);

    // main: remaining encoder ResNet
    gemm_dense<<<go,256,GEMM_SMEM>>>(hh,hl, eW2h,eW2l, encb2, obs, xaf, xah,xal, NB_B,NB_OBS,NB_HID,1);
    gemm_dense<<<gh,256,GEMM_SMEM>>>(xah,xal, eW1h+W1M,eW1l+W1M, encb1+NB_HID, nullptr, nullptr, hh,hl, NB_B,NB_HID,NB_OBS,0);
    gemm_dense<<<go,256,GEMM_SMEM>>>(hh,hl, eW2h+W1M,eW2l+W1M, encb2+NB_OBS, xaf, xbf, xbh,xbl, NB_B,NB_OBS,NB_HID,1);
    gemm_dense<<<gh,256,GEMM_SMEM>>>(xbh,xbl, eW1h+2*W1M,eW1l+2*W1M, encb1+2*NB_HID, nullptr, nullptr, hh,hl, NB_B,NB_HID,NB_OBS,0);
    gemm_dense<<<go,256,GEMM_SMEM>>>(hh,hl, eW2h+2*W1M,eW2l+2*W1M, encb2+2*NB_OBS, xbf, xaf, xah,xal, NB_B,NB_OBS,NB_HID,1);
    gemm_dense<<<gl,256,GEMM_SMEM>>>(xah,xal, eWfh,eWfl, encbf, nullptr, latf, lath,latl, NB_B,NB_LAT,NB_OBS,2);

    // gating + dispatch
    gate_kernel<<<NB_B/8,256>>>(latf, wgate, tokidx, gatew, cnt);
    scan_kernel<<<1,32>>>(cnt, off);
    gather_kernel<<<dim3(NB_E,NB_B/8),256>>>(latf,lath,latl,tokidx,gatew,cnt,off,xeaf,xeah,xeal,dtok,dg);

    // join expert-weight prep before expert GEMMs
    cudaStreamWaitEvent(0, ev3, 0);

    const long w1s=(long)NB_NB*NB_LAT*NB_HID, b1s=(long)NB_NB*NB_HID;
    const long w2s=(long)NB_NB*NB_HID*NB_LAT, b2s=(long)NB_NB*NB_LAT;
    dim3 eg1(NB_HID/BN, NB_B/BM, NB_E), eg2(NB_LAT/BN, NB_B/BM, NB_E);
    float *cf=xeaf, *nf=xebf; bf16 *chh=xeah,*cll=xeal,*nhh=xebh,*nll=xebl;
    for (int blk=0;blk<NB_NB;blk++){
        gemm_exp<<<eg1,256,GEMM_SMEM>>>(chh,cll, xW1h+(size_t)blk*NB_LAT*NB_HID, xW1l+(size_t)blk*NB_LAT*NB_HID, w1s,
                                        expb1+blk*NB_HID, b1s, nullptr, nullptr, heh,hel, NB_HID,NB_LAT,0, cnt,off);
        bool last = (blk==NB_NB-1);
        gemm_exp<<<eg2,256,GEMM_SMEM>>>(heh,hel, xW2h+(size_t)blk*NB_HID*NB_LAT, xW2l+(size_t)blk*NB_HID*NB_LAT, w2s,
                                        expb2+blk*NB_LAT, b2s, cf, nf,
                                        last?nullptr:nhh, last?nullptr:nll, NB_LAT,NB_HID,1, cnt,off);
        { float* t=cf; cf=nf; nf=t; } { bf16* t=chh; chh=nhh; nhh=t; t=cll; cll=nll; nll=t; }
    }
    expert_final_kernel<<<dim3(NB_E,NB_B/8),256>>>(cf, expWf, expbf, cnt, off, dtok, dg, out);

    eps_kernel<<<(NB_B*NB_OUT+255)/256, 256>>>(out);

    // join value chain before returning
    cudaStreamWaitEvent(0, ev2, 0);
}

// round 11
// speedup vs baseline: 1.0381x; 1.0015x over previous
#include <cuda_runtime.h>
#include <cuda_bf16.h>
#include <cstdint>
#include <cstddef>

typedef __nv_bfloat16 bf16;

#define NB_B    4096
#define NB_OBS  1024
#define NB_HID  1024
#define NB_LAT  512
#define NB_OUT  19
#define NB_E    8
#define NB_NB   3
#define NB_DISP (NB_B*2)

#define BM 128
#define BN 128
#define BK 32
#define ROWB 80u                      // padded row: 32 bf16 = 64B + 16B pad
#define OP_BYTES (128u*ROWB)          // 10240
#define STG_BYTES (4u*OP_BYTES)       // 40960 (Ah,Al,Bh,Bl)
#define GEMM_SMEM (2u*STG_BYTES)      // 81920 -> 2 CTAs/SM

// ---------------- static side streams/events (created at program load) ----------
struct SideStreams {
    cudaStream_t s2, s3;
    cudaEvent_t ev0, ev2, ev3;
    SideStreams() {
        cudaStreamCreateWithFlags(&s2, cudaStreamNonBlocking);
        cudaStreamCreateWithFlags(&s3, cudaStreamNonBlocking);
        cudaEventCreateWithFlags(&ev0, cudaEventDisableTiming);
        cudaEventCreateWithFlags(&ev2, cudaEventDisableTiming);
        cudaEventCreateWithFlags(&ev3, cudaEventDisableTiming);
    }
};
static SideStreams g_ss;

// ---------------- scratch ----------------
__device__ __align__(16) bf16 g_encW1t_h[NB_NB*NB_OBS*NB_HID];
__device__ __align__(16) bf16 g_encW1t_l[NB_NB*NB_OBS*NB_HID];
__device__ __align__(16) bf16 g_encW2t_h[NB_NB*NB_HID*NB_OBS];
__device__ __align__(16) bf16 g_encW2t_l[NB_NB*NB_HID*NB_OBS];
__device__ __align__(16) bf16 g_encWft_h[NB_OBS*NB_LAT];
__device__ __align__(16) bf16 g_encWft_l[NB_OBS*NB_LAT];
__device__ __align__(16) bf16 g_expW1t_h[NB_E*NB_NB*NB_LAT*NB_HID];
__device__ __align__(16) bf16 g_expW1t_l[NB_E*NB_NB*NB_LAT*NB_HID];
__device__ __align__(16) bf16 g_expW2t_h[NB_E*NB_NB*NB_HID*NB_LAT];
__device__ __align__(16) bf16 g_expW2t_l[NB_E*NB_NB*NB_HID*NB_LAT];
__device__ __align__(16) bf16 g_valW1t_h[NB_NB*NB_OBS*NB_HID];
__device__ __align__(16) bf16 g_valW1t_l[NB_NB*NB_OBS*NB_HID];
__device__ __align__(16) bf16 g_valW2t_h[NB_NB*NB_HID*NB_OBS];
__device__ __align__(16) bf16 g_valW2t_l[NB_NB*NB_HID*NB_OBS];
__device__ __align__(16) bf16 g_obs_h[NB_B*NB_OBS];
__device__ __align__(16) bf16 g_obs_l[NB_B*NB_OBS];
// encoder-chain activations
__device__ __align__(16) bf16 g_h_h[NB_B*NB_HID];
__device__ __align__(16) bf16 g_h_l[NB_B*NB_HID];
__device__ __align__(16) float g_xa_f[NB_B*NB_OBS];
__device__ __align__(16) bf16 g_xa_h[NB_B*NB_OBS];
__device__ __align__(16) bf16 g_xa_l[NB_B*NB_OBS];
__device__ __align__(16) float g_xb_f[NB_B*NB_OBS];
__device__ __align__(16) bf16 g_xb_h[NB_B*NB_OBS];
__device__ __align__(16) bf16 g_xb_l[NB_B*NB_OBS];
// value-chain activations
__device__ __align__(16) bf16 g_h2_h[NB_B*NB_HID];
__device__ __align__(16) bf16 g_h2_l[NB_B*NB_HID];
__device__ __align__(16) float g_ya_f[NB_B*NB_OBS];
__device__ __align__(16) bf16 g_ya_h[NB_B*NB_OBS];
__device__ __align__(16) bf16 g_ya_l[NB_B*NB_OBS];
__device__ __align__(16) float g_yb_f[NB_B*NB_OBS];
__device__ __align__(16) bf16 g_yb_h[NB_B*NB_OBS];
__device__ __align__(16) bf16 g_yb_l[NB_B*NB_OBS];
// latent + MoE
__device__ __align__(16) float g_lat_f[NB_B*NB_LAT];
__device__ __align__(16) bf16 g_lat_h[NB_B*NB_LAT];
__device__ __align__(16) bf16 g_lat_l[NB_B*NB_LAT];
__device__ __align__(16) float g_xea_f[NB_DISP*NB_LAT];
__device__ __align__(16) bf16 g_xea_h[NB_DISP*NB_LAT];
__device__ __align__(16) bf16 g_xea_l[NB_DISP*NB_LAT];
__device__ __align__(16) float g_xeb_f[NB_DISP*NB_LAT];
__device__ __align__(16) bf16 g_xeb_h[NB_DISP*NB_LAT];
__device__ __align__(16) bf16 g_xeb_l[NB_DISP*NB_LAT];
__device__ __align__(16) bf16 g_he_h[NB_DISP*NB_HID];
__device__ __align__(16) bf16 g_he_l[NB_DISP*NB_HID];
__device__ int   g_tokidx[NB_E*NB_B];
__device__ float g_gatew [NB_E*NB_B];
__device__ int   g_cnt[NB_E];
__device__ int   g_off[NB_E];
__device__ int   g_dtok[NB_DISP];
__device__ float g_dg  [NB_DISP];

// ---------------- PTX helpers (portable, sm_80+) ----------------
__device__ __forceinline__ uint32_t smem_u32(const void* p){ return (uint32_t)__cvta_generic_to_shared(p); }
__device__ __forceinline__ void cp16(uint32_t s, const void* g){
    asm volatile("cp.async.cg.shared.global [%0], [%1], 16;"::"r"(s),"l"(g):"memory");
}
__device__ __forceinline__ void ldm_x4(uint32_t& r0,uint32_t& r1,uint32_t& r2,uint32_t& r3,uint32_t a){
    asm volatile("ldmatrix.sync.aligned.m8n8.x4.shared.b16 {%0,%1,%2,%3},[%4];"
        :"=r"(r0),"=r"(r1),"=r"(r2),"=r"(r3):"r"(a));
}
__device__ __forceinline__ void mma16816(float* c, const uint32_t* a, const uint32_t* b){
    asm volatile("mma.sync.aligned.m16n8k16.row.col.f32.bf16.bf16.f32 "
        "{%0,%1,%2,%3},{%4,%5,%6,%7},{%8,%9},{%0,%1,%2,%3};"
        :"+f"(c[0]),"+f"(c[1]),"+f"(c[2]),"+f"(c[3])
        :"r"(a[0]),"r"(a[1]),"r"(a[2]),"r"(a[3]),"r"(b[0]),"r"(b[1]));
}

// ---------------- bf16x3 warp-MMA GEMM: C = epi(A@W^T + bias [,+R]) ----------------
// Tile 128x128, 8 warps (warp tile 64x32), 2-stage cp.async pipeline, 2 CTAs/SM.
// Inner loop streams A fragments (low register pressure, no spills).
__device__ __forceinline__ void gemm_core(
    const bf16* __restrict__ Ah, const bf16* __restrict__ Al,
    const bf16* __restrict__ Bh, const bf16* __restrict__ Bl,
    const float* __restrict__ bias, const float* __restrict__ Rf,
    float* __restrict__ Cf, bf16* __restrict__ Ch, bf16* __restrict__ Cl,
    int M, int N, int K, int epi, char* dsm)
{
    const int tid=threadIdx.x, wid=tid>>5, lane=tid&31;
    const int row0=blockIdx.y*BM, col0=blockIdx.x*BN;
    const int wm=wid>>2, wn=wid&3;                  // warp tile: 64 x 32
    const uint32_t sb0 = smem_u32(dsm);

    uint32_t soff[2]; size_t aoff[2], boff[2];
#pragma unroll
    for (int i=0;i<2;i++){
        int u=tid*2+i, row=u>>2, seg=u&3;
        soff[i]=(uint32_t)row*ROWB + (uint32_t)seg*16u;
        int ar=row0+row; if (ar>M-1) ar=M-1;
        aoff[i]=(size_t)ar*K + seg*8;
        boff[i]=(size_t)(col0+row)*K + seg*8;
    }
    const int NC = K/BK;
    auto prefetch = [&](int c){
        uint32_t st = sb0 + (uint32_t)(c&1)*STG_BYTES;
        size_t k0 = (size_t)c*BK;
#pragma unroll
        for (int i=0;i<2;i++){
            cp16(st + 0u*OP_BYTES + soff[i], Ah+aoff[i]+k0);
            cp16(st + 1u*OP_BYTES + soff[i], Al+aoff[i]+k0);
            cp16(st + 2u*OP_BYTES + soff[i], Bh+boff[i]+k0);
            cp16(st + 3u*OP_BYTES + soff[i], Bl+boff[i]+k0);
        }
        asm volatile("cp.async.commit_group;":::"memory");
    };

    // A: x4 per 16-row block
    const uint32_t a_lane = (uint32_t)(wm*64 + (lane&7) + ((lane>>3)&1)*8)*ROWB + (uint32_t)(lane>>4)*16u;
    // B: x4 covering TWO n8 blocks (bit3 -> k-half, bit4 -> next 8 rows)
    const uint32_t b_lane4 = (uint32_t)(wn*32 + (lane&7) + ((lane>>4)&1)*8)*ROWB + (uint32_t)((lane>>3)&1)*16u;

    float acc[4][4][4];
#pragma unroll
    for (int i=0;i<4;i++)
#pragma unroll
        for (int j=0;j<4;j++)
#pragma unroll
            for (int k=0;k<4;k++) acc[i][j][k]=0.f;

    prefetch(0); if (NC>1) prefetch(1);
    for (int c=0;c<NC;c++){
        if (c==NC-1) asm volatile("cp.async.wait_group 0;":::"memory");
        else         asm volatile("cp.async.wait_group 1;":::"memory");
        __syncthreads();

        uint32_t st = sb0 + (uint32_t)(c&1)*STG_BYTES;
#pragma unroll
        for (int ks=0;ks<2;ks++){
            // preload all B fragments for this k-half (16 regs live)
            uint32_t bh[4][2], blo[4][2];
#pragma unroll
            for (int np=0;np<2;np++){    // each x4 covers nt=2*np and nt=2*np+1
                uint32_t bd = st + 2u*OP_BYTES + b_lane4 + (uint32_t)np*16u*ROWB + (uint32_t)ks*32u;
                ldm_x4(bh[2*np][0], bh[2*np][1], bh[2*np+1][0], bh[2*np+1][1], bd);
                ldm_x4(blo[2*np][0],blo[2*np][1],blo[2*np+1][0],blo[2*np+1][1], bd + OP_BYTES);
            }
            // stream A fragments: only 8 A-regs live at a time
#pragma unroll
            for (int mt=0;mt<4;mt++){
                uint32_t ah[4], al[4];
                uint32_t ad = st + a_lane + (uint32_t)mt*16u*ROWB + (uint32_t)ks*32u;
                ldm_x4(ah[0],ah[1],ah[2],ah[3], ad);
                ldm_x4(al[0],al[1],al[2],al[3], ad + OP_BYTES);
#pragma unroll
                for (int nt=0;nt<4;nt++){
                    mma16816(acc[mt][nt], ah, bh[nt]);
                    mma16816(acc[mt][nt], ah, blo[nt]);
                    mma16816(acc[mt][nt], al, bh[nt]);
                }
            }
        }
        __syncthreads();
        if (c+2<NC) prefetch(c+2);   // stage (c&1) is free now
    }

    // ---------------- epilogue ----------------
    const int rbase = row0 + wm*64 + (lane>>2);
    const int cbase = col0 + wn*32 + (lane&3)*2;
#pragma unroll
    for (int mt=0;mt<4;mt++){
#pragma unroll
        for (int half=0; half<2; half++){
            const int rr = rbase + mt*16 + half*8;
            if (rr >= M) continue;
#pragma unroll
            for (int nt=0;nt<4;nt++){
                const int cc = cbase + nt*8;
                float v0 = acc[mt][nt][half*2+0] + bias[cc];
                float v1 = acc[mt][nt][half*2+1] + bias[cc+1];
                const size_t base = (size_t)rr*N + cc;
                if (epi==0){ v0=fmaxf(v0,0.f); v1=fmaxf(v1,0.f); }
                else if (epi==1){
                    float2 r2 = *(const float2*)(Rf + base);
                    v0 += r2.x; v1 += r2.y;
                }
                if (Cf){ float2 o; o.x=v0; o.y=v1; *(float2*)(Cf+base)=o; }
                if (Ch){
                    bf16 h0=__float2bfloat16(v0), h1=__float2bfloat16(v1);
                    __nv_bfloat162 th; th.x=h0; th.y=h1;
                    __nv_bfloat162 tl; tl.x=__float2bfloat16(v0-__bfloat162float(h0));
                    tl.y=__float2bfloat16(v1-__bfloat162float(h1));
                    *(__nv_bfloat162*)(Ch+base)=th;
                    *(__nv_bfloat162*)(Cl+base)=tl;
                }
            }
        }
    }
}

__global__ void __launch_bounds__(256,2)
gemm_dense(const bf16* Ah, const bf16* Al, const bf16* Bh, const bf16* Bl,
           const float* bias, const float* Rf, float* Cf, bf16* Ch, bf16* Cl,
           int M, int N, int K, int epi)
{
    extern __shared__ char dsm[];
    gemm_core(Ah,Al,Bh,Bl,bias,Rf,Cf,Ch,Cl,M,N,K,epi,dsm);
}

__global__ void __launch_bounds__(256,2)
gemm_exp(const bf16* Ah, const bf16* Al, const bf16* Wh, const bf16* Wl, long wstride,
         const float* bias, long bstride, const float* Rf, float* Cf, bf16* Ch, bf16* Cl,
         int N, int K, int epi, const int* cnt, const int* off)
{
    extern __shared__ char dsm[];
    int e = blockIdx.z, M = cnt[e];
    if ((int)(blockIdx.y*BM) >= M) return;
    size_t o = (size_t)off[e];
    gemm_core(Ah+o*K, Al+o*K, Wh+(size_t)e*wstride, Wl+(size_t)e*wstride,
              bias+(size_t)e*bstride, Rf?Rf+o*N:nullptr, Cf?Cf+o*N:nullptr,
              Ch?Ch+o*N:nullptr, Cl?Cl+o*N:nullptr, M, N, K, epi, dsm);
}

// ---------------- conversions ----------------
__global__ void conv_split(const float* __restrict__ s, bf16* __restrict__ dh, bf16* __restrict__ dl, int n4)
{
    int i = blockIdx.x*blockDim.x + threadIdx.x;
    if (i>=n4) return;
    float4 v = ((const float4*)s)[i];
    __nv_bfloat162 h0,h1,l0,l1;
    h0.x=__float2bfloat16(v.x); h0.y=__float2bfloat16(v.y);
    h1.x=__float2bfloat16(v.z); h1.y=__float2bfloat16(v.w);
    l0.x=__float2bfloat16(v.x-__bfloat162float(h0.x));
    l0.y=__float2bfloat16(v.y-__bfloat162float(h0.y));
    l1.x=__float2bfloat16(v.z-__bfloat162float(h1.x));
    l1.y=__float2bfloat16(v.w-__bfloat162float(h1.y));
    ((__nv_bfloat162*)dh)[i*2]=h0; ((__nv_bfloat162*)dh)[i*2+1]=h1;
    ((__nv_bfloat162*)dl)[i*2]=l0; ((__nv_bfloat162*)dl)[i*2+1]=l1;
}

// [mats,K,N] fp32 -> [mats,N,K] bf16 hi/lo
__global__ void transpose_conv(const float* __restrict__ src, bf16* __restrict__ dh,
                               bf16* __restrict__ dl, int K, int N)
{
    __shared__ float t[32][33];
    int m = blockIdx.z;
    const float* S = src + (size_t)m*K*N;
    bf16* DH = dh + (size_t)m*K*N;
    bf16* DL = dl + (size_t)m*K*N;
    int n0=blockIdx.x*32, k0=blockIdx.y*32, x=threadIdx.x, y0=threadIdx.y;
#pragma unroll
    for (int yy=0;yy<32;yy+=8) t[y0+yy][x] = S[(size_t)(k0+y0+yy)*N + n0 + x];
    __syncthreads();
#pragma unroll
    for (int yy=0;yy<32;yy+=8){
        float v = t[x][y0+yy];
        bf16 h = __float2bfloat16(v);
        size_t di = (size_t)(n0+y0+yy)*K + k0 + x;
        DH[di]=h; DL[di]=__float2bfloat16(v-__bfloat162float(h));
    }
}

// ---------------- MoE plumbing ----------------
__global__ void init_kernel(float* out, int* cnt)
{
    int i = blockIdx.x*blockDim.x + threadIdx.x;
    if (i<NB_E) cnt[i]=0;
    if (i<NB_B*NB_OUT){ int b=i/NB_OUT, c=i%NB_OUT; out[b*(NB_OUT+1)+c]=0.f; }
}

__global__ void __launch_bounds__(256)
gate_kernel(const float* __restrict__ lat, const float* __restrict__ wg,
            int* tokidx, float* gatew, int* cnt)
{
    __shared__ float swg[NB_LAT*NB_E];
    for (int i=threadIdx.x;i<NB_LAT*NB_E;i+=blockDim.x) swg[i]=wg[i];
    __syncthreads();
    int warp=threadIdx.x>>5, lane=threadIdx.x&31;
    int b = blockIdx.x*8 + warp;
    float acc[NB_E];
#pragma unroll
    for (int e=0;e<NB_E;e++) acc[e]=0.f;
    for (int k=lane;k<NB_LAT;k+=32){
        float x = lat[(size_t)b*NB_LAT+k];
#pragma unroll
        for (int e=0;e<NB_E;e++) acc[e]=fmaf(x,swg[k*NB_E+e],acc[e]);
    }
#pragma unroll
    for (int e=0;e<NB_E;e++)
#pragma unroll
        for (int o=16;o;o>>=1) acc[e]+=__shfl_xor_sync(0xFFFFFFFFu,acc[e],o);
    if (lane==0){
        int e0=0; float v0=acc[0];
        for (int e=1;e<NB_E;e++) if (acc[e]>v0){v0=acc[e];e0=e;}
        int e1=-1; float v1=-3.4e38f;
        for (int e=0;e<NB_E;e++) if (e!=e0 && acc[e]>v1){v1=acc[e];e1=e;}
        float w1=expf(v1-v0), s=1.f+w1, w0=1.f/s; w1/=s;
        int p0=atomicAdd(&cnt[e0],1); tokidx[e0*NB_B+p0]=b; gatew[e0*NB_B+p0]=w0;
        int p1=atomicAdd(&cnt[e1],1); tokidx[e1*NB_B+p1]=b; gatew[e1*NB_B+p1]=w1;
    }
}

__global__ void scan_kernel(const int* cnt, int* off)
{
    if (threadIdx.x==0){ int s=0; for (int e=0;e<NB_E;e++){ off[e]=s; s+=cnt[e]; } }
}

__global__ void __launch_bounds__(256)
gather_kernel(const float* __restrict__ latf, const bf16* __restrict__ lath, const bf16* __restrict__ latl,
              const int* tokidx, const float* gatew, const int* cnt, const int* off,
              float* xef, bf16* xeh, bf16* xel, int* dtok, float* dg)
{
    int e=blockIdx.x, r=blockIdx.y*8 + (threadIdx.x>>5), lane=threadIdx.x&31;
    if (r>=cnt[e]) return;
    int tok = tokidx[e*NB_B+r], dst = off[e]+r;
    const float4* sf=(const float4*)(latf+(size_t)tok*NB_LAT);
    float4* df=(float4*)(xef+(size_t)dst*NB_LAT);
#pragma unroll
    for (int i=0;i<4;i++) df[lane+32*i]=sf[lane+32*i];
    const uint4* sh_=(const uint4*)(lath+(size_t)tok*NB_LAT);
    uint4* dh_=(uint4*)(xeh+(size_t)dst*NB_LAT);
    const uint4* sl_=(const uint4*)(latl+(size_t)tok*NB_LAT);
    uint4* dl_=(uint4*)(xel+(size_t)dst*NB_LAT);
#pragma unroll
    for (int i=0;i<2;i++){ dh_[lane+32*i]=sh_[lane+32*i]; dl_[lane+32*i]=sl_[lane+32*i]; }
    if (lane==0){ dtok[dst]=tok; dg[dst]=gatew[e*NB_B+r]; }
}

__global__ void __launch_bounds__(256)
expert_final_kernel(const float* __restrict__ xe, const float* __restrict__ Wf, const float* __restrict__ bf_,
                    const int* cnt, const int* off, const int* dtok, const float* dg, float* out)
{
    int e=blockIdx.x;
    __shared__ float sW[NB_LAT*NB_OUT];
    for (int i=threadIdx.x;i<NB_LAT*NB_OUT;i+=blockDim.x) sW[i]=Wf[(size_t)e*NB_LAT*NB_OUT+i];
    __syncthreads();
    int r=blockIdx.y*8 + (threadIdx.x>>5), lane=threadIdx.x&31;
    if (r>=cnt[e]) return;
    int dst=off[e]+r;
    float acc[NB_OUT];
#pragma unroll
    for (int c=0;c<NB_OUT;c++) acc[c]=0.f;
    const float* x = xe + (size_t)dst*NB_LAT;
#pragma unroll
    for (int i=0;i<NB_LAT/32;i++){
        int k=lane+32*i; float xv=x[k];
#pragma unroll
        for (int c=0;c<NB_OUT;c++) acc[c]=fmaf(xv,sW[k*NB_OUT+c],acc[c]);
    }
#pragma unroll
    for (int c=0;c<NB_OUT;c++)
#pragma unroll
        for (int o=16;o;o>>=1) acc[c]+=__shfl_xor_sync(0xFFFFFFFFu,acc[c],o);
    if (lane==0){
        int tok=dtok[dst]; float g=dg[dst];
#pragma unroll
        for (int c=0;c<NB_OUT;c++)
            atomicAdd(&out[tok*(NB_OUT+1)+c], g*(acc[c]+bf_[e*NB_OUT+c]));
    }
}

__global__ void __launch_bounds__(256)
value_final_kernel(const float* __restrict__ xv, const float* __restrict__ Wf,
                   const float* __restrict__ bf_, float* out)
{
    int b=blockIdx.x*8 + (threadIdx.x>>5), lane=threadIdx.x&31;
    float acc=0.f;
    const float* x = xv + (size_t)b*NB_OBS;
#pragma unroll
    for (int i=0;i<NB_OBS/32;i++) acc=fmaf(x[lane+32*i],Wf[lane+32*i],acc);
#pragma unroll
    for (int o=16;o;o>>=1) acc+=__shfl_xor_sync(0xFFFFFFFFu,acc,o);
    if (lane==0) out[b*(NB_OUT+1)+NB_OUT]=acc+bf_[0];
}

__global__ void eps_kernel(float* out)
{
    int i=blockIdx.x*blockDim.x+threadIdx.x;
    if (i<NB_B*NB_OUT){
        int b=i/NB_OUT, c=i%NB_OUT;
        float* p=&out[b*(NB_OUT+1)+c];
        if (*p==0.f) *p=2.2204460492503131e-16f;
    }
}

// =====================================================================================
extern "C" void kernel_launch(void* const* d_in, const int* in_sizes, int n_in,
                              void* d_out, int out_size)
{
    const float* obs   =(const float*)d_in[0];
    const float* encW1 =(const float*)d_in[1];  const float* encb1=(const float*)d_in[2];
    const float* encW2 =(const float*)d_in[3];  const float* encb2=(const float*)d_in[4];
    const float* encWf =(const float*)d_in[5];  const float* encbf=(const float*)d_in[6];
    const float* expW1 =(const float*)d_in[7];  const float* expb1=(const float*)d_in[8];
    const float* expW2 =(const float*)d_in[9];  const float* expb2=(const float*)d_in[10];
    const float* expWf =(const float*)d_in[11]; const float* expbf=(const float*)d_in[12];
    const float* valW1 =(const float*)d_in[13]; const float* valb1=(const float*)d_in[14];
    const float* valW2 =(const float*)d_in[15]; const float* valb2=(const float*)d_in[16];
    const float* valWf =(const float*)d_in[17]; const float* valbf=(const float*)d_in[18];
    const float* wgate =(const float*)d_in[19];
    float* out=(float*)d_out;

#define SYM(T,v,s) T* v; cudaGetSymbolAddress((void**)&v, s)
    SYM(bf16,eW1h,g_encW1t_h); SYM(bf16,eW1l,g_encW1t_l);
    SYM(bf16,eW2h,g_encW2t_h); SYM(bf16,eW2l,g_encW2t_l);
    SYM(bf16,eWfh,g_encWft_h); SYM(bf16,eWfl,g_encWft_l);
    SYM(bf16,xW1h,g_expW1t_h); SYM(bf16,xW1l,g_expW1t_l);
    SYM(bf16,xW2h,g_expW2t_h); SYM(bf16,xW2l,g_expW2t_l);
    SYM(bf16,vW1h,g_valW1t_h); SYM(bf16,vW1l,g_valW1t_l);
    SYM(bf16,vW2h,g_valW2t_h); SYM(bf16,vW2l,g_valW2t_l);
    SYM(bf16,obsh,g_obs_h);    SYM(bf16,obsl,g_obs_l);
    SYM(bf16,hh,g_h_h);        SYM(bf16,hl,g_h_l);
    SYM(float,xaf,g_xa_f); SYM(bf16,xah,g_xa_h); SYM(bf16,xal,g_xa_l);
    SYM(float,xbf,g_xb_f); SYM(bf16,xbh,g_xb_h); SYM(bf16,xbl,g_xb_l);
    SYM(bf16,h2h,g_h2_h);  SYM(bf16,h2l,g_h2_l);
    SYM(float,yaf,g_ya_f); SYM(bf16,yah,g_ya_h); SYM(bf16,yal,g_ya_l);
    SYM(float,ybf,g_yb_f); SYM(bf16,ybh,g_yb_h); SYM(bf16,ybl,g_yb_l);
    SYM(float,latf,g_lat_f); SYM(bf16,lath,g_lat_h); SYM(bf16,latl,g_lat_l);
    SYM(float,xeaf,g_xea_f); SYM(bf16,xeah,g_xea_h); SYM(bf16,xeal,g_xea_l);
    SYM(float,xebf,g_xeb_f); SYM(bf16,xebh,g_xeb_h); SYM(bf16,xebl,g_xeb_l);
    SYM(bf16,heh,g_he_h);    SYM(bf16,hel,g_he_l);
    SYM(int,tokidx,g_tokidx); SYM(float,gatew,g_gatew);
    SYM(int,cnt,g_cnt); SYM(int,off,g_off); SYM(int,dtok,g_dtok); SYM(float,dg,g_dg);
#undef SYM

    cudaFuncSetAttribute(gemm_dense, cudaFuncAttributeMaxDynamicSharedMemorySize, GEMM_SMEM);
    cudaFuncSetAttribute(gemm_exp,   cudaFuncAttributeMaxDynamicSharedMemorySize, GEMM_SMEM);

    cudaStream_t s2 = g_ss.s2, s3 = g_ss.s3;
    cudaEvent_t ev0 = g_ss.ev0, ev2 = g_ss.ev2, ev3 = g_ss.ev3;

    dim3 tcb(32,8);
    dim3 gh(NB_HID/BN, NB_B/BM), go(NB_OBS/BN, NB_B/BM), gl(NB_LAT/BN, NB_B/BM);
    const size_t W1M=(size_t)NB_OBS*NB_HID;

    init_kernel<<<(NB_B*NB_OUT+255)/256, 256>>>(out, cnt);
    conv_split<<<(NB_B*NB_OBS/4+255)/256, 256>>>(obs, obsh, obsl, NB_B*NB_OBS/4);
    cudaEventRecord(ev0, 0);   // obs split done -> side chains may start

    transpose_conv<<<dim3(NB_HID/32, NB_OBS/32, NB_NB), tcb>>>(encW1, eW1h, eW1l, NB_OBS, NB_HID);
    transpose_conv<<<dim3(NB_OBS/32, NB_HID/32, NB_NB), tcb>>>(encW2, eW2h, eW2l, NB_HID, NB_OBS);
    transpose_conv<<<dim3(NB_LAT/32, NB_OBS/32, 1),     tcb>>>(encWf, eWfh, eWfl, NB_OBS, NB_LAT);

    // encoder GEMM 1
    gemm_dense<<<gh,256,GEMM_SMEM>>>(obsh,obsl, eW1h,eW1l, encb1, nullptr, nullptr, hh,hl, NB_B,NB_HID,NB_OBS,0);

    // fork side streams
    cudaStreamWaitEvent(s2, ev0, 0);
    cudaStreamWaitEvent(s3, ev0, 0);
    // s3: expert weight prep
    transpose_conv<<<dim3(NB_HID/32, NB_LAT/32, NB_E*NB_NB), tcb, 0, s3>>>(expW1, xW1h, xW1l, NB_LAT, NB_HID);
    transpose_conv<<<dim3(NB_LAT/32, NB_HID/32, NB_E*NB_NB), tcb, 0, s3>>>(expW2, xW2h, xW2l, NB_HID, NB_LAT);
    cudaEventRecord(ev3, s3);
    // s2: value weight prep + value chain
    transpose_conv<<<dim3(NB_HID/32, NB_OBS/32, NB_NB), tcb, 0, s2>>>(valW1, vW1h, vW1l, NB_OBS, NB_HID);
    transpose_conv<<<dim3(NB_OBS/32, NB_HID/32, NB_NB), tcb, 0, s2>>>(valW2, vW2h, vW2l, NB_HID, NB_OBS);
    gemm_dense<<<gh,256,GEMM_SMEM,s2>>>(obsh,obsl, vW1h,vW1l, valb1, nullptr, nullptr, h2h,h2l, NB_B,NB_HID,NB_OBS,0);
    gemm_dense<<<go,256,GEMM_SMEM,s2>>>(h2h,h2l, vW2h,vW2l, valb2, obs, yaf, yah,yal, NB_B,NB_OBS,NB_HID,1);
    gemm_dense<<<gh,256,GEMM_SMEM,s2>>>(yah,yal, vW1h+W1M,vW1l+W1M, valb1+NB_HID, nullptr, nullptr, h2h,h2l, NB_B,NB_HID,NB_OBS,0);
    gemm_dense<<<go,256,GEMM_SMEM,s2>>>(h2h,h2l, vW2h+W1M,vW2l+W1M, valb2+NB_OBS, yaf, ybf, ybh,ybl, NB_B,NB_OBS,NB_HID,1);
    gemm_dense<<<gh,256,GEMM_SMEM,s2>>>(ybh,ybl, vW1h+2*W1M,vW1l+2*W1M, valb1+2*NB_HID, nullptr, nullptr, h2h,h2l, NB_B,NB_HID,NB_OBS,0);
    // last value GEMM: bf16 outputs unused -> skip split store
    gemm_dense<<<go,256,GEMM_SMEM,s2>>>(h2h,h2l, vW2h+2*W1M,vW2l+2*W1M, valb2+2*NB_OBS, ybf, yaf, nullptr,nullptr, NB_B,NB_OBS,NB_HID,1);
    value_final_kernel<<<NB_B/8,256,0,s2>>>(yaf, valWf, valbf, out);
    cudaEventRecord(ev2, s2);

    // main: remaining encoder ResNet
    gemm_dense<<<go,256,GEMM_SMEM>>>(hh,hl, eW2h,eW2l, encb2, obs, xaf, xah,xal, NB_B,NB_OBS,NB_HID,1);
    gemm_dense<<<gh,256,GEMM_SMEM>>>(xah,xal, eW1h+W1M,eW1l+W1M, encb1+NB_HID, nullptr, nullptr, hh,hl, NB_B,NB_HID,NB_OBS,0);
    gemm_dense<<<go,256,GEMM_SMEM>>>(hh,hl, eW2h+W1M,eW2l+W1M, encb2+NB_OBS, xaf, xbf, xbh,xbl, NB_B,NB_OBS,NB_HID,1);
    gemm_dense<<<gh,256,GEMM_SMEM>>>(xbh,xbl, eW1h+2*W1M,eW1l+2*W1M, encb1+2*NB_HID, nullptr, nullptr, hh,hl, NB_B,NB_HID,NB_OBS,0);
    gemm_dense<<<go,256,GEMM_SMEM>>>(hh,hl, eW2h+2*W1M,eW2l+2*W1M, encb2+2*NB_OBS, xbf, xaf, xah,xal, NB_B,NB_OBS,NB_HID,1);
    gemm_dense<<<gl,256,GEMM_SMEM>>>(xah,xal, eWfh,eWfl, encbf, nullptr, latf, lath,latl, NB_B,NB_LAT,NB_OBS,2);

    // gating + dispatch
    gate_kernel<<<NB_B/8,256>>>(latf, wgate, tokidx, gatew, cnt);
    scan_kernel<<<1,32>>>(cnt, off);
    gather_kernel<<<dim3(NB_E,NB_B/8),256>>>(latf,lath,latl,tokidx,gatew,cnt,off,xeaf,xeah,xeal,dtok,dg);

    // join expert-weight prep before expert GEMMs
    cudaStreamWaitEvent(0, ev3, 0);

    const long w1s=(long)NB_NB*NB_LAT*NB_HID, b1s=(long)NB_NB*NB_HID;
    const long w2s=(long)NB_NB*NB_HID*NB_LAT, b2s=(long)NB_NB*NB_LAT;
    dim3 eg1(NB_HID/BN, NB_B/BM, NB_E), eg2(NB_LAT/BN, NB_B/BM, NB_E);
    float *cf=xeaf, *nf=xebf; bf16 *chh=xeah,*cll=xeal,*nhh=xebh,*nll=xebl;
    for (int blk=0;blk<NB_NB;blk++){
        gemm_exp<<<eg1,256,GEMM_SMEM>>>(chh,cll, xW1h+(size_t)blk*NB_LAT*NB_HID, xW1l+(size_t)blk*NB_LAT*NB_HID, w1s,
                                        expb1+blk*NB_HID, b1s, nullptr, nullptr, heh,hel, NB_HID,NB_LAT,0, cnt,off);
        bool last = (blk==NB_NB-1);
        gemm_exp<<<eg2,256,GEMM_SMEM>>>(heh,hel, xW2h+(size_t)blk*NB_HID*NB_LAT, xW2l+(size_t)blk*NB_HID*NB_LAT, w2s,
                                        expb2+blk*NB_LAT, b2s, cf, nf,
                                        last?nullptr:nhh, last?nullptr:nll, NB_LAT,NB_HID,1, cnt,off);
        { float* t=cf; cf=nf; nf=t; } { bf16* t=chh; chh=nhh; nhh=t; t=cll; cll=nll; nll=t; }
    }
    expert_final_kernel<<<dim3(NB_E,NB_B/8),256>>>(cf, expWf, expbf, cnt, off, dtok, dg, out);

    eps_kernel<<<(NB_B*NB_OUT+255)/256, 256>>>(out);

    // join value chain before returning
    cudaStreamWaitEvent(0, ev2, 0);
}

// round 13
// speedup vs baseline: 1.0604x; 1.0215x over previous
#include <cuda_runtime.h>
#include <cuda_bf16.h>
#include <cstdint>
#include <cstddef>

typedef __nv_bfloat16 bf16;

#define NB_B    4096
#define NB_OBS  1024
#define NB_HID  1024
#define NB_LAT  512
#define NB_OUT  19
#define NB_E    8
#define NB_NB   3
#define NB_DISP (NB_B*2)

#define BM 128
#define BN 128
#define BK 32
#define ROWB 80u                      // padded row: 32 bf16 = 64B + 16B pad
#define OP_BYTES (128u*ROWB)          // 10240
#define STG_BYTES (4u*OP_BYTES)       // 40960 (Ah,Al,Bh,Bl)
#define GEMM_SMEM (2u*STG_BYTES)      // 81920 -> 2 CTAs/SM

// ---------------- static side streams/events (created at program load) ----------
struct SideStreams {
    cudaStream_t s2, s3;
    cudaEvent_t ev0, ev2, ev3;
    SideStreams() {
        cudaStreamCreateWithFlags(&s2, cudaStreamNonBlocking);
        cudaStreamCreateWithFlags(&s3, cudaStreamNonBlocking);
        cudaEventCreateWithFlags(&ev0, cudaEventDisableTiming);
        cudaEventCreateWithFlags(&ev2, cudaEventDisableTiming);
        cudaEventCreateWithFlags(&ev3, cudaEventDisableTiming);
    }
};
static SideStreams g_ss;

// ---------------- scratch ----------------
__device__ __align__(16) bf16 g_encW1t_h[NB_NB*NB_OBS*NB_HID];
__device__ __align__(16) bf16 g_encW1t_l[NB_NB*NB_OBS*NB_HID];
__device__ __align__(16) bf16 g_encW2t_h[NB_NB*NB_HID*NB_OBS];
__device__ __align__(16) bf16 g_encW2t_l[NB_NB*NB_HID*NB_OBS];
__device__ __align__(16) bf16 g_encWft_h[NB_OBS*NB_LAT];
__device__ __align__(16) bf16 g_encWft_l[NB_OBS*NB_LAT];
__device__ __align__(16) bf16 g_expW1t_h[NB_E*NB_NB*NB_LAT*NB_HID];
__device__ __align__(16) bf16 g_expW1t_l[NB_E*NB_NB*NB_LAT*NB_HID];
__device__ __align__(16) bf16 g_expW2t_h[NB_E*NB_NB*NB_HID*NB_LAT];
__device__ __align__(16) bf16 g_expW2t_l[NB_E*NB_NB*NB_HID*NB_LAT];
__device__ __align__(16) bf16 g_valW1t_h[NB_NB*NB_OBS*NB_HID];
__device__ __align__(16) bf16 g_valW1t_l[NB_NB*NB_OBS*NB_HID];
__device__ __align__(16) bf16 g_valW2t_h[NB_NB*NB_HID*NB_OBS];
__device__ __align__(16) bf16 g_valW2t_l[NB_NB*NB_HID*NB_OBS];
__device__ __align__(16) bf16 g_obs_h[NB_B*NB_OBS];
__device__ __align__(16) bf16 g_obs_l[NB_B*NB_OBS];
// encoder-chain activations
__device__ __align__(16) bf16 g_h_h[NB_B*NB_HID];
__device__ __align__(16) bf16 g_h_l[NB_B*NB_HID];
__device__ __align__(16) float g_xa_f[NB_B*NB_OBS];
__device__ __align__(16) bf16 g_xa_h[NB_B*NB_OBS];
__device__ __align__(16) bf16 g_xa_l[NB_B*NB_OBS];
__device__ __align__(16) float g_xb_f[NB_B*NB_OBS];
__device__ __align__(16) bf16 g_xb_h[NB_B*NB_OBS];
__device__ __align__(16) bf16 g_xb_l[NB_B*NB_OBS];
// value-chain activations
__device__ __align__(16) bf16 g_h2_h[NB_B*NB_HID];
__device__ __align__(16) bf16 g_h2_l[NB_B*NB_HID];
__device__ __align__(16) float g_ya_f[NB_B*NB_OBS];
__device__ __align__(16) bf16 g_ya_h[NB_B*NB_OBS];
__device__ __align__(16) bf16 g_ya_l[NB_B*NB_OBS];
__device__ __align__(16) float g_yb_f[NB_B*NB_OBS];
__device__ __align__(16) bf16 g_yb_h[NB_B*NB_OBS];
__device__ __align__(16) bf16 g_yb_l[NB_B*NB_OBS];
// latent + MoE
__device__ __align__(16) float g_lat_f[NB_B*NB_LAT];
__device__ __align__(16) bf16 g_lat_h[NB_B*NB_LAT];
__device__ __align__(16) bf16 g_lat_l[NB_B*NB_LAT];
__device__ __align__(16) float g_xea_f[NB_DISP*NB_LAT];
__device__ __align__(16) bf16 g_xea_h[NB_DISP*NB_LAT];
__device__ __align__(16) bf16 g_xea_l[NB_DISP*NB_LAT];
__device__ __align__(16) float g_xeb_f[NB_DISP*NB_LAT];
__device__ __align__(16) bf16 g_xeb_h[NB_DISP*NB_LAT];
__device__ __align__(16) bf16 g_xeb_l[NB_DISP*NB_LAT];
__device__ __align__(16) bf16 g_he_h[NB_DISP*NB_HID];
__device__ __align__(16) bf16 g_he_l[NB_DISP*NB_HID];
__device__ int   g_tokidx[NB_E*NB_B];
__device__ float g_gatew [NB_E*NB_B];
__device__ int   g_cnt[NB_E];
__device__ int   g_off[NB_E];
__device__ int   g_dtok[NB_DISP];
__device__ float g_dg  [NB_DISP];

// ---------------- PTX helpers (portable, sm_80+) ----------------
__device__ __forceinline__ uint32_t smem_u32(const void* p){ return (uint32_t)__cvta_generic_to_shared(p); }
__device__ __forceinline__ void cp16(uint32_t s, const void* g){
    asm volatile("cp.async.cg.shared.global [%0], [%1], 16;"::"r"(s),"l"(g):"memory");
}
__device__ __forceinline__ void ldm_x4(uint32_t& r0,uint32_t& r1,uint32_t& r2,uint32_t& r3,uint32_t a){
    asm volatile("ldmatrix.sync.aligned.m8n8.x4.shared.b16 {%0,%1,%2,%3},[%4];"
        :"=r"(r0),"=r"(r1),"=r"(r2),"=r"(r3):"r"(a));
}
__device__ __forceinline__ void mma16816(float* c, const uint32_t* a, const uint32_t* b){
    asm volatile("mma.sync.aligned.m16n8k16.row.col.f32.bf16.bf16.f32 "
        "{%0,%1,%2,%3},{%4,%5,%6,%7},{%8,%9},{%0,%1,%2,%3};"
        :"+f"(c[0]),"+f"(c[1]),"+f"(c[2]),"+f"(c[3])
        :"r"(a[0]),"r"(a[1]),"r"(a[2]),"r"(a[3]),"r"(b[0]),"r"(b[1]));
}

// ---------------- bf16x3 warp-MMA GEMM: C = epi(A@W^T + bias [,+R]) ----------------
// Tile 128x128, 8 warps (warp tile 64x32), 2-stage cp.async pipeline, 2 CTAs/SM.
// ONE barrier per chunk: the top barrier both publishes stage c's data to all
// warps and certifies that stage (c+1)&1 (read in iteration c-1) is free, so
// prefetch(c+1) can issue immediately after it and overlap the MMAs.
__device__ __forceinline__ void gemm_core(
    const bf16* __restrict__ Ah, const bf16* __restrict__ Al,
    const bf16* __restrict__ Bh, const bf16* __restrict__ Bl,
    const float* __restrict__ bias, const float* __restrict__ Rf,
    float* __restrict__ Cf, bf16* __restrict__ Ch, bf16* __restrict__ Cl,
    int M, int N, int K, int epi, char* dsm)
{
    const int tid=threadIdx.x, wid=tid>>5, lane=tid&31;
    const int row0=blockIdx.y*BM, col0=blockIdx.x*BN;
    const int wm=wid>>2, wn=wid&3;                  // warp tile: 64 x 32
    const uint32_t sb0 = smem_u32(dsm);

    uint32_t soff[2]; size_t aoff[2], boff[2];
#pragma unroll
    for (int i=0;i<2;i++){
        int u=tid*2+i, row=u>>2, seg=u&3;
        soff[i]=(uint32_t)row*ROWB + (uint32_t)seg*16u;
        int ar=row0+row; if (ar>M-1) ar=M-1;
        aoff[i]=(size_t)ar*K + seg*8;
        boff[i]=(size_t)(col0+row)*K + seg*8;
    }
    const int NC = K/BK;
    auto prefetch = [&](int c){
        uint32_t st = sb0 + (uint32_t)(c&1)*STG_BYTES;
        size_t k0 = (size_t)c*BK;
#pragma unroll
        for (int i=0;i<2;i++){
            cp16(st + 0u*OP_BYTES + soff[i], Ah+aoff[i]+k0);
            cp16(st + 1u*OP_BYTES + soff[i], Al+aoff[i]+k0);
            cp16(st + 2u*OP_BYTES + soff[i], Bh+boff[i]+k0);
            cp16(st + 3u*OP_BYTES + soff[i], Bl+boff[i]+k0);
        }
        asm volatile("cp.async.commit_group;":::"memory");
    };

    // A: x4 per 16-row block
    const uint32_t a_lane = (uint32_t)(wm*64 + (lane&7) + ((lane>>3)&1)*8)*ROWB + (uint32_t)(lane>>4)*16u;
    // B: x4 covering TWO n8 blocks (bit3 -> k-half, bit4 -> next 8 rows)
    const uint32_t b_lane4 = (uint32_t)(wn*32 + (lane&7) + ((lane>>4)&1)*8)*ROWB + (uint32_t)((lane>>3)&1)*16u;

    float acc[4][4][4];
#pragma unroll
    for (int i=0;i<4;i++)
#pragma unroll
        for (int j=0;j<4;j++)
#pragma unroll
            for (int k=0;k<4;k++) acc[i][j][k]=0.f;

    prefetch(0);
    for (int c=0;c<NC;c++){
        asm volatile("cp.async.wait_group 0;":::"memory");
        __syncthreads();
        if (c+1<NC) prefetch(c+1);   // stage (c+1)&1 was read in iter c-1; barrier above certifies it's free

        uint32_t st = sb0 + (uint32_t)(c&1)*STG_BYTES;
#pragma unroll
        for (int ks=0;ks<2;ks++){
            // preload all B fragments for this k-half (16 regs live)
            uint32_t bh[4][2], blo[4][2];
#pragma unroll
            for (int np=0;np<2;np++){    // each x4 covers nt=2*np and nt=2*np+1
                uint32_t bd = st + 2u*OP_BYTES + b_lane4 + (uint32_t)np*16u*ROWB + (uint32_t)ks*32u;
                ldm_x4(bh[2*np][0], bh[2*np][1], bh[2*np+1][0], bh[2*np+1][1], bd);
                ldm_x4(blo[2*np][0],blo[2*np][1],blo[2*np+1][0],blo[2*np+1][1], bd + OP_BYTES);
            }
            // stream A fragments: only 8 A-regs live at a time
#pragma unroll
            for (int mt=0;mt<4;mt++){
                uint32_t ah[4], al[4];
                uint32_t ad = st + a_lane + (uint32_t)mt*16u*ROWB + (uint32_t)ks*32u;
                ldm_x4(ah[0],ah[1],ah[2],ah[3], ad);
                ldm_x4(al[0],al[1],al[2],al[3], ad + OP_BYTES);
#pragma unroll
                for (int nt=0;nt<4;nt++){
                    mma16816(acc[mt][nt], ah, bh[nt]);
                    mma16816(acc[mt][nt], ah, blo[nt]);
                    mma16816(acc[mt][nt], al, bh[nt]);
                }
            }
        }
    }

    // ---------------- epilogue ----------------
    const int rbase = row0 + wm*64 + (lane>>2);
    const int cbase = col0 + wn*32 + (lane&3)*2;
#pragma unroll
    for (int mt=0;mt<4;mt++){
#pragma unroll
        for (int half=0; half<2; half++){
            const int rr = rbase + mt*16 + half*8;
            if (rr >= M) continue;
#pragma unroll
            for (int nt=0;nt<4;nt++){
                const int cc = cbase + nt*8;
                float v0 = acc[mt][nt][half*2+0] + bias[cc];
                float v1 = acc[mt][nt][half*2+1] + bias[cc+1];
                const size_t base = (size_t)rr*N + cc;
                if (epi==0){ v0=fmaxf(v0,0.f); v1=fmaxf(v1,0.f); }
                else if (epi==1){
                    float2 r2 = *(const float2*)(Rf + base);
                    v0 += r2.x; v1 += r2.y;
                }
                if (Cf){ float2 o; o.x=v0; o.y=v1; *(float2*)(Cf+base)=o; }
                if (Ch){
                    bf16 h0=__float2bfloat16(v0), h1=__float2bfloat16(v1);
                    __nv_bfloat162 th; th.x=h0; th.y=h1;
                    __nv_bfloat162 tl; tl.x=__float2bfloat16(v0-__bfloat162float(h0));
                    tl.y=__float2bfloat16(v1-__bfloat162float(h1));
                    *(__nv_bfloat162*)(Ch+base)=th;
                    *(__nv_bfloat162*)(Cl+base)=tl;
                }
            }
        }
    }
}

__global__ void __launch_bounds__(256,2)
gemm_dense(const bf16* Ah, const bf16* Al, const bf16* Bh, const bf16* Bl,
           const float* bias, const float* Rf, float* Cf, bf16* Ch, bf16* Cl,
           int M, int N, int K, int epi)
{
    extern __shared__ char dsm[];
    gemm_core(Ah,Al,Bh,Bl,bias,Rf,Cf,Ch,Cl,M,N,K,epi,dsm);
}

__global__ void __launch_bounds__(256,2)
gemm_exp(const bf16* Ah, const bf16* Al, const bf16* Wh, const bf16* Wl, long wstride,
         const float* bias, long bstride, const float* Rf, float* Cf, bf16* Ch, bf16* Cl,
         int N, int K, int epi, const int* cnt, const int* off)
{
    extern __shared__ char dsm[];
    int e = blockIdx.z, M = cnt[e];
    if ((int)(blockIdx.y*BM) >= M) return;
    size_t o = (size_t)off[e];
    gemm_core(Ah+o*K, Al+o*K, Wh+(size_t)e*wstride, Wl+(size_t)e*wstride,
              bias+(size_t)e*bstride, Rf?Rf+o*N:nullptr, Cf?Cf+o*N:nullptr,
              Ch?Ch+o*N:nullptr, Cl?Cl+o*N:nullptr, M, N, K, epi, dsm);
}

// ---------------- conversions ----------------
__global__ void conv_split(const float* __restrict__ s, bf16* __restrict__ dh, bf16* __restrict__ dl, int n4)
{
    int i = blockIdx.x*blockDim.x + threadIdx.x;
    if (i>=n4) return;
    float4 v = ((const float4*)s)[i];
    __nv_bfloat162 h0,h1,l0,l1;
    h0.x=__float2bfloat16(v.x); h0.y=__float2bfloat16(v.y);
    h1.x=__float2bfloat16(v.z); h1.y=__float2bfloat16(v.w);
    l0.x=__float2bfloat16(v.x-__bfloat162float(h0.x));
    l0.y=__float2bfloat16(v.y-__bfloat162float(h0.y));
    l1.x=__float2bfloat16(v.z-__bfloat162float(h1.x));
    l1.y=__float2bfloat16(v.w-__bfloat162float(h1.y));
    ((__nv_bfloat162*)dh)[i*2]=h0; ((__nv_bfloat162*)dh)[i*2+1]=h1;
    ((__nv_bfloat162*)dl)[i*2]=l0; ((__nv_bfloat162*)dl)[i*2+1]=l1;
}

// [mats,K,N] fp32 -> [mats,N,K] bf16 hi/lo
__global__ void transpose_conv(const float* __restrict__ src, bf16* __restrict__ dh,
                               bf16* __restrict__ dl, int K, int N)
{
    __shared__ float t[32][33];
    int m = blockIdx.z;
    const float* S = src + (size_t)m*K*N;
    bf16* DH = dh + (size_t)m*K*N;
    bf16* DL = dl + (size_t)m*K*N;
    int n0=blockIdx.x*32, k0=blockIdx.y*32, x=threadIdx.x, y0=threadIdx.y;
#pragma unroll
    for (int yy=0;yy<32;yy+=8) t[y0+yy][x] = S[(size_t)(k0+y0+yy)*N + n0 + x];
    __syncthreads();
#pragma unroll
    for (int yy=0;yy<32;yy+=8){
        float v = t[x][y0+yy];
        bf16 h = __float2bfloat16(v);
        size_t di = (size_t)(n0+y0+yy)*K + k0 + x;
        DH[di]=h; DL[di]=__float2bfloat16(v-__bfloat162float(h));
    }
}

// ---------------- MoE plumbing ----------------
__global__ void init_kernel(float* out, int* cnt)
{
    int i = blockIdx.x*blockDim.x + threadIdx.x;
    if (i<NB_E) cnt[i]=0;
    if (i<NB_B*NB_OUT){ int b=i/NB_OUT, c=i%NB_OUT; out[b*(NB_OUT+1)+c]=0.f; }
}

__global__ void __launch_bounds__(256)
gate_kernel(const float* __restrict__ lat, const float* __restrict__ wg,
            int* tokidx, float* gatew, int* cnt)
{
    __shared__ float swg[NB_LAT*NB_E];
    for (int i=threadIdx.x;i<NB_LAT*NB_E;i+=blockDim.x) swg[i]=wg[i];
    __syncthreads();
    int warp=threadIdx.x>>5, lane=threadIdx.x&31;
    int b = blockIdx.x*8 + warp;
    float acc[NB_E];
#pragma unroll
    for (int e=0;e<NB_E;e++) acc[e]=0.f;
    for (int k=lane;k<NB_LAT;k+=32){
        float x = lat[(size_t)b*NB_LAT+k];
#pragma unroll
        for (int e=0;e<NB_E;e++) acc[e]=fmaf(x,swg[k*NB_E+e],acc[e]);
    }
#pragma unroll
    for (int e=0;e<NB_E;e++)
#pragma unroll
        for (int o=16;o;o>>=1) acc[e]+=__shfl_xor_sync(0xFFFFFFFFu,acc[e],o);
    if (lane==0){
        int e0=0; float v0=acc[0];
        for (int e=1;e<NB_E;e++) if (acc[e]>v0){v0=acc[e];e0=e;}
        int e1=-1; float v1=-3.4e38f;
        for (int e=0;e<NB_E;e++) if (e!=e0 && acc[e]>v1){v1=acc[e];e1=e;}
        float w1=expf(v1-v0), s=1.f+w1, w0=1.f/s; w1/=s;
        int p0=atomicAdd(&cnt[e0],1); tokidx[e0*NB_B+p0]=b; gatew[e0*NB_B+p0]=w0;
        int p1=atomicAdd(&cnt[e1],1); tokidx[e1*NB_B+p1]=b; gatew[e1*NB_B+p1]=w1;
    }
}

__global__ void scan_kernel(const int* cnt, int* off)
{
    if (threadIdx.x==0){ int s=0; for (int e=0;e<NB_E;e++){ off[e]=s; s+=cnt[e]; } }
}

__global__ void __launch_bounds__(256)
gather_kernel(const float* __restrict__ latf, const bf16* __restrict__ lath, const bf16* __restrict__ latl,
              const int* tokidx, const float* gatew, const int* cnt, const int* off,
              float* xef, bf16* xeh, bf16* xel, int* dtok, float* dg)
{
    int e=blockIdx.x, r=blockIdx.y*8 + (threadIdx.x>>5), lane=threadIdx.x&31;
    if (r>=cnt[e]) return;
    int tok = tokidx[e*NB_B+r], dst = off[e]+r;
    const float4* sf=(const float4*)(latf+(size_t)tok*NB_LAT);
    float4* df=(float4*)(xef+(size_t)dst*NB_LAT);
#pragma unroll
    for (int i=0;i<4;i++) df[lane+32*i]=sf[lane+32*i];
    const uint4* sh_=(const uint4*)(lath+(size_t)tok*NB_LAT);
    uint4* dh_=(uint4*)(xeh+(size_t)dst*NB_LAT);
    const uint4* sl_=(const uint4*)(latl+(size_t)tok*NB_LAT);
    uint4* dl_=(uint4*)(xel+(size_t)dst*NB_LAT);
#pragma unroll
    for (int i=0;i<2;i++){ dh_[lane+32*i]=sh_[lane+32*i]; dl_[lane+32*i]=sl_[lane+32*i]; }
    if (lane==0){ dtok[dst]=tok; dg[dst]=gatew[e*NB_B+r]; }
}

__global__ void __launch_bounds__(256)
expert_final_kernel(const float* __restrict__ xe, const float* __restrict__ Wf, const float* __restrict__ bf_,
                    const int* cnt, const int* off, const int* dtok, const float* dg, float* out)
{
    int e=blockIdx.x;
    __shared__ float sW[NB_LAT*NB_OUT];
    for (int i=threadIdx.x;i<NB_LAT*NB_OUT;i+=blockDim.x) sW[i]=Wf[(size_t)e*NB_LAT*NB_OUT+i];
    __syncthreads();
    int r=blockIdx.y*8 + (threadIdx.x>>5), lane=threadIdx.x&31;
    if (r>=cnt[e]) return;
    int dst=off[e]+r;
    float acc[NB_OUT];
#pragma unroll
    for (int c=0;c<NB_OUT;c++) acc[c]=0.f;
    const float* x = xe + (size_t)dst*NB_LAT;
#pragma unroll
    for (int i=0;i<NB_LAT/32;i++){
        int k=lane+32*i; float xv=x[k];
#pragma unroll
        for (int c=0;c<NB_OUT;c++) acc[c]=fmaf(xv,sW[k*NB_OUT+c],acc[c]);
    }
#pragma unroll
    for (int c=0;c<NB_OUT;c++)
#pragma unroll
        for (int o=16;o;o>>=1) acc[c]+=__shfl_xor_sync(0xFFFFFFFFu,acc[c],o);
    if (lane==0){
        int tok=dtok[dst]; float g=dg[dst];
#pragma unroll
        for (int c=0;c<NB_OUT;c++)
            atomicAdd(&out[tok*(NB_OUT+1)+c], g*(acc[c]+bf_[e*NB_OUT+c]));
    }
}

__global__ void __launch_bounds__(256)
value_final_kernel(const float* __restrict__ xv, const float* __restrict__ Wf,
                   const float* __restrict__ bf_, float* out)
{
    int b=blockIdx.x*8 + (threadIdx.x>>5), lane=threadIdx.x&31;
    float acc=0.f;
    const float* x = xv + (size_t)b*NB_OBS;
#pragma unroll
    for (int i=0;i<NB_OBS/32;i++) acc=fmaf(x[lane+32*i],Wf[lane+32*i],acc);
#pragma unroll
    for (int o=16;o;o>>=1) acc+=__shfl_xor_sync(0xFFFFFFFFu,acc,o);
    if (lane==0) out[b*(NB_OUT+1)+NB_OUT]=acc+bf_[0];
}

__global__ void eps_kernel(float* out)
{
    int i=blockIdx.x*blockDim.x+threadIdx.x;
    if (i<NB_B*NB_OUT){
        int b=i/NB_OUT, c=i%NB_OUT;
        float* p=&out[b*(NB_OUT+1)+c];
        if (*p==0.f) *p=2.2204460492503131e-16f;
    }
}

// =====================================================================================
extern "C" void kernel_launch(void* const* d_in, const int* in_sizes, int n_in,
                              void* d_out, int out_size)
{
    const float* obs   =(const float*)d_in[0];
    const float* encW1 =(const float*)d_in[1];  const float* encb1=(const float*)d_in[2];
    const float* encW2 =(const float*)d_in[3];  const float* encb2=(const float*)d_in[4];
    const float* encWf =(const float*)d_in[5];  const float* encbf=(const float*)d_in[6];
    const float* expW1 =(const float*)d_in[7];  const float* expb1=(const float*)d_in[8];
    const float* expW2 =(const float*)d_in[9];  const float* expb2=(const float*)d_in[10];
    const float* expWf =(const float*)d_in[11]; const float* expbf=(const float*)d_in[12];
    const float* valW1 =(const float*)d_in[13]; const float* valb1=(const float*)d_in[14];
    const float* valW2 =(const float*)d_in[15]; const float* valb2=(const float*)d_in[16];
    const float* valWf =(const float*)d_in[17]; const float* valbf=(const float*)d_in[18];
    const float* wgate =(const float*)d_in[19];
    float* out=(float*)d_out;

#define SYM(T,v,s) T* v; cudaGetSymbolAddress((void**)&v, s)
    SYM(bf16,eW1h,g_encW1t_h); SYM(bf16,eW1l,g_encW1t_l);
    SYM(bf16,eW2h,g_encW2t_h); SYM(bf16,eW2l,g_encW2t_l);
    SYM(bf16,eWfh,g_encWft_h); SYM(bf16,eWfl,g_encWft_l);
    SYM(bf16,xW1h,g_expW1t_h); SYM(bf16,xW1l,g_expW1t_l);
    SYM(bf16,xW2h,g_expW2t_h); SYM(bf16,xW2l,g_expW2t_l);
    SYM(bf16,vW1h,g_valW1t_h); SYM(bf16,vW1l,g_valW1t_l);
    SYM(bf16,vW2h,g_valW2t_h); SYM(bf16,vW2l,g_valW2t_l);
    SYM(bf16,obsh,g_obs_h);    SYM(bf16,obsl,g_obs_l);
    SYM(bf16,hh,g_h_h);        SYM(bf16,hl,g_h_l);
    SYM(float,xaf,g_xa_f); SYM(bf16,xah,g_xa_h); SYM(bf16,xal,g_xa_l);
    SYM(float,xbf,g_xb_f); SYM(bf16,xbh,g_xb_h); SYM(bf16,xbl,g_xb_l);
    SYM(bf16,h2h,g_h2_h);  SYM(bf16,h2l,g_h2_l);
    SYM(float,yaf,g_ya_f); SYM(bf16,yah,g_ya_h); SYM(bf16,yal,g_ya_l);
    SYM(float,ybf,g_yb_f); SYM(bf16,ybh,g_yb_h); SYM(bf16,ybl,g_yb_l);
    SYM(float,latf,g_lat_f); SYM(bf16,lath,g_lat_h); SYM(bf16,latl,g_lat_l);
    SYM(float,xeaf,g_xea_f); SYM(bf16,xeah,g_xea_h); SYM(bf16,xeal,g_xea_l);
    SYM(float,xebf,g_xeb_f); SYM(bf16,xebh,g_xeb_h); SYM(bf16,xebl,g_xeb_l);
    SYM(bf16,heh,g_he_h);    SYM(bf16,hel,g_he_l);
    SYM(int,tokidx,g_tokidx); SYM(float,gatew,g_gatew);
    SYM(int,cnt,g_cnt); SYM(int,off,g_off); SYM(int,dtok,g_dtok); SYM(float,dg,g_dg);
#undef SYM

    cudaFuncSetAttribute(gemm_dense, cudaFuncAttributeMaxDynamicSharedMemorySize, GEMM_SMEM);
    cudaFuncSetAttribute(gemm_exp,   cudaFuncAttributeMaxDynamicSharedMemorySize, GEMM_SMEM);

    cudaStream_t s2 = g_ss.s2, s3 = g_ss.s3;
    cudaEvent_t ev0 = g_ss.ev0, ev2 = g_ss.ev2, ev3 = g_ss.ev3;

    dim3 tcb(32,8);
    dim3 gh(NB_HID/BN, NB_B/BM), go(NB_OBS/BN, NB_B/BM), gl(NB_LAT/BN, NB_B/BM);
    const size_t W1M=(size_t)NB_OBS*NB_HID;

    init_kernel<<<(NB_B*NB_OUT+255)/256, 256>>>(out, cnt);
    conv_split<<<(NB_B*NB_OBS/4+255)/256, 256>>>(obs, obsh, obsl, NB_B*NB_OBS/4);
    cudaEventRecord(ev0, 0);   // obs split done -> side chains may start

    transpose_conv<<<dim3(NB_HID/32, NB_OBS/32, NB_NB), tcb>>>(encW1, eW1h, eW1l, NB_OBS, NB_HID);
    transpose_conv<<<dim3(NB_OBS/32, NB_HID/32, NB_NB), tcb>>>(encW2, eW2h, eW2l, NB_HID, NB_OBS);
    transpose_conv<<<dim3(NB_LAT/32, NB_OBS/32, 1),     tcb>>>(encWf, eWfh, eWfl, NB_OBS, NB_LAT);

    // encoder GEMM 1
    gemm_dense<<<gh,256,GEMM_SMEM>>>(obsh,obsl, eW1h,eW1l, encb1, nullptr, nullptr, hh,hl, NB_B,NB_HID,NB_OBS,0);

    // fork side streams
    cudaStreamWaitEvent(s2, ev0, 0);
    cudaStreamWaitEvent(s3, ev0, 0);
    // s3: expert weight prep
    transpose_conv<<<dim3(NB_HID/32, NB_LAT/32, NB_E*NB_NB), tcb, 0, s3>>>(expW1, xW1h, xW1l, NB_LAT, NB_HID);
    transpose_conv<<<dim3(NB_LAT/32, NB_HID/32, NB_E*NB_NB), tcb, 0, s3>>>(expW2, xW2h, xW2l, NB_HID, NB_LAT);
    cudaEventRecord(ev3, s3);
    // s2: value weight prep + value chain
    transpose_conv<<<dim3(NB_HID/32, NB_OBS/32, NB_NB), tcb, 0, s2>>>(valW1, vW1h, vW1l, NB_OBS, NB_HID);
    transpose_conv<<<dim3(NB_OBS/32, NB_HID/32, NB_NB), tcb, 0, s2>>>(valW2, vW2h, vW2l, NB_HID, NB_OBS);
    gemm_dense<<<gh,256,GEMM_SMEM,s2>>>(obsh,obsl, vW1h,vW1l, valb1, nullptr, nullptr, h2h,h2l, NB_B,NB_HID,NB_OBS,0);
    gemm_dense<<<go,256,GEMM_SMEM,s2>>>(h2h,h2l, vW2h,vW2l, valb2, obs, yaf, yah,yal, NB_B,NB_OBS,NB_HID,1);
    gemm_dense<<<gh,256,GEMM_SMEM,s2>>>(yah,yal, vW1h+W1M,vW1l+W1M, valb1+NB_HID, nullptr, nullptr, h2h,h2l, NB_B,NB_HID,NB_OBS,0);
    gemm_dense<<<go,256,GEMM_SMEM,s2>>>(h2h,h2l, vW2h+W1M,vW2l+W1M, valb2+NB_OBS, yaf, ybf, ybh,ybl, NB_B,NB_OBS,NB_HID,1);
    gemm_dense<<<gh,256,GEMM_SMEM,s2>>>(ybh,ybl, vW1h+2*W1M,vW1l+2*W1M, valb1+2*NB_HID, nullptr, nullptr, h2h,h2l, NB_B,NB_HID,NB_OBS,0);
    // last value GEMM: bf16 outputs unused -> skip split store
    gemm_dense<<<go,256,GEMM_SMEM,s2>>>(h2h,h2l, vW2h+2*W1M,vW2l+2*W1M, valb2+2*NB_OBS, ybf, yaf, nullptr,nullptr, NB_B,NB_OBS,NB_HID,1);
    value_final_kernel<<<NB_B/8,256,0,s2>>>(yaf, valWf, valbf, out);
    cudaEventRecord(ev2, s2);

    // main: remaining encoder ResNet
    gemm_dense<<<go,256,GEMM_SMEM>>>(hh,hl, eW2h,eW2l, encb2, obs, xaf, xah,xal, NB_B,NB_OBS,NB_HID,1);
    gemm_dense<<<gh,256,GEMM_SMEM>>>(xah,xal, eW1h+W1M,eW1l+W1M, encb1+NB_HID, nullptr, nullptr, hh,hl, NB_B,NB_HID,NB_OBS,0);
    gemm_dense<<<go,256,GEMM_SMEM>>>(hh,hl, eW2h+W1M,eW2l+W1M, encb2+NB_OBS, xaf, xbf, xbh,xbl, NB_B,NB_OBS,NB_HID,1);
    gemm_dense<<<gh,256,GEMM_SMEM>>>(xbh,xbl, eW1h+2*W1M,eW1l+2*W1M, encb1+2*NB_HID, nullptr, nullptr, hh,hl, NB_B,NB_HID,NB_OBS,0);
    gemm_dense<<<go,256,GEMM_SMEM>>>(hh,hl, eW2h+2*W1M,eW2l+2*W1M, encb2+2*NB_OBS, xbf, xaf, xah,xal, NB_B,NB_OBS,NB_HID,1);
    gemm_dense<<<gl,256,GEMM_SMEM>>>(xah,xal, eWfh,eWfl, encbf, nullptr, latf, lath,latl, NB_B,NB_LAT,NB_OBS,2);

    // gating + dispatch
    gate_kernel<<<NB_B/8,256>>>(latf, wgate, tokidx, gatew, cnt);
    scan_kernel<<<1,32>>>(cnt, off);
    gather_kernel<<<dim3(NB_E,NB_B/8),256>>>(latf,lath,latl,tokidx,gatew,cnt,off,xeaf,xeah,xeal,dtok,dg);

    // join expert-weight prep before expert GEMMs
    cudaStreamWaitEvent(0, ev3, 0);

    const long w1s=(long)NB_NB*NB_LAT*NB_HID, b1s=(long)NB_NB*NB_HID;
    const long w2s=(long)NB_NB*NB_HID*NB_LAT, b2s=(long)NB_NB*NB_LAT;
    dim3 eg1(NB_HID/BN, NB_B/BM, NB_E), eg2(NB_LAT/BN, NB_B/BM, NB_E);
    float *cf=xeaf, *nf=xebf; bf16 *chh=xeah,*cll=xeal,*nhh=xebh,*nll=xebl;
    for (int blk=0;blk<NB_NB;blk++){
        gemm_exp<<<eg1,256,GEMM_SMEM>>>(chh,cll, xW1h+(size_t)blk*NB_LAT*NB_HID, xW1l+(size_t)blk*NB_LAT*NB_HID, w1s,
                                        expb1+blk*NB_HID, b1s, nullptr, nullptr, heh,hel, NB_HID,NB_LAT,0, cnt,off);
        bool last = (blk==NB_NB-1);
        gemm_exp<<<eg2,256,GEMM_SMEM>>>(heh,hel, xW2h+(size_t)blk*NB_HID*NB_LAT, xW2l+(size_t)blk*NB_HID*NB_LAT, w2s,
                                        expb2+blk*NB_LAT, b2s, cf, nf,
                                        last?nullptr:nhh, last?nullptr:nll, NB_LAT,NB_HID,1, cnt,off);
        { float* t=cf; cf=nf; nf=t; } { bf16* t=chh; chh=nhh; nhh=t; t=cll; cll=nll; nll=t; }
    }
    expert_final_kernel<<<dim3(NB_E,NB_B/8),256>>>(cf, expWf, expbf, cnt, off, dtok, dg, out);

    eps_kernel<<<(NB_B*NB_OUT+255)/256, 256>>>(out);

    // join value chain before returning
    cudaStreamWaitEvent(0, ev2, 0);
}

// round 14
// speedup vs baseline: 1.0889x; 1.0269x over previous
#include <cuda_runtime.h>
#include <cuda_bf16.h>
#include <cstdint>
#include <cstddef>

typedef __nv_bfloat16 bf16;

#define NB_B    4096
#define NB_OBS  1024
#define NB_HID  1024
#define NB_LAT  512
#define NB_OUT  19
#define NB_E    8
#define NB_NB   3
#define NB_DISP (NB_B*2)

#define BM 128
#define BN 128
#define BK 32
#define ROWB 80u                      // padded row: 32 bf16 = 64B + 16B pad
#define OP_BYTES (128u*ROWB)          // 10240
#define STG_BYTES (4u*OP_BYTES)       // 40960 (Ah,Al,Bh,Bl)
#define GEMM_SMEM (2u*STG_BYTES)      // 81920 -> 2 CTAs/SM

// ---------------- static side streams/events (created at program load) ----------
struct SideStreams {
    cudaStream_t s2, s3;
    cudaEvent_t ev0, ev2, ev3, ev4;
    SideStreams() {
        cudaStreamCreateWithFlags(&s2, cudaStreamNonBlocking);
        cudaStreamCreateWithFlags(&s3, cudaStreamNonBlocking);
        cudaEventCreateWithFlags(&ev0, cudaEventDisableTiming);
        cudaEventCreateWithFlags(&ev2, cudaEventDisableTiming);
        cudaEventCreateWithFlags(&ev3, cudaEventDisableTiming);
        cudaEventCreateWithFlags(&ev4, cudaEventDisableTiming);
    }
};
static SideStreams g_ss;

// ---------------- scratch ----------------
__device__ __align__(16) bf16 g_encW1t_h[NB_NB*NB_OBS*NB_HID];
__device__ __align__(16) bf16 g_encW1t_l[NB_NB*NB_OBS*NB_HID];
__device__ __align__(16) bf16 g_encW2t_h[NB_NB*NB_HID*NB_OBS];
__device__ __align__(16) bf16 g_encW2t_l[NB_NB*NB_HID*NB_OBS];
__device__ __align__(16) bf16 g_encWft_h[NB_OBS*NB_LAT];
__device__ __align__(16) bf16 g_encWft_l[NB_OBS*NB_LAT];
__device__ __align__(16) bf16 g_expW1t_h[NB_E*NB_NB*NB_LAT*NB_HID];
__device__ __align__(16) bf16 g_expW1t_l[NB_E*NB_NB*NB_LAT*NB_HID];
__device__ __align__(16) bf16 g_expW2t_h[NB_E*NB_NB*NB_HID*NB_LAT];
__device__ __align__(16) bf16 g_expW2t_l[NB_E*NB_NB*NB_HID*NB_LAT];
__device__ __align__(16) bf16 g_valW1t_h[NB_NB*NB_OBS*NB_HID];
__device__ __align__(16) bf16 g_valW1t_l[NB_NB*NB_OBS*NB_HID];
__device__ __align__(16) bf16 g_valW2t_h[NB_NB*NB_HID*NB_OBS];
__device__ __align__(16) bf16 g_valW2t_l[NB_NB*NB_HID*NB_OBS];
__device__ __align__(16) bf16 g_obs_h[NB_B*NB_OBS];
__device__ __align__(16) bf16 g_obs_l[NB_B*NB_OBS];
// encoder-chain activations
__device__ __align__(16) bf16 g_h_h[NB_B*NB_HID];
__device__ __align__(16) bf16 g_h_l[NB_B*NB_HID];
__device__ __align__(16) float g_xa_f[NB_B*NB_OBS];
__device__ __align__(16) bf16 g_xa_h[NB_B*NB_OBS];
__device__ __align__(16) bf16 g_xa_l[NB_B*NB_OBS];
__device__ __align__(16) float g_xb_f[NB_B*NB_OBS];
__device__ __align__(16) bf16 g_xb_h[NB_B*NB_OBS];
__device__ __align__(16) bf16 g_xb_l[NB_B*NB_OBS];
// value-chain activations
__device__ __align__(16) bf16 g_h2_h[NB_B*NB_HID];
__device__ __align__(16) bf16 g_h2_l[NB_B*NB_HID];
__device__ __align__(16) float g_ya_f[NB_B*NB_OBS];
__device__ __align__(16) bf16 g_ya_h[NB_B*NB_OBS];
__device__ __align__(16) bf16 g_ya_l[NB_B*NB_OBS];
__device__ __align__(16) float g_yb_f[NB_B*NB_OBS];
__device__ __align__(16) bf16 g_yb_h[NB_B*NB_OBS];
__device__ __align__(16) bf16 g_yb_l[NB_B*NB_OBS];
// latent + MoE
__device__ __align__(16) float g_lat_f[NB_B*NB_LAT];
__device__ __align__(16) bf16 g_lat_h[NB_B*NB_LAT];
__device__ __align__(16) bf16 g_lat_l[NB_B*NB_LAT];
__device__ __align__(16) float g_xea_f[NB_DISP*NB_LAT];
__device__ __align__(16) bf16 g_xea_h[NB_DISP*NB_LAT];
__device__ __align__(16) bf16 g_xea_l[NB_DISP*NB_LAT];
__device__ __align__(16) float g_xeb_f[NB_DISP*NB_LAT];
__device__ __align__(16) bf16 g_xeb_h[NB_DISP*NB_LAT];
__device__ __align__(16) bf16 g_xeb_l[NB_DISP*NB_LAT];
__device__ __align__(16) bf16 g_he_h[NB_DISP*NB_HID];
__device__ __align__(16) bf16 g_he_l[NB_DISP*NB_HID];
__device__ int   g_tokidx[NB_E*NB_B];
__device__ float g_gatew [NB_E*NB_B];
__device__ int   g_cnt[NB_E];
__device__ int   g_off[NB_E];
__device__ int   g_dtok[NB_DISP];
__device__ float g_dg  [NB_DISP];

// ---------------- PTX helpers (portable, sm_80+) ----------------
__device__ __forceinline__ uint32_t smem_u32(const void* p){ return (uint32_t)__cvta_generic_to_shared(p); }
__device__ __forceinline__ void cp16(uint32_t s, const void* g){
    asm volatile("cp.async.cg.shared.global [%0], [%1], 16;"::"r"(s),"l"(g):"memory");
}
__device__ __forceinline__ void ldm_x4(uint32_t& r0,uint32_t& r1,uint32_t& r2,uint32_t& r3,uint32_t a){
    asm volatile("ldmatrix.sync.aligned.m8n8.x4.shared.b16 {%0,%1,%2,%3},[%4];"
        :"=r"(r0),"=r"(r1),"=r"(r2),"=r"(r3):"r"(a));
}
__device__ __forceinline__ void mma16816(float* c, const uint32_t* a, const uint32_t* b){
    asm volatile("mma.sync.aligned.m16n8k16.row.col.f32.bf16.bf16.f32 "
        "{%0,%1,%2,%3},{%4,%5,%6,%7},{%8,%9},{%0,%1,%2,%3};"
        :"+f"(c[0]),"+f"(c[1]),"+f"(c[2]),"+f"(c[3])
        :"r"(a[0]),"r"(a[1]),"r"(a[2]),"r"(a[3]),"r"(b[0]),"r"(b[1]));
}

// ---------------- bf16x3 warp-MMA GEMM: C = epi(A@W^T + bias [,+R]) ----------------
// Tile 128x128, 8 warps (warp tile 64x32), 2-stage cp.async pipeline, 2 CTAs/SM.
// ONE barrier per chunk (publishes stage c data + certifies stage (c+1)&1 free).
__device__ __forceinline__ void gemm_core(
    const bf16* __restrict__ Ah, const bf16* __restrict__ Al,
    const bf16* __restrict__ Bh, const bf16* __restrict__ Bl,
    const float* __restrict__ bias, const float* __restrict__ Rf,
    float* __restrict__ Cf, bf16* __restrict__ Ch, bf16* __restrict__ Cl,
    int M, int N, int K, int epi, char* dsm)
{
    const int tid=threadIdx.x, wid=tid>>5, lane=tid&31;
    const int row0=blockIdx.y*BM, col0=blockIdx.x*BN;
    const int wm=wid>>2, wn=wid&3;                  // warp tile: 64 x 32
    const uint32_t sb0 = smem_u32(dsm);

    uint32_t soff[2]; size_t aoff[2], boff[2];
#pragma unroll
    for (int i=0;i<2;i++){
        int u=tid*2+i, row=u>>2, seg=u&3;
        soff[i]=(uint32_t)row*ROWB + (uint32_t)seg*16u;
        int ar=row0+row; if (ar>M-1) ar=M-1;
        aoff[i]=(size_t)ar*K + seg*8;
        boff[i]=(size_t)(col0+row)*K + seg*8;
    }
    const int NC = K/BK;
    auto prefetch = [&](int c){
        uint32_t st = sb0 + (uint32_t)(c&1)*STG_BYTES;
        size_t k0 = (size_t)c*BK;
#pragma unroll
        for (int i=0;i<2;i++){
            cp16(st + 0u*OP_BYTES + soff[i], Ah+aoff[i]+k0);
            cp16(st + 1u*OP_BYTES + soff[i], Al+aoff[i]+k0);
            cp16(st + 2u*OP_BYTES + soff[i], Bh+boff[i]+k0);
            cp16(st + 3u*OP_BYTES + soff[i], Bl+boff[i]+k0);
        }
        asm volatile("cp.async.commit_group;":::"memory");
    };

    // A: x4 per 16-row block
    const uint32_t a_lane = (uint32_t)(wm*64 + (lane&7) + ((lane>>3)&1)*8)*ROWB + (uint32_t)(lane>>4)*16u;
    // B: x4 covering TWO n8 blocks (bit3 -> k-half, bit4 -> next 8 rows)
    const uint32_t b_lane4 = (uint32_t)(wn*32 + (lane&7) + ((lane>>4)&1)*8)*ROWB + (uint32_t)((lane>>3)&1)*16u;

    float acc[4][4][4];
#pragma unroll
    for (int i=0;i<4;i++)
#pragma unroll
        for (int j=0;j<4;j++)
#pragma unroll
            for (int k=0;k<4;k++) acc[i][j][k]=0.f;

    prefetch(0);
    for (int c=0;c<NC;c++){
        asm volatile("cp.async.wait_group 0;":::"memory");
        __syncthreads();
        if (c+1<NC) prefetch(c+1);   // stage (c+1)&1 was read in iter c-1; barrier above certifies it's free

        uint32_t st = sb0 + (uint32_t)(c&1)*STG_BYTES;
#pragma unroll
        for (int ks=0;ks<2;ks++){
            // preload all B fragments for this k-half (16 regs live)
            uint32_t bh[4][2], blo[4][2];
#pragma unroll
            for (int np=0;np<2;np++){    // each x4 covers nt=2*np and nt=2*np+1
                uint32_t bd = st + 2u*OP_BYTES + b_lane4 + (uint32_t)np*16u*ROWB + (uint32_t)ks*32u;
                ldm_x4(bh[2*np][0], bh[2*np][1], bh[2*np+1][0], bh[2*np+1][1], bd);
                ldm_x4(blo[2*np][0],blo[2*np][1],blo[2*np+1][0],blo[2*np+1][1], bd + OP_BYTES);
            }
            // stream A fragments: only 8 A-regs live at a time
#pragma unroll
            for (int mt=0;mt<4;mt++){
                uint32_t ah[4], al[4];
                uint32_t ad = st + a_lane + (uint32_t)mt*16u*ROWB + (uint32_t)ks*32u;
                ldm_x4(ah[0],ah[1],ah[2],ah[3], ad);
                ldm_x4(al[0],al[1],al[2],al[3], ad + OP_BYTES);
#pragma unroll
                for (int nt=0;nt<4;nt++){
                    mma16816(acc[mt][nt], ah, bh[nt]);
                    mma16816(acc[mt][nt], ah, blo[nt]);
                    mma16816(acc[mt][nt], al, bh[nt]);
                }
            }
        }
    }

    // ---------------- epilogue ----------------
    const int rbase = row0 + wm*64 + (lane>>2);
    const int cbase = col0 + wn*32 + (lane&3)*2;
#pragma unroll
    for (int mt=0;mt<4;mt++){
#pragma unroll
        for (int half=0; half<2; half++){
            const int rr = rbase + mt*16 + half*8;
            if (rr >= M) continue;
#pragma unroll
            for (int nt=0;nt<4;nt++){
                const int cc = cbase + nt*8;
                float v0 = acc[mt][nt][half*2+0] + bias[cc];
                float v1 = acc[mt][nt][half*2+1] + bias[cc+1];
                const size_t base = (size_t)rr*N + cc;
                if (epi==0){ v0=fmaxf(v0,0.f); v1=fmaxf(v1,0.f); }
                else if (epi==1){
                    float2 r2 = *(const float2*)(Rf + base);
                    v0 += r2.x; v1 += r2.y;
                }
                if (Cf){ float2 o; o.x=v0; o.y=v1; *(float2*)(Cf+base)=o; }
                if (Ch){
                    bf16 h0=__float2bfloat16(v0), h1=__float2bfloat16(v1);
                    __nv_bfloat162 th; th.x=h0; th.y=h1;
                    __nv_bfloat162 tl; tl.x=__float2bfloat16(v0-__bfloat162float(h0));
                    tl.y=__float2bfloat16(v1-__bfloat162float(h1));
                    *(__nv_bfloat162*)(Ch+base)=th;
                    *(__nv_bfloat162*)(Cl+base)=tl;
                }
            }
        }
    }
}

__global__ void __launch_bounds__(256,2)
gemm_dense(const bf16* Ah, const bf16* Al, const bf16* Bh, const bf16* Bl,
           const float* bias, const float* Rf, float* Cf, bf16* Ch, bf16* Cl,
           int M, int N, int K, int epi)
{
    extern __shared__ char dsm[];
    gemm_core(Ah,Al,Bh,Bl,bias,Rf,Cf,Ch,Cl,M,N,K,epi,dsm);
}

__global__ void __launch_bounds__(256,2)
gemm_exp(const bf16* Ah, const bf16* Al, const bf16* Wh, const bf16* Wl, long wstride,
         const float* bias, long bstride, const float* Rf, float* Cf, bf16* Ch, bf16* Cl,
         int N, int K, int epi, const int* cnt, const int* off)
{
    extern __shared__ char dsm[];
    int e = blockIdx.z, M = cnt[e];
    if ((int)(blockIdx.y*BM) >= M) return;
    size_t o = (size_t)off[e];
    gemm_core(Ah+o*K, Al+o*K, Wh+(size_t)e*wstride, Wl+(size_t)e*wstride,
              bias+(size_t)e*bstride, Rf?Rf+o*N:nullptr, Cf?Cf+o*N:nullptr,
              Ch?Ch+o*N:nullptr, Cl?Cl+o*N:nullptr, M, N, K, epi, dsm);
}

// ---------------- conversions ----------------
__global__ void conv_split(const float* __restrict__ s, bf16* __restrict__ dh, bf16* __restrict__ dl, int n4)
{
    int i = blockIdx.x*blockDim.x + threadIdx.x;
    if (i>=n4) return;
    float4 v = ((const float4*)s)[i];
    __nv_bfloat162 h0,h1,l0,l1;
    h0.x=__float2bfloat16(v.x); h0.y=__float2bfloat16(v.y);
    h1.x=__float2bfloat16(v.z); h1.y=__float2bfloat16(v.w);
    l0.x=__float2bfloat16(v.x-__bfloat162float(h0.x));
    l0.y=__float2bfloat16(v.y-__bfloat162float(h0.y));
    l1.x=__float2bfloat16(v.z-__bfloat162float(h1.x));
    l1.y=__float2bfloat16(v.w-__bfloat162float(h1.y));
    ((__nv_bfloat162*)dh)[i*2]=h0; ((__nv_bfloat162*)dh)[i*2+1]=h1;
    ((__nv_bfloat162*)dl)[i*2]=l0; ((__nv_bfloat162*)dl)[i*2+1]=l1;
}

// [mats,K,N] fp32 -> [mats,N,K] bf16 hi/lo
__global__ void transpose_conv(const float* __restrict__ src, bf16* __restrict__ dh,
                               bf16* __restrict__ dl, int K, int N)
{
    __shared__ float t[32][33];
    int m = blockIdx.z;
    const float* S = src + (size_t)m*K*N;
    bf16* DH = dh + (size_t)m*K*N;
    bf16* DL = dl + (size_t)m*K*N;
    int n0=blockIdx.x*32, k0=blockIdx.y*32, x=threadIdx.x, y0=threadIdx.y;
#pragma unroll
    for (int yy=0;yy<32;yy+=8) t[y0+yy][x] = S[(size_t)(k0+y0+yy)*N + n0 + x];
    __syncthreads();
#pragma unroll
    for (int yy=0;yy<32;yy+=8){
        float v = t[x][y0+yy];
        bf16 h = __float2bfloat16(v);
        size_t di = (size_t)(n0+y0+yy)*K + k0 + x;
        DH[di]=h; DL[di]=__float2bfloat16(v-__bfloat162float(h));
    }
}

// ---------------- MoE plumbing ----------------
__global__ void init_kernel(float* out, int* cnt)
{
    int i = blockIdx.x*blockDim.x + threadIdx.x;
    if (i<NB_E) cnt[i]=0;
    if (i<NB_B*NB_OUT){ int b=i/NB_OUT, c=i%NB_OUT; out[b*(NB_OUT+1)+c]=0.f; }
}

__global__ void __launch_bounds__(256)
gate_kernel(const float* __restrict__ lat, const float* __restrict__ wg,
            int* tokidx, float* gatew, int* cnt)
{
    __shared__ float swg[NB_LAT*NB_E];
    for (int i=threadIdx.x;i<NB_LAT*NB_E;i+=blockDim.x) swg[i]=wg[i];
    __syncthreads();
    int warp=threadIdx.x>>5, lane=threadIdx.x&31;
    int b = blockIdx.x*8 + warp;
    float acc[NB_E];
#pragma unroll
    for (int e=0;e<NB_E;e++) acc[e]=0.f;
    for (int k=lane;k<NB_LAT;k+=32){
        float x = lat[(size_t)b*NB_LAT+k];
#pragma unroll
        for (int e=0;e<NB_E;e++) acc[e]=fmaf(x,swg[k*NB_E+e],acc[e]);
    }
#pragma unroll
    for (int e=0;e<NB_E;e++)
#pragma unroll
        for (int o=16;o;o>>=1) acc[e]+=__shfl_xor_sync(0xFFFFFFFFu,acc[e],o);
    if (lane==0){
        int e0=0; float v0=acc[0];
        for (int e=1;e<NB_E;e++) if (acc[e]>v0){v0=acc[e];e0=e;}
        int e1=-1; float v1=-3.4e38f;
        for (int e=0;e<NB_E;e++) if (e!=e0 && acc[e]>v1){v1=acc[e];e1=e;}
        float w1=expf(v1-v0), s=1.f+w1, w0=1.f/s; w1/=s;
        int p0=atomicAdd(&cnt[e0],1); tokidx[e0*NB_B+p0]=b; gatew[e0*NB_B+p0]=w0;
        int p1=atomicAdd(&cnt[e1],1); tokidx[e1*NB_B+p1]=b; gatew[e1*NB_B+p1]=w1;
    }
}

__global__ void scan_kernel(const int* cnt, int* off)
{
    if (threadIdx.x==0){ int s=0; for (int e=0;e<NB_E;e++){ off[e]=s; s+=cnt[e]; } }
}

__global__ void __launch_bounds__(256)
gather_kernel(const float* __restrict__ latf, const bf16* __restrict__ lath, const bf16* __restrict__ latl,
              const int* tokidx, const float* gatew, const int* cnt, const int* off,
              float* xef, bf16* xeh, bf16* xel, int* dtok, float* dg)
{
    int e=blockIdx.x, r=blockIdx.y*8 + (threadIdx.x>>5), lane=threadIdx.x&31;
    if (r>=cnt[e]) return;
    int tok = tokidx[e*NB_B+r], dst = off[e]+r;
    const float4* sf=(const float4*)(latf+(size_t)tok*NB_LAT);
    float4* df=(float4*)(xef+(size_t)dst*NB_LAT);
#pragma unroll
    for (int i=0;i<4;i++) df[lane+32*i]=sf[lane+32*i];
    const uint4* sh_=(const uint4*)(lath+(size_t)tok*NB_LAT);
    uint4* dh_=(uint4*)(xeh+(size_t)dst*NB_LAT);
    const uint4* sl_=(const uint4*)(latl+(size_t)tok*NB_LAT);
    uint4* dl_=(uint4*)(xel+(size_t)dst*NB_LAT);
#pragma unroll
    for (int i=0;i<2;i++){ dh_[lane+32*i]=sh_[lane+32*i]; dl_[lane+32*i]=sl_[lane+32*i]; }
    if (lane==0){ dtok[dst]=tok; dg[dst]=gatew[e*NB_B+r]; }
}

__global__ void __launch_bounds__(256)
expert_final_kernel(const float* __restrict__ xe, const float* __restrict__ Wf, const float* __restrict__ bf_,
                    const int* cnt, const int* off, const int* dtok, const float* dg, float* out)
{
    int e=blockIdx.x;
    __shared__ float sW[NB_LAT*NB_OUT];
    for (int i=threadIdx.x;i<NB_LAT*NB_OUT;i+=blockDim.x) sW[i]=Wf[(size_t)e*NB_LAT*NB_OUT+i];
    __syncthreads();
    int r=blockIdx.y*8 + (threadIdx.x>>5), lane=threadIdx.x&31;
    if (r>=cnt[e]) return;
    int dst=off[e]+r;
    float acc[NB_OUT];
#pragma unroll
    for (int c=0;c<NB_OUT;c++) acc[c]=0.f;
    const float* x = xe + (size_t)dst*NB_LAT;
#pragma unroll
    for (int i=0;i<NB_LAT/32;i++){
        int k=lane+32*i; float xv=x[k];
#pragma unroll
        for (int c=0;c<NB_OUT;c++) acc[c]=fmaf(xv,sW[k*NB_OUT+c],acc[c]);
    }
#pragma unroll
    for (int c=0;c<NB_OUT;c++)
#pragma unroll
        for (int o=16;o;o>>=1) acc[c]+=__shfl_xor_sync(0xFFFFFFFFu,acc[c],o);
    if (lane==0){
        int tok=dtok[dst]; float g=dg[dst];
#pragma unroll
        for (int c=0;c<NB_OUT;c++)
            atomicAdd(&out[tok*(NB_OUT+1)+c], g*(acc[c]+bf_[e*NB_OUT+c]));
    }
}

__global__ void __launch_bounds__(256)
value_final_kernel(const float* __restrict__ xv, const float* __restrict__ Wf,
                   const float* __restrict__ bf_, float* out)
{
    int b=blockIdx.x*8 + (threadIdx.x>>5), lane=threadIdx.x&31;
    float acc=0.f;
    const float* x = xv + (size_t)b*NB_OBS;
#pragma unroll
    for (int i=0;i<NB_OBS/32;i++) acc=fmaf(x[lane+32*i],Wf[lane+32*i],acc);
#pragma unroll
    for (int o=16;o;o>>=1) acc+=__shfl_xor_sync(0xFFFFFFFFu,acc,o);
    if (lane==0) out[b*(NB_OUT+1)+NB_OUT]=acc+bf_[0];
}

__global__ void eps_kernel(float* out)
{
    int i=blockIdx.x*blockDim.x+threadIdx.x;
    if (i<NB_B*NB_OUT){
        int b=i/NB_OUT, c=i%NB_OUT;
        float* p=&out[b*(NB_OUT+1)+c];
        if (*p==0.f) *p=2.2204460492503131e-16f;
    }
}

// =====================================================================================
extern "C" void kernel_launch(void* const* d_in, const int* in_sizes, int n_in,
                              void* d_out, int out_size)
{
    const float* obs   =(const float*)d_in[0];
    const float* encW1 =(const float*)d_in[1];  const float* encb1=(const float*)d_in[2];
    const float* encW2 =(const float*)d_in[3];  const float* encb2=(const float*)d_in[4];
    const float* encWf =(const float*)d_in[5];  const float* encbf=(const float*)d_in[6];
    const float* expW1 =(const float*)d_in[7];  const float* expb1=(const float*)d_in[8];
    const float* expW2 =(const float*)d_in[9];  const float* expb2=(const float*)d_in[10];
    const float* expWf =(const float*)d_in[11]; const float* expbf=(const float*)d_in[12];
    const float* valW1 =(const float*)d_in[13]; const float* valb1=(const float*)d_in[14];
    const float* valW2 =(const float*)d_in[15]; const float* valb2=(const float*)d_in[16];
    const float* valWf =(const float*)d_in[17]; const float* valbf=(const float*)d_in[18];
    const float* wgate =(const float*)d_in[19];
    float* out=(float*)d_out;

#define SYM(T,v,s) T* v; cudaGetSymbolAddress((void**)&v, s)
    SYM(bf16,eW1h,g_encW1t_h); SYM(bf16,eW1l,g_encW1t_l);
    SYM(bf16,eW2h,g_encW2t_h); SYM(bf16,eW2l,g_encW2t_l);
    SYM(bf16,eWfh,g_encWft_h); SYM(bf16,eWfl,g_encWft_l);
    SYM(bf16,xW1h,g_expW1t_h); SYM(bf16,xW1l,g_expW1t_l);
    SYM(bf16,xW2h,g_expW2t_h); SYM(bf16,xW2l,g_expW2t_l);
    SYM(bf16,vW1h,g_valW1t_h); SYM(bf16,vW1l,g_valW1t_l);
    SYM(bf16,vW2h,g_valW2t_h); SYM(bf16,vW2l,g_valW2t_l);
    SYM(bf16,obsh,g_obs_h);    SYM(bf16,obsl,g_obs_l);
    SYM(bf16,hh,g_h_h);        SYM(bf16,hl,g_h_l);
    SYM(float,xaf,g_xa_f); SYM(bf16,xah,g_xa_h); SYM(bf16,xal,g_xa_l);
    SYM(float,xbf,g_xb_f); SYM(bf16,xbh,g_xb_h); SYM(bf16,xbl,g_xb_l);
    SYM(bf16,h2h,g_h2_h);  SYM(bf16,h2l,g_h2_l);
    SYM(float,yaf,g_ya_f); SYM(bf16,yah,g_ya_h); SYM(bf16,yal,g_ya_l);
    SYM(float,ybf,g_yb_f); SYM(bf16,ybh,g_yb_h); SYM(bf16,ybl,g_yb_l);
    SYM(float,latf,g_lat_f); SYM(bf16,lath,g_lat_h); SYM(bf16,latl,g_lat_l);
    SYM(float,xeaf,g_xea_f); SYM(bf16,xeah,g_xea_h); SYM(bf16,xeal,g_xea_l);
    SYM(float,xebf,g_xeb_f); SYM(bf16,xebh,g_xeb_h); SYM(bf16,xebl,g_xeb_l);
    SYM(bf16,heh,g_he_h);    SYM(bf16,hel,g_he_l);
    SYM(int,tokidx,g_tokidx); SYM(float,gatew,g_gatew);
    SYM(int,cnt,g_cnt); SYM(int,off,g_off); SYM(int,dtok,g_dtok); SYM(float,dg,g_dg);
#undef SYM

    cudaFuncSetAttribute(gemm_dense, cudaFuncAttributeMaxDynamicSharedMemorySize, GEMM_SMEM);
    cudaFuncSetAttribute(gemm_exp,   cudaFuncAttributeMaxDynamicSharedMemorySize, GEMM_SMEM);

    cudaStream_t s2 = g_ss.s2, s3 = g_ss.s3;
    cudaEvent_t ev0 = g_ss.ev0, ev2 = g_ss.ev2, ev3 = g_ss.ev3, ev4 = g_ss.ev4;

    dim3 tcb(32,8);
    dim3 gh(NB_HID/BN, NB_B/BM), go(NB_OBS/BN, NB_B/BM), gl(NB_LAT/BN, NB_B/BM);
    const size_t W1M=(size_t)NB_OBS*NB_HID;

    init_kernel<<<(NB_B*NB_OUT+255)/256, 256>>>(out, cnt);
    conv_split<<<(NB_B*NB_OBS/4+255)/256, 256>>>(obs, obsh, obsl, NB_B*NB_OBS/4);
    cudaEventRecord(ev0, 0);   // obs split done -> side chains may start

    // main: only encW1 transpose blocks encoder GEMM1
    transpose_conv<<<dim3(NB_HID/32, NB_OBS/32, NB_NB), tcb>>>(encW1, eW1h, eW1l, NB_OBS, NB_HID);
    gemm_dense<<<gh,256,GEMM_SMEM>>>(obsh,obsl, eW1h,eW1l, encb1, nullptr, nullptr, hh,hl, NB_B,NB_HID,NB_OBS,0);

    // fork side streams
    cudaStreamWaitEvent(s2, ev0, 0);
    cudaStreamWaitEvent(s3, ev0, 0);
    // s3: encW2/encWf prep (hides under encoder GEMM1) then expert weight prep
    transpose_conv<<<dim3(NB_OBS/32, NB_HID/32, NB_NB), tcb, 0, s3>>>(encW2, eW2h, eW2l, NB_HID, NB_OBS);
    transpose_conv<<<dim3(NB_LAT/32, NB_OBS/32, 1),     tcb, 0, s3>>>(encWf, eWfh, eWfl, NB_OBS, NB_LAT);
    cudaEventRecord(ev4, s3);
    transpose_conv<<<dim3(NB_HID/32, NB_LAT/32, NB_E*NB_NB), tcb, 0, s3>>>(expW1, xW1h, xW1l, NB_LAT, NB_HID);
    transpose_conv<<<dim3(NB_LAT/32, NB_HID/32, NB_E*NB_NB), tcb, 0, s3>>>(expW2, xW2h, xW2l, NB_HID, NB_LAT);
    cudaEventRecord(ev3, s3);
    // s2: value weight prep + value chain
    transpose_conv<<<dim3(NB_HID/32, NB_OBS/32, NB_NB), tcb, 0, s2>>>(valW1, vW1h, vW1l, NB_OBS, NB_HID);
    transpose_conv<<<dim3(NB_OBS/32, NB_HID/32, NB_NB), tcb, 0, s2>>>(valW2, vW2h, vW2l, NB_HID, NB_OBS);
    gemm_dense<<<gh,256,GEMM_SMEM,s2>>>(obsh,obsl, vW1h,vW1l, valb1, nullptr, nullptr, h2h,h2l, NB_B,NB_HID,NB_OBS,0);
    gemm_dense<<<go,256,GEMM_SMEM,s2>>>(h2h,h2l, vW2h,vW2l, valb2, obs, yaf, yah,yal, NB_B,NB_OBS,NB_HID,1);
    gemm_dense<<<gh,256,GEMM_SMEM,s2>>>(yah,yal, vW1h+W1M,vW1l+W1M, valb1+NB_HID, nullptr, nullptr, h2h,h2l, NB_B,NB_HID,NB_OBS,0);
    gemm_dense<<<go,256,GEMM_SMEM,s2>>>(h2h,h2l, vW2h+W1M,vW2l+W1M, valb2+NB_OBS, yaf, ybf, ybh,ybl, NB_B,NB_OBS,NB_HID,1);
    gemm_dense<<<gh,256,GEMM_SMEM,s2>>>(ybh,ybl, vW1h+2*W1M,vW1l+2*W1M, valb1+2*NB_HID, nullptr, nullptr, h2h,h2l, NB_B,NB_HID,NB_OBS,0);
    // last value GEMM: bf16 outputs unused -> skip split store
    gemm_dense<<<go,256,GEMM_SMEM,s2>>>(h2h,h2l, vW2h+2*W1M,vW2l+2*W1M, valb2+2*NB_OBS, ybf, yaf, nullptr,nullptr, NB_B,NB_OBS,NB_HID,1);
    value_final_kernel<<<NB_B/8,256,0,s2>>>(yaf, valWf, valbf, out);
    cudaEventRecord(ev2, s2);

    // main: wait for encW2/encWf prep (hidden under GEMM1), then remaining encoder ResNet
    cudaStreamWaitEvent(0, ev4, 0);
    gemm_dense<<<go,256,GEMM_SMEM>>>(hh,hl, eW2h,eW2l, encb2, obs, xaf, xah,xal, NB_B,NB_OBS,NB_HID,1);
    gemm_dense<<<gh,256,GEMM_SMEM>>>(xah,xal, eW1h+W1M,eW1l+W1M, encb1+NB_HID, nullptr, nullptr, hh,hl, NB_B,NB_HID,NB_OBS,0);
    gemm_dense<<<go,256,GEMM_SMEM>>>(hh,hl, eW2h+W1M,eW2l+W1M, encb2+NB_OBS, xaf, xbf, xbh,xbl, NB_B,NB_OBS,NB_HID,1);
    gemm_dense<<<gh,256,GEMM_SMEM>>>(xbh,xbl, eW1h+2*W1M,eW1l+2*W1M, encb1+2*NB_HID, nullptr, nullptr, hh,hl, NB_B,NB_HID,NB_OBS,0);
    gemm_dense<<<go,256,GEMM_SMEM>>>(hh,hl, eW2h+2*W1M,eW2l+2*W1M, encb2+2*NB_OBS, xbf, xaf, xah,xal, NB_B,NB_OBS,NB_HID,1);
    gemm_dense<<<gl,256,GEMM_SMEM>>>(xah,xal, eWfh,eWfl, encbf, nullptr, latf, lath,latl, NB_B,NB_LAT,NB_OBS,2);

    // gating + dispatch
    gate_kernel<<<NB_B/8,256>>>(latf, wgate, tokidx, gatew, cnt);
    scan_kernel<<<1,32>>>(cnt, off);
    gather_kernel<<<dim3(NB_E,NB_B/8),256>>>(latf,lath,latl,tokidx,gatew,cnt,off,xeaf,xeah,xeal,dtok,dg);

    // join expert-weight prep before expert GEMMs
    cudaStreamWaitEvent(0, ev3, 0);

    const long w1s=(long)NB_NB*NB_LAT*NB_HID, b1s=(long)NB_NB*NB_HID;
    const long w2s=(long)NB_NB*NB_HID*NB_LAT, b2s=(long)NB_NB*NB_LAT;
    dim3 eg1(NB_HID/BN, NB_B/BM, NB_E), eg2(NB_LAT/BN, NB_B/BM, NB_E);
    float *cf=xeaf, *nf=xebf; bf16 *chh=xeah,*cll=xeal,*nhh=xebh,*nll=xebl;
    for (int blk=0;blk<NB_NB;blk++){
        gemm_exp<<<eg1,256,GEMM_SMEM>>>(chh,cll, xW1h+(size_t)blk*NB_LAT*NB_HID, xW1l+(size_t)blk*NB_LAT*NB_HID, w1s,
                                        expb1+blk*NB_HID, b1s, nullptr, nullptr, heh,hel, NB_HID,NB_LAT,0, cnt,off);
        bool last = (blk==NB_NB-1);
        gemm_exp<<<eg2,256,GEMM_SMEM>>>(heh,hel, xW2h+(size_t)blk*NB_HID*NB_LAT, xW2l+(size_t)blk*NB_HID*NB_LAT, w2s,
                                        expb2+blk*NB_LAT, b2s, cf, nf,
                                        last?nullptr:nhh, last?nullptr:nll, NB_LAT,NB_HID,1, cnt,off);
        { float* t=cf; cf=nf; nf=t; } { bf16* t=chh; chh=nhh; nhh=t; t=cll; cll=nll; nll=t; }
    }
    expert_final_kernel<<<dim3(NB_E,NB_B/8),256>>>(cf, expWf, expbf, cnt, off, dtok, dg, out);

    eps_kernel<<<(NB_B*NB_OUT+255)/256, 256>>>(out);

    // join value chain before returning
    cudaStreamWaitEvent(0, ev2, 0);
}

// round 15
// speedup vs baseline: 1.1093x; 1.0187x over previous
#include <cuda_runtime.h>
#include <cuda_bf16.h>
#include <cstdint>
#include <cstddef>

typedef __nv_bfloat16 bf16;

#define NB_B    4096
#define NB_OBS  1024
#define NB_HID  1024
#define NB_LAT  512
#define NB_OUT  19
#define NB_E    8
#define NB_NB   3
#define NB_DISP (NB_B*2)

#define BM 128
#define BN 128
#define BK 32
#define ROWB 80u                      // padded row: 32 bf16 = 64B + 16B pad
#define OP_BYTES (128u*ROWB)          // 10240
#define STG_BYTES (4u*OP_BYTES)       // 40960 (Ah,Al,Bh,Bl)
#define GEMM_SMEM (2u*STG_BYTES)      // 81920 -> 2 CTAs/SM

// ---------------- static side streams/events (created at program load) ----------
struct SideStreams {
    cudaStream_t s2, s3;
    cudaEvent_t ev0, ev2, ev3, ev4;
    SideStreams() {
        cudaStreamCreateWithFlags(&s2, cudaStreamNonBlocking);
        cudaStreamCreateWithFlags(&s3, cudaStreamNonBlocking);
        cudaEventCreateWithFlags(&ev0, cudaEventDisableTiming);
        cudaEventCreateWithFlags(&ev2, cudaEventDisableTiming);
        cudaEventCreateWithFlags(&ev3, cudaEventDisableTiming);
        cudaEventCreateWithFlags(&ev4, cudaEventDisableTiming);
    }
};
static SideStreams g_ss;

// ---------------- scratch ----------------
__device__ __align__(16) bf16 g_encW1t_h[NB_NB*NB_OBS*NB_HID];
__device__ __align__(16) bf16 g_encW1t_l[NB_NB*NB_OBS*NB_HID];
__device__ __align__(16) bf16 g_encW2t_h[NB_NB*NB_HID*NB_OBS];
__device__ __align__(16) bf16 g_encW2t_l[NB_NB*NB_HID*NB_OBS];
__device__ __align__(16) bf16 g_encWft_h[NB_OBS*NB_LAT];
__device__ __align__(16) bf16 g_encWft_l[NB_OBS*NB_LAT];
__device__ __align__(16) bf16 g_expW1t_h[NB_E*NB_NB*NB_LAT*NB_HID];
__device__ __align__(16) bf16 g_expW1t_l[NB_E*NB_NB*NB_LAT*NB_HID];
__device__ __align__(16) bf16 g_expW2t_h[NB_E*NB_NB*NB_HID*NB_LAT];
__device__ __align__(16) bf16 g_expW2t_l[NB_E*NB_NB*NB_HID*NB_LAT];
__device__ __align__(16) bf16 g_valW1t_h[NB_NB*NB_OBS*NB_HID];
__device__ __align__(16) bf16 g_valW1t_l[NB_NB*NB_OBS*NB_HID];
__device__ __align__(16) bf16 g_valW2t_h[NB_NB*NB_HID*NB_OBS];
__device__ __align__(16) bf16 g_valW2t_l[NB_NB*NB_HID*NB_OBS];
__device__ __align__(16) bf16 g_obs_h[NB_B*NB_OBS];
__device__ __align__(16) bf16 g_obs_l[NB_B*NB_OBS];
// encoder-chain activations
__device__ __align__(16) bf16 g_h_h[NB_B*NB_HID];
__device__ __align__(16) bf16 g_h_l[NB_B*NB_HID];
__device__ __align__(16) float g_xa_f[NB_B*NB_OBS];
__device__ __align__(16) bf16 g_xa_h[NB_B*NB_OBS];
__device__ __align__(16) bf16 g_xa_l[NB_B*NB_OBS];
__device__ __align__(16) float g_xb_f[NB_B*NB_OBS];
__device__ __align__(16) bf16 g_xb_h[NB_B*NB_OBS];
__device__ __align__(16) bf16 g_xb_l[NB_B*NB_OBS];
// value-chain activations
__device__ __align__(16) bf16 g_h2_h[NB_B*NB_HID];
__device__ __align__(16) bf16 g_h2_l[NB_B*NB_HID];
__device__ __align__(16) float g_ya_f[NB_B*NB_OBS];
__device__ __align__(16) bf16 g_ya_h[NB_B*NB_OBS];
__device__ __align__(16) bf16 g_ya_l[NB_B*NB_OBS];
__device__ __align__(16) float g_yb_f[NB_B*NB_OBS];
__device__ __align__(16) bf16 g_yb_h[NB_B*NB_OBS];
__device__ __align__(16) bf16 g_yb_l[NB_B*NB_OBS];
// latent + MoE
__device__ __align__(16) float g_lat_f[NB_B*NB_LAT];
__device__ __align__(16) bf16 g_lat_h[NB_B*NB_LAT];
__device__ __align__(16) bf16 g_lat_l[NB_B*NB_LAT];
__device__ __align__(16) float g_xea_f[NB_DISP*NB_LAT];
__device__ __align__(16) bf16 g_xea_h[NB_DISP*NB_LAT];
__device__ __align__(16) bf16 g_xea_l[NB_DISP*NB_LAT];
__device__ __align__(16) float g_xeb_f[NB_DISP*NB_LAT];
__device__ __align__(16) bf16 g_xeb_h[NB_DISP*NB_LAT];
__device__ __align__(16) bf16 g_xeb_l[NB_DISP*NB_LAT];
__device__ __align__(16) bf16 g_he_h[NB_DISP*NB_HID];
__device__ __align__(16) bf16 g_he_l[NB_DISP*NB_HID];
__device__ int   g_tokidx[NB_E*NB_B];
__device__ float g_gatew [NB_E*NB_B];
__device__ int   g_cnt[NB_E];
__device__ int   g_off[NB_E];
__device__ int   g_dtok[NB_DISP];
__device__ float g_dg  [NB_DISP];

// ---------------- PTX helpers (portable, sm_80+) ----------------
__device__ __forceinline__ uint32_t smem_u32(const void* p){ return (uint32_t)__cvta_generic_to_shared(p); }
__device__ __forceinline__ void cp16(uint32_t s, const void* g){
    asm volatile("cp.async.cg.shared.global [%0], [%1], 16;"::"r"(s),"l"(g):"memory");
}
__device__ __forceinline__ void ldm_x4(uint32_t& r0,uint32_t& r1,uint32_t& r2,uint32_t& r3,uint32_t a){
    asm volatile("ldmatrix.sync.aligned.m8n8.x4.shared.b16 {%0,%1,%2,%3},[%4];"
        :"=r"(r0),"=r"(r1),"=r"(r2),"=r"(r3):"r"(a));
}
__device__ __forceinline__ void mma16816(float* c, const uint32_t* a, const uint32_t* b){
    asm volatile("mma.sync.aligned.m16n8k16.row.col.f32.bf16.bf16.f32 "
        "{%0,%1,%2,%3},{%4,%5,%6,%7},{%8,%9},{%0,%1,%2,%3};"
        :"+f"(c[0]),"+f"(c[1]),"+f"(c[2]),"+f"(c[3])
        :"r"(a[0]),"r"(a[1]),"r"(a[2]),"r"(a[3]),"r"(b[0]),"r"(b[1]));
}

// ---------------- bf16x3 warp-MMA GEMM: C = epi(A@W^T + bias [,+R]) ----------------
// Tile 128x128, 8 warps (warp tile 64x32), 2-stage cp.async pipeline, 2 CTAs/SM.
// ONE barrier per chunk; A-fragments double-buffered so mt+1's ldmatrix issues
// before mt's 12 MMAs (hides LDSM latency; issue-bound fix per R14 ncu).
__device__ __forceinline__ void gemm_core(
    const bf16* __restrict__ Ah, const bf16* __restrict__ Al,
    const bf16* __restrict__ Bh, const bf16* __restrict__ Bl,
    const float* __restrict__ bias, const float* __restrict__ Rf,
    float* __restrict__ Cf, bf16* __restrict__ Ch, bf16* __restrict__ Cl,
    int M, int N, int K, int epi, char* dsm)
{
    const int tid=threadIdx.x, wid=tid>>5, lane=tid&31;
    const int row0=blockIdx.y*BM, col0=blockIdx.x*BN;
    const int wm=wid>>2, wn=wid&3;                  // warp tile: 64 x 32
    const uint32_t sb0 = smem_u32(dsm);

    uint32_t soff[2]; size_t aoff[2], boff[2];
#pragma unroll
    for (int i=0;i<2;i++){
        int u=tid*2+i, row=u>>2, seg=u&3;
        soff[i]=(uint32_t)row*ROWB + (uint32_t)seg*16u;
        int ar=row0+row; if (ar>M-1) ar=M-1;
        aoff[i]=(size_t)ar*K + seg*8;
        boff[i]=(size_t)(col0+row)*K + seg*8;
    }
    const int NC = K/BK;
    auto prefetch = [&](int c){
        uint32_t st = sb0 + (uint32_t)(c&1)*STG_BYTES;
        size_t k0 = (size_t)c*BK;
#pragma unroll
        for (int i=0;i<2;i++){
            cp16(st + 0u*OP_BYTES + soff[i], Ah+aoff[i]+k0);
            cp16(st + 1u*OP_BYTES + soff[i], Al+aoff[i]+k0);
            cp16(st + 2u*OP_BYTES + soff[i], Bh+boff[i]+k0);
            cp16(st + 3u*OP_BYTES + soff[i], Bl+boff[i]+k0);
        }
        asm volatile("cp.async.commit_group;":::"memory");
    };

    // A: x4 per 16-row block
    const uint32_t a_lane = (uint32_t)(wm*64 + (lane&7) + ((lane>>3)&1)*8)*ROWB + (uint32_t)(lane>>4)*16u;
    // B: x4 covering TWO n8 blocks (bit3 -> k-half, bit4 -> next 8 rows)
    const uint32_t b_lane4 = (uint32_t)(wn*32 + (lane&7) + ((lane>>4)&1)*8)*ROWB + (uint32_t)((lane>>3)&1)*16u;

    float acc[4][4][4];
#pragma unroll
    for (int i=0;i<4;i++)
#pragma unroll
        for (int j=0;j<4;j++)
#pragma unroll
            for (int k=0;k<4;k++) acc[i][j][k]=0.f;

    prefetch(0);
    for (int c=0;c<NC;c++){
        asm volatile("cp.async.wait_group 0;":::"memory");
        __syncthreads();
        if (c+1<NC) prefetch(c+1);   // stage (c+1)&1 was read in iter c-1; barrier certifies it's free

        uint32_t st = sb0 + (uint32_t)(c&1)*STG_BYTES;
#pragma unroll
        for (int ks=0;ks<2;ks++){
            // preload all B fragments for this k-half (16 regs live)
            uint32_t bh[4][2], blo[4][2];
#pragma unroll
            for (int np=0;np<2;np++){    // each x4 covers nt=2*np and nt=2*np+1
                uint32_t bd = st + 2u*OP_BYTES + b_lane4 + (uint32_t)np*16u*ROWB + (uint32_t)ks*32u;
                ldm_x4(bh[2*np][0], bh[2*np][1], bh[2*np+1][0], bh[2*np+1][1], bd);
                ldm_x4(blo[2*np][0],blo[2*np][1],blo[2*np+1][0],blo[2*np+1][1], bd + OP_BYTES);
            }
            // A fragments: double-buffered; mt+1's LDSMs issue before mt's MMAs
            uint32_t ah[2][4], al[2][4];
            {
                uint32_t ad0 = st + a_lane + (uint32_t)ks*32u;
                ldm_x4(ah[0][0],ah[0][1],ah[0][2],ah[0][3], ad0);
                ldm_x4(al[0][0],al[0][1],al[0][2],al[0][3], ad0 + OP_BYTES);
            }
#pragma unroll
            for (int mt=0;mt<4;mt++){
                int cur = mt&1, nxt = cur^1;
                if (mt<3){
                    uint32_t ad = st + a_lane + (uint32_t)(mt+1)*16u*ROWB + (uint32_t)ks*32u;
                    ldm_x4(ah[nxt][0],ah[nxt][1],ah[nxt][2],ah[nxt][3], ad);
                    ldm_x4(al[nxt][0],al[nxt][1],al[nxt][2],al[nxt][3], ad + OP_BYTES);
                }
#pragma unroll
                for (int nt=0;nt<4;nt++){
                    mma16816(acc[mt][nt], ah[cur], bh[nt]);
                    mma16816(acc[mt][nt], ah[cur], blo[nt]);
                    mma16816(acc[mt][nt], al[cur], bh[nt]);
                }
            }
        }
    }

    // ---------------- epilogue ----------------
    const int rbase = row0 + wm*64 + (lane>>2);
    const int cbase = col0 + wn*32 + (lane&3)*2;
#pragma unroll
    for (int mt=0;mt<4;mt++){
#pragma unroll
        for (int half=0; half<2; half++){
            const int rr = rbase + mt*16 + half*8;
            if (rr >= M) continue;
#pragma unroll
            for (int nt=0;nt<4;nt++){
                const int cc = cbase + nt*8;
                float v0 = acc[mt][nt][half*2+0] + bias[cc];
                float v1 = acc[mt][nt][half*2+1] + bias[cc+1];
                const size_t base = (size_t)rr*N + cc;
                if (epi==0){ v0=fmaxf(v0,0.f); v1=fmaxf(v1,0.f); }
                else if (epi==1){
                    float2 r2 = *(const float2*)(Rf + base);
                    v0 += r2.x; v1 += r2.y;
                }
                if (Cf){ float2 o; o.x=v0; o.y=v1; *(float2*)(Cf+base)=o; }
                if (Ch){
                    bf16 h0=__float2bfloat16(v0), h1=__float2bfloat16(v1);
                    __nv_bfloat162 th; th.x=h0; th.y=h1;
                    __nv_bfloat162 tl; tl.x=__float2bfloat16(v0-__bfloat162float(h0));
                    tl.y=__float2bfloat16(v1-__bfloat162float(h1));
                    *(__nv_bfloat162*)(Ch+base)=th;
                    *(__nv_bfloat162*)(Cl+base)=tl;
                }
            }
        }
    }
}

__global__ void __launch_bounds__(256,2)
gemm_dense(const bf16* Ah, const bf16* Al, const bf16* Bh, const bf16* Bl,
           const float* bias, const float* Rf, float* Cf, bf16* Ch, bf16* Cl,
           int M, int N, int K, int epi)
{
    extern __shared__ char dsm[];
    gemm_core(Ah,Al,Bh,Bl,bias,Rf,Cf,Ch,Cl,M,N,K,epi,dsm);
}

__global__ void __launch_bounds__(256,2)
gemm_exp(const bf16* Ah, const bf16* Al, const bf16* Wh, const bf16* Wl, long wstride,
         const float* bias, long bstride, const float* Rf, float* Cf, bf16* Ch, bf16* Cl,
         int N, int K, int epi, const int* cnt, const int* off)
{
    extern __shared__ char dsm[];
    int e = blockIdx.z, M = cnt[e];
    if ((int)(blockIdx.y*BM) >= M) return;
    size_t o = (size_t)off[e];
    gemm_core(Ah+o*K, Al+o*K, Wh+(size_t)e*wstride, Wl+(size_t)e*wstride,
              bias+(size_t)e*bstride, Rf?Rf+o*N:nullptr, Cf?Cf+o*N:nullptr,
              Ch?Ch+o*N:nullptr, Cl?Cl+o*N:nullptr, M, N, K, epi, dsm);
}

// ---------------- conversions ----------------
__global__ void conv_split(const float* __restrict__ s, bf16* __restrict__ dh, bf16* __restrict__ dl, int n4)
{
    int i = blockIdx.x*blockDim.x + threadIdx.x;
    if (i>=n4) return;
    float4 v = ((const float4*)s)[i];
    __nv_bfloat162 h0,h1,l0,l1;
    h0.x=__float2bfloat16(v.x); h0.y=__float2bfloat16(v.y);
    h1.x=__float2bfloat16(v.z); h1.y=__float2bfloat16(v.w);
    l0.x=__float2bfloat16(v.x-__bfloat162float(h0.x));
    l0.y=__float2bfloat16(v.y-__bfloat162float(h0.y));
    l1.x=__float2bfloat16(v.z-__bfloat162float(h1.x));
    l1.y=__float2bfloat16(v.w-__bfloat162float(h1.y));
    ((__nv_bfloat162*)dh)[i*2]=h0; ((__nv_bfloat162*)dh)[i*2+1]=h1;
    ((__nv_bfloat162*)dl)[i*2]=l0; ((__nv_bfloat162*)dl)[i*2+1]=l1;
}

// [mats,K,N] fp32 -> [mats,N,K] bf16 hi/lo
__global__ void transpose_conv(const float* __restrict__ src, bf16* __restrict__ dh,
                               bf16* __restrict__ dl, int K, int N)
{
    __shared__ float t[32][33];
    int m = blockIdx.z;
    const float* S = src + (size_t)m*K*N;
    bf16* DH = dh + (size_t)m*K*N;
    bf16* DL = dl + (size_t)m*K*N;
    int n0=blockIdx.x*32, k0=blockIdx.y*32, x=threadIdx.x, y0=threadIdx.y;
#pragma unroll
    for (int yy=0;yy<32;yy+=8) t[y0+yy][x] = S[(size_t)(k0+y0+yy)*N + n0 + x];
    __syncthreads();
#pragma unroll
    for (int yy=0;yy<32;yy+=8){
        float v = t[x][y0+yy];
        bf16 h = __float2bfloat16(v);
        size_t di = (size_t)(n0+y0+yy)*K + k0 + x;
        DH[di]=h; DL[di]=__float2bfloat16(v-__bfloat162float(h));
    }
}

// ---------------- MoE plumbing ----------------
__global__ void init_kernel(float* out, int* cnt)
{
    int i = blockIdx.x*blockDim.x + threadIdx.x;
    if (i<NB_E) cnt[i]=0;
    if (i<NB_B*NB_OUT){ int b=i/NB_OUT, c=i%NB_OUT; out[b*(NB_OUT+1)+c]=0.f; }
}

__global__ void __launch_bounds__(256)
gate_kernel(const float* __restrict__ lat, const float* __restrict__ wg,
            int* tokidx, float* gatew, int* cnt)
{
    __shared__ float swg[NB_LAT*NB_E];
    for (int i=threadIdx.x;i<NB_LAT*NB_E;i+=blockDim.x) swg[i]=wg[i];
    __syncthreads();
    int warp=threadIdx.x>>5, lane=threadIdx.x&31;
    int b = blockIdx.x*8 + warp;
    float acc[NB_E];
#pragma unroll
    for (int e=0;e<NB_E;e++) acc[e]=0.f;
    for (int k=lane;k<NB_LAT;k+=32){
        float x = lat[(size_t)b*NB_LAT+k];
#pragma unroll
        for (int e=0;e<NB_E;e++) acc[e]=fmaf(x,swg[k*NB_E+e],acc[e]);
    }
#pragma unroll
    for (int e=0;e<NB_E;e++)
#pragma unroll
        for (int o=16;o;o>>=1) acc[e]+=__shfl_xor_sync(0xFFFFFFFFu,acc[e],o);
    if (lane==0){
        int e0=0; float v0=acc[0];
        for (int e=1;e<NB_E;e++) if (acc[e]>v0){v0=acc[e];e0=e;}
        int e1=-1; float v1=-3.4e38f;
        for (int e=0;e<NB_E;e++) if (e!=e0 && acc[e]>v1){v1=acc[e];e1=e;}
        float w1=expf(v1-v0), s=1.f+w1, w0=1.f/s; w1/=s;
        int p0=atomicAdd(&cnt[e0],1); tokidx[e0*NB_B+p0]=b; gatew[e0*NB_B+p0]=w0;
        int p1=atomicAdd(&cnt[e1],1); tokidx[e1*NB_B+p1]=b; gatew[e1*NB_B+p1]=w1;
    }
}

__global__ void scan_kernel(const int* cnt, int* off)
{
    if (threadIdx.x==0){ int s=0; for (int e=0;e<NB_E;e++){ off[e]=s; s+=cnt[e]; } }
}

__global__ void __launch_bounds__(256)
gather_kernel(const float* __restrict__ latf, const bf16* __restrict__ lath, const bf16* __restrict__ latl,
              const int* tokidx, const float* gatew, const int* cnt, const int* off,
              float* xef, bf16* xeh, bf16* xel, int* dtok, float* dg)
{
    int e=blockIdx.x, r=blockIdx.y*8 + (threadIdx.x>>5), lane=threadIdx.x&31;
    if (r>=cnt[e]) return;
    int tok = tokidx[e*NB_B+r], dst = off[e]+r;
    const float4* sf=(const float4*)(latf+(size_t)tok*NB_LAT);
    float4* df=(float4*)(xef+(size_t)dst*NB_LAT);
#pragma unroll
    for (int i=0;i<4;i++) df[lane+32*i]=sf[lane+32*i];
    const uint4* sh_=(const uint4*)(lath+(size_t)tok*NB_LAT);
    uint4* dh_=(uint4*)(xeh+(size_t)dst*NB_LAT);
    const uint4* sl_=(const uint4*)(latl+(size_t)tok*NB_LAT);
    uint4* dl_=(uint4*)(xel+(size_t)dst*NB_LAT);
#pragma unroll
    for (int i=0;i<2;i++){ dh_[lane+32*i]=sh_[lane+32*i]; dl_[lane+32*i]=sl_[lane+32*i]; }
    if (lane==0){ dtok[dst]=tok; dg[dst]=gatew[e*NB_B+r]; }
}

__global__ void __launch_bounds__(256)
expert_final_kernel(const float* __restrict__ xe, const float* __restrict__ Wf, const float* __restrict__ bf_,
                    const int* cnt, const int* off, const int* dtok, const float* dg, float* out)
{
    int e=blockIdx.x;
    __shared__ float sW[NB_LAT*NB_OUT];
    for (int i=threadIdx.x;i<NB_LAT*NB_OUT;i+=blockDim.x) sW[i]=Wf[(size_t)e*NB_LAT*NB_OUT+i];
    __syncthreads();
    int r=blockIdx.y*8 + (threadIdx.x>>5), lane=threadIdx.x&31;
    if (r>=cnt[e]) return;
    int dst=off[e]+r;
    float acc[NB_OUT];
#pragma unroll
    for (int c=0;c<NB_OUT;c++) acc[c]=0.f;
    const float* x = xe + (size_t)dst*NB_LAT;
#pragma unroll
    for (int i=0;i<NB_LAT/32;i++){
        int k=lane+32*i; float xv=x[k];
#pragma unroll
        for (int c=0;c<NB_OUT;c++) acc[c]=fmaf(xv,sW[k*NB_OUT+c],acc[c]);
    }
#pragma unroll
    for (int c=0;c<NB_OUT;c++)
#pragma unroll
        for (int o=16;o;o>>=1) acc[c]+=__shfl_xor_sync(0xFFFFFFFFu,acc[c],o);
    if (lane==0){
        int tok=dtok[dst]; float g=dg[dst];
#pragma unroll
        for (int c=0;c<NB_OUT;c++)
            atomicAdd(&out[tok*(NB_OUT+1)+c], g*(acc[c]+bf_[e*NB_OUT+c]));
    }
}

__global__ void __launch_bounds__(256)
value_final_kernel(const float* __restrict__ xv, const float* __restrict__ Wf,
                   const float* __restrict__ bf_, float* out)
{
    int b=blockIdx.x*8 + (threadIdx.x>>5), lane=threadIdx.x&31;
    float acc=0.f;
    const float* x = xv + (size_t)b*NB_OBS;
#pragma unroll
    for (int i=0;i<NB_OBS/32;i++) acc=fmaf(x[lane+32*i],Wf[lane+32*i],acc);
#pragma unroll
    for (int o=16;o;o>>=1) acc+=__shfl_xor_sync(0xFFFFFFFFu,acc,o);
    if (lane==0) out[b*(NB_OUT+1)+NB_OUT]=acc+bf_[0];
}

__global__ void eps_kernel(float* out)
{
    int i=blockIdx.x*blockDim.x+threadIdx.x;
    if (i<NB_B*NB_OUT){
        int b=i/NB_OUT, c=i%NB_OUT;
        float* p=&out[b*(NB_OUT+1)+c];
        if (*p==0.f) *p=2.2204460492503131e-16f;
    }
}

// =====================================================================================
extern "C" void kernel_launch(void* const* d_in, const int* in_sizes, int n_in,
                              void* d_out, int out_size)
{
    const float* obs   =(const float*)d_in[0];
    const float* encW1 =(const float*)d_in[1];  const float* encb1=(const float*)d_in[2];
    const float* encW2 =(const float*)d_in[3];  const float* encb2=(const float*)d_in[4];
    const float* encWf =(const float*)d_in[5];  const float* encbf=(const float*)d_in[6];
    const float* expW1 =(const float*)d_in[7];  const float* expb1=(const float*)d_in[8];
    const float* expW2 =(const float*)d_in[9];  const float* expb2=(const float*)d_in[10];
    const float* expWf =(const float*)d_in[11]; const float* expbf=(const float*)d_in[12];
    const float* valW1 =(const float*)d_in[13]; const float* valb1=(const float*)d_in[14];
    const float* valW2 =(const float*)d_in[15]; const float* valb2=(const float*)d_in[16];
    const float* valWf =(const float*)d_in[17]; const float* valbf=(const float*)d_in[18];
    const float* wgate =(const float*)d_in[19];
    float* out=(float*)d_out;

#define SYM(T,v,s) T* v; cudaGetSymbolAddress((void**)&v, s)
    SYM(bf16,eW1h,g_encW1t_h); SYM(bf16,eW1l,g_encW1t_l);
    SYM(bf16,eW2h,g_encW2t_h); SYM(bf16,eW2l,g_encW2t_l);
    SYM(bf16,eWfh,g_encWft_h); SYM(bf16,eWfl,g_encWft_l);
    SYM(bf16,xW1h,g_expW1t_h); SYM(bf16,xW1l,g_expW1t_l);
    SYM(bf16,xW2h,g_expW2t_h); SYM(bf16,xW2l,g_expW2t_l);
    SYM(bf16,vW1h,g_valW1t_h); SYM(bf16,vW1l,g_valW1t_l);
    SYM(bf16,vW2h,g_valW2t_h); SYM(bf16,vW2l,g_valW2t_l);
    SYM(bf16,obsh,g_obs_h);    SYM(bf16,obsl,g_obs_l);
    SYM(bf16,hh,g_h_h);        SYM(bf16,hl,g_h_l);
    SYM(float,xaf,g_xa_f); SYM(bf16,xah,g_xa_h); SYM(bf16,xal,g_xa_l);
    SYM(float,xbf,g_xb_f); SYM(bf16,xbh,g_xb_h); SYM(bf16,xbl,g_xb_l);
    SYM(bf16,h2h,g_h2_h);  SYM(bf16,h2l,g_h2_l);
    SYM(float,yaf,g_ya_f); SYM(bf16,yah,g_ya_h); SYM(bf16,yal,g_ya_l);
    SYM(float,ybf,g_yb_f); SYM(bf16,ybh,g_yb_h); SYM(bf16,ybl,g_yb_l);
    SYM(float,latf,g_lat_f); SYM(bf16,lath,g_lat_h); SYM(bf16,latl,g_lat_l);
    SYM(float,xeaf,g_xea_f); SYM(bf16,xeah,g_xea_h); SYM(bf16,xeal,g_xea_l);
    SYM(float,xebf,g_xeb_f); SYM(bf16,xebh,g_xeb_h); SYM(bf16,xebl,g_xeb_l);
    SYM(bf16,heh,g_he_h);    SYM(bf16,hel,g_he_l);
    SYM(int,tokidx,g_tokidx); SYM(float,gatew,g_gatew);
    SYM(int,cnt,g_cnt); SYM(int,off,g_off); SYM(int,dtok,g_dtok); SYM(float,dg,g_dg);
#undef SYM

    cudaFuncSetAttribute(gemm_dense, cudaFuncAttributeMaxDynamicSharedMemorySize, GEMM_SMEM);
    cudaFuncSetAttribute(gemm_exp,   cudaFuncAttributeMaxDynamicSharedMemorySize, GEMM_SMEM);

    cudaStream_t s2 = g_ss.s2, s3 = g_ss.s3;
    cudaEvent_t ev0 = g_ss.ev0, ev2 = g_ss.ev2, ev3 = g_ss.ev3, ev4 = g_ss.ev4;

    dim3 tcb(32,8);
    dim3 gh(NB_HID/BN, NB_B/BM), go(NB_OBS/BN, NB_B/BM), gl(NB_LAT/BN, NB_B/BM);
    const size_t W1M=(size_t)NB_OBS*NB_HID;

    init_kernel<<<(NB_B*NB_OUT+255)/256, 256>>>(out, cnt);
    conv_split<<<(NB_B*NB_OBS/4+255)/256, 256>>>(obs, obsh, obsl, NB_B*NB_OBS/4);
    cudaEventRecord(ev0, 0);   // obs split done -> side chains may start

    // main: only encW1 transpose blocks encoder GEMM1
    transpose_conv<<<dim3(NB_HID/32, NB_OBS/32, NB_NB), tcb>>>(encW1, eW1h, eW1l, NB_OBS, NB_HID);
    gemm_dense<<<gh,256,GEMM_SMEM>>>(obsh,obsl, eW1h,eW1l, encb1, nullptr, nullptr, hh,hl, NB_B,NB_HID,NB_OBS,0);

    // fork side streams
    cudaStreamWaitEvent(s2, ev0, 0);
    cudaStreamWaitEvent(s3, ev0, 0);
    // s3: encW2/encWf prep (hides under encoder GEMM1) then expert weight prep
    transpose_conv<<<dim3(NB_OBS/32, NB_HID/32, NB_NB), tcb, 0, s3>>>(encW2, eW2h, eW2l, NB_HID, NB_OBS);
    transpose_conv<<<dim3(NB_LAT/32, NB_OBS/32, 1),     tcb, 0, s3>>>(encWf, eWfh, eWfl, NB_OBS, NB_LAT);
    cudaEventRecord(ev4, s3);
    transpose_conv<<<dim3(NB_HID/32, NB_LAT/32, NB_E*NB_NB), tcb, 0, s3>>>(expW1, xW1h, xW1l, NB_LAT, NB_HID);
    transpose_conv<<<dim3(NB_LAT/32, NB_HID/32, NB_E*NB_NB), tcb, 0, s3>>>(expW2, xW2h, xW2l, NB_HID, NB_LAT);
    cudaEventRecord(ev3, s3);
    // s2: value weight prep + value chain
    transpose_conv<<<dim3(NB_HID/32, NB_OBS/32, NB_NB), tcb, 0, s2>>>(valW1, vW1h, vW1l, NB_OBS, NB_HID);
    transpose_conv<<<dim3(NB_OBS/32, NB_HID/32, NB_NB), tcb, 0, s2>>>(valW2, vW2h, vW2l, NB_HID, NB_OBS);
    gemm_dense<<<gh,256,GEMM_SMEM,s2>>>(obsh,obsl, vW1h,vW1l, valb1, nullptr, nullptr, h2h,h2l, NB_B,NB_HID,NB_OBS,0);
    gemm_dense<<<go,256,GEMM_SMEM,s2>>>(h2h,h2l, vW2h,vW2l, valb2, obs, yaf, yah,yal, NB_B,NB_OBS,NB_HID,1);
    gemm_dense<<<gh,256,GEMM_SMEM,s2>>>(yah,yal, vW1h+W1M,vW1l+W1M, valb1+NB_HID, nullptr, nullptr, h2h,h2l, NB_B,NB_HID,NB_OBS,0);
    gemm_dense<<<go,256,GEMM_SMEM,s2>>>(h2h,h2l, vW2h+W1M,vW2l+W1M, valb2+NB_OBS, yaf, ybf, ybh,ybl, NB_B,NB_OBS,NB_HID,1);
    gemm_dense<<<gh,256,GEMM_SMEM,s2>>>(ybh,ybl, vW1h+2*W1M,vW1l+2*W1M, valb1+2*NB_HID, nullptr, nullptr, h2h,h2l, NB_B,NB_HID,NB_OBS,0);
    // last value GEMM: bf16 outputs unused -> skip split store
    gemm_dense<<<go,256,GEMM_SMEM,s2>>>(h2h,h2l, vW2h+2*W1M,vW2l+2*W1M, valb2+2*NB_OBS, ybf, yaf, nullptr,nullptr, NB_B,NB_OBS,NB_HID,1);
    value_final_kernel<<<NB_B/8,256,0,s2>>>(yaf, valWf, valbf, out);
    cudaEventRecord(ev2, s2);

    // main: wait for encW2/encWf prep (hidden under GEMM1), then remaining encoder ResNet
    cudaStreamWaitEvent(0, ev4, 0);
    gemm_dense<<<go,256,GEMM_SMEM>>>(hh,hl, eW2h,eW2l, encb2, obs, xaf, xah,xal, NB_B,NB_OBS,NB_HID,1);
    gemm_dense<<<gh,256,GEMM_SMEM>>>(xah,xal, eW1h+W1M,eW1l+W1M, encb1+NB_HID, nullptr, nullptr, hh,hl, NB_B,NB_HID,NB_OBS,0);
    gemm_dense<<<go,256,GEMM_SMEM>>>(hh,hl, eW2h+W1M,eW2l+W1M, encb2+NB_OBS, xaf, xbf, xbh,xbl, NB_B,NB_OBS,NB_HID,1);
    gemm_dense<<<gh,256,GEMM_SMEM>>>(xbh,xbl, eW1h+2*W1M,eW1l+2*W1M, encb1+2*NB_HID, nullptr, nullptr, hh,hl, NB_B,NB_HID,NB_OBS,0);
    gemm_dense<<<go,256,GEMM_SMEM>>>(hh,hl, eW2h+2*W1M,eW2l+2*W1M, encb2+2*NB_OBS, xbf, xaf, xah,xal, NB_B,NB_OBS,NB_HID,1);
    gemm_dense<<<gl,256,GEMM_SMEM>>>(xah,xal, eWfh,eWfl, encbf, nullptr, latf, lath,latl, NB_B,NB_LAT,NB_OBS,2);

    // gating + dispatch
    gate_kernel<<<NB_B/8,256>>>(latf, wgate, tokidx, gatew, cnt);
    scan_kernel<<<1,32>>>(cnt, off);
    gather_kernel<<<dim3(NB_E,NB_B/8),256>>>(latf,lath,latl,tokidx,gatew,cnt,off,xeaf,xeah,xeal,dtok,dg);

    // join expert-weight prep before expert GEMMs
    cudaStreamWaitEvent(0, ev3, 0);

    const long w1s=(long)NB_NB*NB_LAT*NB_HID, b1s=(long)NB_NB*NB_HID;
    const long w2s=(long)NB_NB*NB_HID*NB_LAT, b2s=(long)NB_NB*NB_LAT;
    dim3 eg1(NB_HID/BN, NB_B/BM, NB_E), eg2(NB_LAT/BN, NB_B/BM, NB_E);
    float *cf=xeaf, *nf=xebf; bf16 *chh=xeah,*cll=xeal,*nhh=xebh,*nll=xebl;
    for (int blk=0;blk<NB_NB;blk++){
        gemm_exp<<<eg1,256,GEMM_SMEM>>>(chh,cll, xW1h+(size_t)blk*NB_LAT*NB_HID, xW1l+(size_t)blk*NB_LAT*NB_HID, w1s,
                                        expb1+blk*NB_HID, b1s, nullptr, nullptr, heh,hel, NB_HID,NB_LAT,0, cnt,off);
        bool last = (blk==NB_NB-1);
        gemm_exp<<<eg2,256,GEMM_SMEM>>>(heh,hel, xW2h+(size_t)blk*NB_HID*NB_LAT, xW2l+(size_t)blk*NB_HID*NB_LAT, w2s,
                                        expb2+blk*NB_LAT, b2s, cf, nf,
                                        last?nullptr:nhh, last?nullptr:nll, NB_LAT,NB_HID,1, cnt,off);
        { float* t=cf; cf=nf; nf=t; } { bf16* t=chh; chh=nhh; nhh=t; t=cll; cll=nll; nll=t; }
    }
    expert_final_kernel<<<dim3(NB_E,NB_B/8),256>>>(cf, expWf, expbf, cnt, off, dtok, dg, out);

    eps_kernel<<<(NB_B*NB_OUT+255)/256, 256>>>(out);

    // join value chain before returning
    cudaStreamWaitEvent(0, ev2, 0);
}

// round 16
// speedup vs baseline: 1.1096x; 1.0003x over previous
#include <cuda_runtime.h>
#include <cuda_bf16.h>
#include <cstdint>
#include <cstddef>

typedef __nv_bfloat16 bf16;

#define NB_B    4096
#define NB_OBS  1024
#define NB_HID  1024
#define NB_LAT  512
#define NB_OUT  19
#define NB_E    8
#define NB_NB   3
#define NB_DISP (NB_B*2)

#define BM 128
#define BN 128
#define BK 32
#define ROWB 80u                      // padded row: 32 bf16 = 64B + 16B pad
#define OP_BYTES (128u*ROWB)          // 10240
#define STG_BYTES (4u*OP_BYTES)       // 40960 (Ah,Al,Bh,Bl)
#define GEMM_SMEM (2u*STG_BYTES)      // 81920 -> 2 CTAs/SM

// ---------------- static side streams/events (created at program load) ----------
struct SideStreams {
    cudaStream_t s2, s3;
    cudaEvent_t ev0, ev2, ev3, ev4;
    SideStreams() {
        cudaStreamCreateWithFlags(&s2, cudaStreamNonBlocking);
        cudaStreamCreateWithFlags(&s3, cudaStreamNonBlocking);
        cudaEventCreateWithFlags(&ev0, cudaEventDisableTiming);
        cudaEventCreateWithFlags(&ev2, cudaEventDisableTiming);
        cudaEventCreateWithFlags(&ev3, cudaEventDisableTiming);
        cudaEventCreateWithFlags(&ev4, cudaEventDisableTiming);
    }
};
static SideStreams g_ss;

// ---------------- scratch ----------------
__device__ __align__(16) bf16 g_encW1t_h[NB_NB*NB_OBS*NB_HID];
__device__ __align__(16) bf16 g_encW1t_l[NB_NB*NB_OBS*NB_HID];
__device__ __align__(16) bf16 g_encW2t_h[NB_NB*NB_HID*NB_OBS];
__device__ __align__(16) bf16 g_encW2t_l[NB_NB*NB_HID*NB_OBS];
__device__ __align__(16) bf16 g_encWft_h[NB_OBS*NB_LAT];
__device__ __align__(16) bf16 g_encWft_l[NB_OBS*NB_LAT];
__device__ __align__(16) bf16 g_expW1t_h[NB_E*NB_NB*NB_LAT*NB_HID];
__device__ __align__(16) bf16 g_expW1t_l[NB_E*NB_NB*NB_LAT*NB_HID];
__device__ __align__(16) bf16 g_expW2t_h[NB_E*NB_NB*NB_HID*NB_LAT];
__device__ __align__(16) bf16 g_expW2t_l[NB_E*NB_NB*NB_HID*NB_LAT];
__device__ __align__(16) bf16 g_valW1t_h[NB_NB*NB_OBS*NB_HID];
__device__ __align__(16) bf16 g_valW1t_l[NB_NB*NB_OBS*NB_HID];
__device__ __align__(16) bf16 g_valW2t_h[NB_NB*NB_HID*NB_OBS];
__device__ __align__(16) bf16 g_valW2t_l[NB_NB*NB_HID*NB_OBS];
__device__ __align__(16) bf16 g_obs_h[NB_B*NB_OBS];
__device__ __align__(16) bf16 g_obs_l[NB_B*NB_OBS];
// encoder-chain activations
__device__ __align__(16) bf16 g_h_h[NB_B*NB_HID];
__device__ __align__(16) bf16 g_h_l[NB_B*NB_HID];
__device__ __align__(16) float g_xa_f[NB_B*NB_OBS];
__device__ __align__(16) bf16 g_xa_h[NB_B*NB_OBS];
__device__ __align__(16) bf16 g_xa_l[NB_B*NB_OBS];
__device__ __align__(16) float g_xb_f[NB_B*NB_OBS];
__device__ __align__(16) bf16 g_xb_h[NB_B*NB_OBS];
__device__ __align__(16) bf16 g_xb_l[NB_B*NB_OBS];
// value-chain activations
__device__ __align__(16) bf16 g_h2_h[NB_B*NB_HID];
__device__ __align__(16) bf16 g_h2_l[NB_B*NB_HID];
__device__ __align__(16) float g_ya_f[NB_B*NB_OBS];
__device__ __align__(16) bf16 g_ya_h[NB_B*NB_OBS];
__device__ __align__(16) bf16 g_ya_l[NB_B*NB_OBS];
__device__ __align__(16) float g_yb_f[NB_B*NB_OBS];
__device__ __align__(16) bf16 g_yb_h[NB_B*NB_OBS];
__device__ __align__(16) bf16 g_yb_l[NB_B*NB_OBS];
// latent + MoE
__device__ __align__(16) float g_lat_f[NB_B*NB_LAT];
__device__ __align__(16) bf16 g_lat_h[NB_B*NB_LAT];
__device__ __align__(16) bf16 g_lat_l[NB_B*NB_LAT];
__device__ __align__(16) float g_xea_f[NB_DISP*NB_LAT];
__device__ __align__(16) bf16 g_xea_h[NB_DISP*NB_LAT];
__device__ __align__(16) bf16 g_xea_l[NB_DISP*NB_LAT];
__device__ __align__(16) float g_xeb_f[NB_DISP*NB_LAT];
__device__ __align__(16) bf16 g_xeb_h[NB_DISP*NB_LAT];
__device__ __align__(16) bf16 g_xeb_l[NB_DISP*NB_LAT];
__device__ __align__(16) bf16 g_he_h[NB_DISP*NB_HID];
__device__ __align__(16) bf16 g_he_l[NB_DISP*NB_HID];
__device__ int   g_tokidx[NB_E*NB_B];
__device__ float g_gatew [NB_E*NB_B];
__device__ int   g_cnt[NB_E];
__device__ int   g_off[NB_E];
__device__ int   g_dtok[NB_DISP];
__device__ float g_dg  [NB_DISP];

// ---------------- PTX helpers (portable, sm_80+) ----------------
__device__ __forceinline__ uint32_t smem_u32(const void* p){ return (uint32_t)__cvta_generic_to_shared(p); }
__device__ __forceinline__ void cp16(uint32_t s, const void* g){
    asm volatile("cp.async.cg.shared.global [%0], [%1], 16;"::"r"(s),"l"(g):"memory");
}
__device__ __forceinline__ void ldm_x4(uint32_t& r0,uint32_t& r1,uint32_t& r2,uint32_t& r3,uint32_t a){
    asm volatile("ldmatrix.sync.aligned.m8n8.x4.shared.b16 {%0,%1,%2,%3},[%4];"
        :"=r"(r0),"=r"(r1),"=r"(r2),"=r"(r3):"r"(a));
}
// register-pure MMA: non-volatile so the compiler may schedule/interleave freely
__device__ __forceinline__ void mma16816(float* c, const uint32_t* a, const uint32_t* b){
    asm("mma.sync.aligned.m16n8k16.row.col.f32.bf16.bf16.f32 "
        "{%0,%1,%2,%3},{%4,%5,%6,%7},{%8,%9},{%0,%1,%2,%3};"
        :"+f"(c[0]),"+f"(c[1]),"+f"(c[2]),"+f"(c[3])
        :"r"(a[0]),"r"(a[1]),"r"(a[2]),"r"(a[3]),"r"(b[0]),"r"(b[1]));
}

// ---------------- bf16x3 warp-MMA GEMM: C = epi(A@W^T + bias [,+R]) ----------------
// Tile 128x128, 8 warps (warp tile 64x32), 2-stage cp.async pipeline, 2 CTAs/SM.
// ONE barrier per chunk; A double-buffered; MMAs issued in three passes of 4
// independent instructions (dep distance 4, not 1) to keep the tensor pipe fed.
__device__ __forceinline__ void gemm_core(
    const bf16* __restrict__ Ah, const bf16* __restrict__ Al,
    const bf16* __restrict__ Bh, const bf16* __restrict__ Bl,
    const float* __restrict__ bias, const float* __restrict__ Rf,
    float* __restrict__ Cf, bf16* __restrict__ Ch, bf16* __restrict__ Cl,
    int M, int N, int K, int epi, char* dsm)
{
    const int tid=threadIdx.x, wid=tid>>5, lane=tid&31;
    const int row0=blockIdx.y*BM, col0=blockIdx.x*BN;
    const int wm=wid>>2, wn=wid&3;                  // warp tile: 64 x 32
    const uint32_t sb0 = smem_u32(dsm);

    uint32_t soff[2]; size_t aoff[2], boff[2];
#pragma unroll
    for (int i=0;i<2;i++){
        int u=tid*2+i, row=u>>2, seg=u&3;
        soff[i]=(uint32_t)row*ROWB + (uint32_t)seg*16u;
        int ar=row0+row; if (ar>M-1) ar=M-1;
        aoff[i]=(size_t)ar*K + seg*8;
        boff[i]=(size_t)(col0+row)*K + seg*8;
    }
    const int NC = K/BK;
    auto prefetch = [&](int c){
        uint32_t st = sb0 + (uint32_t)(c&1)*STG_BYTES;
        size_t k0 = (size_t)c*BK;
#pragma unroll
        for (int i=0;i<2;i++){
            cp16(st + 0u*OP_BYTES + soff[i], Ah+aoff[i]+k0);
            cp16(st + 1u*OP_BYTES + soff[i], Al+aoff[i]+k0);
            cp16(st + 2u*OP_BYTES + soff[i], Bh+boff[i]+k0);
            cp16(st + 3u*OP_BYTES + soff[i], Bl+boff[i]+k0);
        }
        asm volatile("cp.async.commit_group;":::"memory");
    };

    // A: x4 per 16-row block
    const uint32_t a_lane = (uint32_t)(wm*64 + (lane&7) + ((lane>>3)&1)*8)*ROWB + (uint32_t)(lane>>4)*16u;
    // B: x4 covering TWO n8 blocks (bit3 -> k-half, bit4 -> next 8 rows)
    const uint32_t b_lane4 = (uint32_t)(wn*32 + (lane&7) + ((lane>>4)&1)*8)*ROWB + (uint32_t)((lane>>3)&1)*16u;

    float acc[4][4][4];
#pragma unroll
    for (int i=0;i<4;i++)
#pragma unroll
        for (int j=0;j<4;j++)
#pragma unroll
            for (int k=0;k<4;k++) acc[i][j][k]=0.f;

    prefetch(0);
    for (int c=0;c<NC;c++){
        asm volatile("cp.async.wait_group 0;":::"memory");
        __syncthreads();
        if (c+1<NC) prefetch(c+1);   // stage (c+1)&1 was read in iter c-1; barrier certifies it's free

        uint32_t st = sb0 + (uint32_t)(c&1)*STG_BYTES;
#pragma unroll
        for (int ks=0;ks<2;ks++){
            // preload all B fragments for this k-half (16 regs live)
            uint32_t bh[4][2], blo[4][2];
#pragma unroll
            for (int np=0;np<2;np++){    // each x4 covers nt=2*np and nt=2*np+1
                uint32_t bd = st + 2u*OP_BYTES + b_lane4 + (uint32_t)np*16u*ROWB + (uint32_t)ks*32u;
                ldm_x4(bh[2*np][0], bh[2*np][1], bh[2*np+1][0], bh[2*np+1][1], bd);
                ldm_x4(blo[2*np][0],blo[2*np][1],blo[2*np+1][0],blo[2*np+1][1], bd + OP_BYTES);
            }
            // A fragments: double-buffered; mt+1's LDSMs issue before mt's MMAs
            uint32_t ah[2][4], al[2][4];
            {
                uint32_t ad0 = st + a_lane + (uint32_t)ks*32u;
                ldm_x4(ah[0][0],ah[0][1],ah[0][2],ah[0][3], ad0);
                ldm_x4(al[0][0],al[0][1],al[0][2],al[0][3], ad0 + OP_BYTES);
            }
#pragma unroll
            for (int mt=0;mt<4;mt++){
                int cur = mt&1, nxt = cur^1;
                if (mt<3){
                    uint32_t ad = st + a_lane + (uint32_t)(mt+1)*16u*ROWB + (uint32_t)ks*32u;
                    ldm_x4(ah[nxt][0],ah[nxt][1],ah[nxt][2],ah[nxt][3], ad);
                    ldm_x4(al[nxt][0],al[nxt][1],al[nxt][2],al[nxt][3], ad + OP_BYTES);
                }
                // three passes of 4 independent MMAs (dep distance 4 per accumulator)
#pragma unroll
                for (int nt=0;nt<4;nt++) mma16816(acc[mt][nt], ah[cur], bh[nt]);
#pragma unroll
                for (int nt=0;nt<4;nt++) mma16816(acc[mt][nt], ah[cur], blo[nt]);
#pragma unroll
                for (int nt=0;nt<4;nt++) mma16816(acc[mt][nt], al[cur], bh[nt]);
            }
        }
    }

    // ---------------- epilogue ----------------
    const int rbase = row0 + wm*64 + (lane>>2);
    const int cbase = col0 + wn*32 + (lane&3)*2;
#pragma unroll
    for (int mt=0;mt<4;mt++){
#pragma unroll
        for (int half=0; half<2; half++){
            const int rr = rbase + mt*16 + half*8;
            if (rr >= M) continue;
#pragma unroll
            for (int nt=0;nt<4;nt++){
                const int cc = cbase + nt*8;
                float v0 = acc[mt][nt][half*2+0] + bias[cc];
                float v1 = acc[mt][nt][half*2+1] + bias[cc+1];
                const size_t base = (size_t)rr*N + cc;
                if (epi==0){ v0=fmaxf(v0,0.f); v1=fmaxf(v1,0.f); }
                else if (epi==1){
                    float2 r2 = *(const float2*)(Rf + base);
                    v0 += r2.x; v1 += r2.y;
                }
                if (Cf){ float2 o; o.x=v0; o.y=v1; *(float2*)(Cf+base)=o; }
                if (Ch){
                    bf16 h0=__float2bfloat16(v0), h1=__float2bfloat16(v1);
                    __nv_bfloat162 th; th.x=h0; th.y=h1;
                    __nv_bfloat162 tl; tl.x=__float2bfloat16(v0-__bfloat162float(h0));
                    tl.y=__float2bfloat16(v1-__bfloat162float(h1));
                    *(__nv_bfloat162*)(Ch+base)=th;
                    *(__nv_bfloat162*)(Cl+base)=tl;
                }
            }
        }
    }
}

__global__ void __launch_bounds__(256,2)
gemm_dense(const bf16* Ah, const bf16* Al, const bf16* Bh, const bf16* Bl,
           const float* bias, const float* Rf, float* Cf, bf16* Ch, bf16* Cl,
           int M, int N, int K, int epi)
{
    extern __shared__ char dsm[];
    gemm_core(Ah,Al,Bh,Bl,bias,Rf,Cf,Ch,Cl,M,N,K,epi,dsm);
}

__global__ void __launch_bounds__(256,2)
gemm_exp(const bf16* Ah, const bf16* Al, const bf16* Wh, const bf16* Wl, long wstride,
         const float* bias, long bstride, const float* Rf, float* Cf, bf16* Ch, bf16* Cl,
         int N, int K, int epi, const int* cnt, const int* off)
{
    extern __shared__ char dsm[];
    int e = blockIdx.z, M = cnt[e];
    if ((int)(blockIdx.y*BM) >= M) return;
    size_t o = (size_t)off[e];
    gemm_core(Ah+o*K, Al+o*K, Wh+(size_t)e*wstride, Wl+(size_t)e*wstride,
              bias+(size_t)e*bstride, Rf?Rf+o*N:nullptr, Cf?Cf+o*N:nullptr,
              Ch?Ch+o*N:nullptr, Cl?Cl+o*N:nullptr, M, N, K, epi, dsm);
}

// ---------------- conversions ----------------
__global__ void conv_split(const float* __restrict__ s, bf16* __restrict__ dh, bf16* __restrict__ dl, int n4)
{
    int i = blockIdx.x*blockDim.x + threadIdx.x;
    if (i>=n4) return;
    float4 v = ((const float4*)s)[i];
    __nv_bfloat162 h0,h1,l0,l1;
    h0.x=__float2bfloat16(v.x); h0.y=__float2bfloat16(v.y);
    h1.x=__float2bfloat16(v.z); h1.y=__float2bfloat16(v.w);
    l0.x=__float2bfloat16(v.x-__bfloat162float(h0.x));
    l0.y=__float2bfloat16(v.y-__bfloat162float(h0.y));
    l1.x=__float2bfloat16(v.z-__bfloat162float(h1.x));
    l1.y=__float2bfloat16(v.w-__bfloat162float(h1.y));
    ((__nv_bfloat162*)dh)[i*2]=h0; ((__nv_bfloat162*)dh)[i*2+1]=h1;
    ((__nv_bfloat162*)dl)[i*2]=l0; ((__nv_bfloat162*)dl)[i*2+1]=l1;
}

// [mats,K,N] fp32 -> [mats,N,K] bf16 hi/lo
__global__ void transpose_conv(const float* __restrict__ src, bf16* __restrict__ dh,
                               bf16* __restrict__ dl, int K, int N)
{
    __shared__ float t[32][33];
    int m = blockIdx.z;
    const float* S = src + (size_t)m*K*N;
    bf16* DH = dh + (size_t)m*K*N;
    bf16* DL = dl + (size_t)m*K*N;
    int n0=blockIdx.x*32, k0=blockIdx.y*32, x=threadIdx.x, y0=threadIdx.y;
#pragma unroll
    for (int yy=0;yy<32;yy+=8) t[y0+yy][x] = S[(size_t)(k0+y0+yy)*N + n0 + x];
    __syncthreads();
#pragma unroll
    for (int yy=0;yy<32;yy+=8){
        float v = t[x][y0+yy];
        bf16 h = __float2bfloat16(v);
        size_t di = (size_t)(n0+y0+yy)*K + k0 + x;
        DH[di]=h; DL[di]=__float2bfloat16(v-__bfloat162float(h));
    }
}

// ---------------- MoE plumbing ----------------
__global__ void init_kernel(float* out, int* cnt)
{
    int i = blockIdx.x*blockDim.x + threadIdx.x;
    if (i<NB_E) cnt[i]=0;
    if (i<NB_B*NB_OUT){ int b=i/NB_OUT, c=i%NB_OUT; out[b*(NB_OUT+1)+c]=0.f; }
}

__global__ void __launch_bounds__(256)
gate_kernel(const float* __restrict__ lat, const float* __restrict__ wg,
            int* tokidx, float* gatew, int* cnt)
{
    __shared__ float swg[NB_LAT*NB_E];
    for (int i=threadIdx.x;i<NB_LAT*NB_E;i+=blockDim.x) swg[i]=wg[i];
    __syncthreads();
    int warp=threadIdx.x>>5, lane=threadIdx.x&31;
    int b = blockIdx.x*8 + warp;
    float acc[NB_E];
#pragma unroll
    for (int e=0;e<NB_E;e++) acc[e]=0.f;
    for (int k=lane;k<NB_LAT;k+=32){
        float x = lat[(size_t)b*NB_LAT+k];
#pragma unroll
        for (int e=0;e<NB_E;e++) acc[e]=fmaf(x,swg[k*NB_E+e],acc[e]);
    }
#pragma unroll
    for (int e=0;e<NB_E;e++)
#pragma unroll
        for (int o=16;o;o>>=1) acc[e]+=__shfl_xor_sync(0xFFFFFFFFu,acc[e],o);
    if (lane==0){
        int e0=0; float v0=acc[0];
        for (int e=1;e<NB_E;e++) if (acc[e]>v0){v0=acc[e];e0=e;}
        int e1=-1; float v1=-3.4e38f;
        for (int e=0;e<NB_E;e++) if (e!=e0 && acc[e]>v1){v1=acc[e];e1=e;}
        float w1=expf(v1-v0), s=1.f+w1, w0=1.f/s; w1/=s;
        int p0=atomicAdd(&cnt[e0],1); tokidx[e0*NB_B+p0]=b; gatew[e0*NB_B+p0]=w0;
        int p1=atomicAdd(&cnt[e1],1); tokidx[e1*NB_B+p1]=b; gatew[e1*NB_B+p1]=w1;
    }
}

__global__ void scan_kernel(const int* cnt, int* off)
{
    if (threadIdx.x==0){ int s=0; for (int e=0;e<NB_E;e++){ off[e]=s; s+=cnt[e]; } }
}

__global__ void __launch_bounds__(256)
gather_kernel(const float* __restrict__ latf, const bf16* __restrict__ lath, const bf16* __restrict__ latl,
              const int* tokidx, const float* gatew, const int* cnt, const int* off,
              float* xef, bf16* xeh, bf16* xel, int* dtok, float* dg)
{
    int e=blockIdx.x, r=blockIdx.y*8 + (threadIdx.x>>5), lane=threadIdx.x&31;
    if (r>=cnt[e]) return;
    int tok = tokidx[e*NB_B+r], dst = off[e]+r;
    const float4* sf=(const float4*)(latf+(size_t)tok*NB_LAT);
    float4* df=(float4*)(xef+(size_t)dst*NB_LAT);
#pragma unroll
    for (int i=0;i<4;i++) df[lane+32*i]=sf[lane+32*i];
    const uint4* sh_=(const uint4*)(lath+(size_t)tok*NB_LAT);
    uint4* dh_=(uint4*)(xeh+(size_t)dst*NB_LAT);
    const uint4* sl_=(const uint4*)(latl+(size_t)tok*NB_LAT);
    uint4* dl_=(uint4*)(xel+(size_t)dst*NB_LAT);
#pragma unroll
    for (int i=0;i<2;i++){ dh_[lane+32*i]=sh_[lane+32*i]; dl_[lane+32*i]=sl_[lane+32*i]; }
    if (lane==0){ dtok[dst]=tok; dg[dst]=gatew[e*NB_B+r]; }
}

__global__ void __launch_bounds__(256)
expert_final_kernel(const float* __restrict__ xe, const float* __restrict__ Wf, const float* __restrict__ bf_,
                    const int* cnt, const int* off, const int* dtok, const float* dg, float* out)
{
    int e=blockIdx.x;
    __shared__ float sW[NB_LAT*NB_OUT];
    for (int i=threadIdx.x;i<NB_LAT*NB_OUT;i+=blockDim.x) sW[i]=Wf[(size_t)e*NB_LAT*NB_OUT+i];
    __syncthreads();
    int r=blockIdx.y*8 + (threadIdx.x>>5), lane=threadIdx.x&31;
    if (r>=cnt[e]) return;
    int dst=off[e]+r;
    float acc[NB_OUT];
#pragma unroll
    for (int c=0;c<NB_OUT;c++) acc[c]=0.f;
    const float* x = xe + (size_t)dst*NB_LAT;
#pragma unroll
    for (int i=0;i<NB_LAT/32;i++){
        int k=lane+32*i; float xv=x[k];
#pragma unroll
        for (int c=0;c<NB_OUT;c++) acc[c]=fmaf(xv,sW[k*NB_OUT+c],acc[c]);
    }
#pragma unroll
    for (int c=0;c<NB_OUT;c++)
#pragma unroll
        for (int o=16;o;o>>=1) acc[c]+=__shfl_xor_sync(0xFFFFFFFFu,acc[c],o);
    if (lane==0){
        int tok=dtok[dst]; float g=dg[dst];
#pragma unroll
        for (int c=0;c<NB_OUT;c++)
            atomicAdd(&out[tok*(NB_OUT+1)+c], g*(acc[c]+bf_[e*NB_OUT+c]));
    }
}

__global__ void __launch_bounds__(256)
value_final_kernel(const float* __restrict__ xv, const float* __restrict__ Wf,
                   const float* __restrict__ bf_, float* out)
{
    int b=blockIdx.x*8 + (threadIdx.x>>5), lane=threadIdx.x&31;
    float acc=0.f;
    const float* x = xv + (size_t)b*NB_OBS;
#pragma unroll
    for (int i=0;i<NB_OBS/32;i++) acc=fmaf(x[lane+32*i],Wf[lane+32*i],acc);
#pragma unroll
    for (int o=16;o;o>>=1) acc+=__shfl_xor_sync(0xFFFFFFFFu,acc,o);
    if (lane==0) out[b*(NB_OUT+1)+NB_OUT]=acc+bf_[0];
}

__global__ void eps_kernel(float* out)
{
    int i=blockIdx.x*blockDim.x+threadIdx.x;
    if (i<NB_B*NB_OUT){
        int b=i/NB_OUT, c=i%NB_OUT;
        float* p=&out[b*(NB_OUT+1)+c];
        if (*p==0.f) *p=2.2204460492503131e-16f;
    }
}

// =====================================================================================
extern "C" void kernel_launch(void* const* d_in, const int* in_sizes, int n_in,
                              void* d_out, int out_size)
{
    const float* obs   =(const float*)d_in[0];
    const float* encW1 =(const float*)d_in[1];  const float* encb1=(const float*)d_in[2];
    const float* encW2 =(const float*)d_in[3];  const float* encb2=(const float*)d_in[4];
    const float* encWf =(const float*)d_in[5];  const float* encbf=(const float*)d_in[6];
    const float* expW1 =(const float*)d_in[7];  const float* expb1=(const float*)d_in[8];
    const float* expW2 =(const float*)d_in[9];  const float* expb2=(const float*)d_in[10];
    const float* expWf =(const float*)d_in[11]; const float* expbf=(const float*)d_in[12];
    const float* valW1 =(const float*)d_in[13]; const float* valb1=(const float*)d_in[14];
    const float* valW2 =(const float*)d_in[15]; const float* valb2=(const float*)d_in[16];
    const float* valWf =(const float*)d_in[17]; const float* valbf=(const float*)d_in[18];
    const float* wgate =(const float*)d_in[19];
    float* out=(float*)d_out;

#define SYM(T,v,s) T* v; cudaGetSymbolAddress((void**)&v, s)
    SYM(bf16,eW1h,g_encW1t_h); SYM(bf16,eW1l,g_encW1t_l);
    SYM(bf16,eW2h,g_encW2t_h); SYM(bf16,eW2l,g_encW2t_l);
    SYM(bf16,eWfh,g_encWft_h); SYM(bf16,eWfl,g_encWft_l);
    SYM(bf16,xW1h,g_expW1t_h); SYM(bf16,xW1l,g_expW1t_l);
    SYM(bf16,xW2h,g_expW2t_h); SYM(bf16,xW2l,g_expW2t_l);
    SYM(bf16,vW1h,g_valW1t_h); SYM(bf16,vW1l,g_valW1t_l);
    SYM(bf16,vW2h,g_valW2t_h); SYM(bf16,vW2l,g_valW2t_l);
    SYM(bf16,obsh,g_obs_h);    SYM(bf16,obsl,g_obs_l);
    SYM(bf16,hh,g_h_h);        SYM(bf16,hl,g_h_l);
    SYM(float,xaf,g_xa_f); SYM(bf16,xah,g_xa_h); SYM(bf16,xal,g_xa_l);
    SYM(float,xbf,g_xb_f); SYM(bf16,xbh,g_xb_h); SYM(bf16,xbl,g_xb_l);
    SYM(bf16,h2h,g_h2_h);  SYM(bf16,h2l,g_h2_l);
    SYM(float,yaf,g_ya_f); SYM(bf16,yah,g_ya_h); SYM(bf16,yal,g_ya_l);
    SYM(float,ybf,g_yb_f); SYM(bf16,ybh,g_yb_h); SYM(bf16,ybl,g_yb_l);
    SYM(float,latf,g_lat_f); SYM(bf16,lath,g_lat_h); SYM(bf16,latl,g_lat_l);
    SYM(float,xeaf,g_xea_f); SYM(bf16,xeah,g_xea_h); SYM(bf16,xeal,g_xea_l);
    SYM(float,xebf,g_xeb_f); SYM(bf16,xebh,g_xeb_h); SYM(bf16,xebl,g_xeb_l);
    SYM(bf16,heh,g_he_h);    SYM(bf16,hel,g_he_l);
    SYM(int,tokidx,g_tokidx); SYM(float,gatew,g_gatew);
    SYM(int,cnt,g_cnt); SYM(int,off,g_off); SYM(int,dtok,g_dtok); SYM(float,dg,g_dg);
#undef SYM

    cudaFuncSetAttribute(gemm_dense, cudaFuncAttributeMaxDynamicSharedMemorySize, GEMM_SMEM);
    cudaFuncSetAttribute(gemm_exp,   cudaFuncAttributeMaxDynamicSharedMemorySize, GEMM_SMEM);

    cudaStream_t s2 = g_ss.s2, s3 = g_ss.s3;
    cudaEvent_t ev0 = g_ss.ev0, ev2 = g_ss.ev2, ev3 = g_ss.ev3, ev4 = g_ss.ev4;

    dim3 tcb(32,8);
    dim3 gh(NB_HID/BN, NB_B/BM), go(NB_OBS/BN, NB_B/BM), gl(NB_LAT/BN, NB_B/BM);
    const size_t W1M=(size_t)NB_OBS*NB_HID;

    init_kernel<<<(NB_B*NB_OUT+255)/256, 256>>>(out, cnt);
    conv_split<<<(NB_B*NB_OBS/4+255)/256, 256>>>(obs, obsh, obsl, NB_B*NB_OBS/4);
    cudaEventRecord(ev0, 0);   // obs split done -> side chains may start

    // main: only encW1 transpose blocks encoder GEMM1
    transpose_conv<<<dim3(NB_HID/32, NB_OBS/32, NB_NB), tcb>>>(encW1, eW1h, eW1l, NB_OBS, NB_HID);
    gemm_dense<<<gh,256,GEMM_SMEM>>>(obsh,obsl, eW1h,eW1l, encb1, nullptr, nullptr, hh,hl, NB_B,NB_HID,NB_OBS,0);

    // fork side streams
    cudaStreamWaitEvent(s2, ev0, 0);
    cudaStreamWaitEvent(s3, ev0, 0);
    // s3: encW2/encWf prep (hides under encoder GEMM1) then expert weight prep
    transpose_conv<<<dim3(NB_OBS/32, NB_HID/32, NB_NB), tcb, 0, s3>>>(encW2, eW2h, eW2l, NB_HID, NB_OBS);
    transpose_conv<<<dim3(NB_LAT/32, NB_OBS/32, 1),     tcb, 0, s3>>>(encWf, eWfh, eWfl, NB_OBS, NB_LAT);
    cudaEventRecord(ev4, s3);
    transpose_conv<<<dim3(NB_HID/32, NB_LAT/32, NB_E*NB_NB), tcb, 0, s3>>>(expW1, xW1h, xW1l, NB_LAT, NB_HID);
    transpose_conv<<<dim3(NB_LAT/32, NB_HID/32, NB_E*NB_NB), tcb, 0, s3>>>(expW2, xW2h, xW2l, NB_HID, NB_LAT);
    cudaEventRecord(ev3, s3);
    // s2: value weight prep + value chain
    transpose_conv<<<dim3(NB_HID/32, NB_OBS/32, NB_NB), tcb, 0, s2>>>(valW1, vW1h, vW1l, NB_OBS, NB_HID);
    transpose_conv<<<dim3(NB_OBS/32, NB_HID/32, NB_NB), tcb, 0, s2>>>(valW2, vW2h, vW2l, NB_HID, NB_OBS);
    gemm_dense<<<gh,256,GEMM_SMEM,s2>>>(obsh,obsl, vW1h,vW1l, valb1, nullptr, nullptr, h2h,h2l, NB_B,NB_HID,NB_OBS,0);
    gemm_dense<<<go,256,GEMM_SMEM,s2>>>(h2h,h2l, vW2h,vW2l, valb2, obs, yaf, yah,yal, NB_B,NB_OBS,NB_HID,1);
    gemm_dense<<<gh,256,GEMM_SMEM,s2>>>(yah,yal, vW1h+W1M,vW1l+W1M, valb1+NB_HID, nullptr, nullptr, h2h,h2l, NB_B,NB_HID,NB_OBS,0);
    gemm_dense<<<go,256,GEMM_SMEM,s2>>>(h2h,h2l, vW2h+W1M,vW2l+W1M, valb2+NB_OBS, yaf, ybf, ybh,ybl, NB_B,NB_OBS,NB_HID,1);
    gemm_dense<<<gh,256,GEMM_SMEM,s2>>>(ybh,ybl, vW1h+2*W1M,vW1l+2*W1M, valb1+2*NB_HID, nullptr, nullptr, h2h,h2l, NB_B,NB_HID,NB_OBS,0);
    // last value GEMM: bf16 outputs unused -> skip split store
    gemm_dense<<<go,256,GEMM_SMEM,s2>>>(h2h,h2l, vW2h+2*W1M,vW2l+2*W1M, valb2+2*NB_OBS, ybf, yaf, nullptr,nullptr, NB_B,NB_OBS,NB_HID,1);
    value_final_kernel<<<NB_B/8,256,0,s2>>>(yaf, valWf, valbf, out);
    cudaEventRecord(ev2, s2);

    // main: wait for encW2/encWf prep (hidden under GEMM1), then remaining encoder ResNet
    cudaStreamWaitEvent(0, ev4, 0);
    gemm_dense<<<go,256,GEMM_SMEM>>>(hh,hl, eW2h,eW2l, encb2, obs, xaf, xah,xal, NB_B,NB_OBS,NB_HID,1);
    gemm_dense<<<gh,256,GEMM_SMEM>>>(xah,xal, eW1h+W1M,eW1l+W1M, encb1+NB_HID, nullptr, nullptr, hh,hl, NB_B,NB_HID,NB_OBS,0);
    gemm_dense<<<go,256,GEMM_SMEM>>>(hh,hl, eW2h+W1M,eW2l+W1M, encb2+NB_OBS, xaf, xbf, xbh,xbl, NB_B,NB_OBS,NB_HID,1);
    gemm_dense<<<gh,256,GEMM_SMEM>>>(xbh,xbl, eW1h+2*W1M,eW1l+2*W1M, encb1+2*NB_HID, nullptr, nullptr, hh,hl, NB_B,NB_HID,NB_OBS,0);
    gemm_dense<<<go,256,GEMM_SMEM>>>(hh,hl, eW2h+2*W1M,eW2l+2*W1M, encb2+2*NB_OBS, xbf, xaf, xah,xal, NB_B,NB_OBS,NB_HID,1);
    gemm_dense<<<gl,256,GEMM_SMEM>>>(xah,xal, eWfh,eWfl, encbf, nullptr, latf, lath,latl, NB_B,NB_LAT,NB_OBS,2);

    // gating + dispatch
    gate_kernel<<<NB_B/8,256>>>(latf, wgate, tokidx, gatew, cnt);
    scan_kernel<<<1,32>>>(cnt, off);
    gather_kernel<<<dim3(NB_E,NB_B/8),256>>>(latf,lath,latl,tokidx,gatew,cnt,off,xeaf,xeah,xeal,dtok,dg);

    // join expert-weight prep before expert GEMMs
    cudaStreamWaitEvent(0, ev3, 0);

    const long w1s=(long)NB_NB*NB_LAT*NB_HID, b1s=(long)NB_NB*NB_HID;
    const long w2s=(long)NB_NB*NB_HID*NB_LAT, b2s=(long)NB_NB*NB_LAT;
    dim3 eg1(NB_HID/BN, NB_B/BM, NB_E), eg2(NB_LAT/BN, NB_B/BM, NB_E);
    float *cf=xeaf, *nf=xebf; bf16 *chh=xeah,*cll=xeal,*nhh=xebh,*nll=xebl;
    for (int blk=0;blk<NB_NB;blk++){
        gemm_exp<<<eg1,256,GEMM_SMEM>>>(chh,cll, xW1h+(size_t)blk*NB_LAT*NB_HID, xW1l+(size_t)blk*NB_LAT*NB_HID, w1s,
                                        expb1+blk*NB_HID, b1s, nullptr, nullptr, heh,hel, NB_HID,NB_LAT,0, cnt,off);
        bool last = (blk==NB_NB-1);
        gemm_exp<<<eg2,256,GEMM_SMEM>>>(heh,hel, xW2h+(size_t)blk*NB_HID*NB_LAT, xW2l+(size_t)blk*NB_HID*NB_LAT, w2s,
                                        expb2+blk*NB_LAT, b2s, cf, nf,
                                        last?nullptr:nhh, last?nullptr:nll, NB_LAT,NB_HID,1, cnt,off);
        { float* t=cf; cf=nf; nf=t; } { bf16* t=chh; chh=nhh; nhh=t; t=cll; cll=nll; nll=t; }
    }
    expert_final_kernel<<<dim3(NB_E,NB_B/8),256>>>(cf, expWf, expbf, cnt, off, dtok, dg, out);

    eps_kernel<<<(NB_B*NB_OUT+255)/256, 256>>>(out);

    // join value chain before returning
    cudaStreamWaitEvent(0, ev2, 0);
}